// round 6
// baseline (speedup 1.0000x reference)
#include <cuda_runtime.h>
#include <cuda_bf16.h>
#include <math.h>

// ---------------- problem constants ----------------
#define NB 16      // batch
#define NT 4096    // tokens
#define HH 1024    // hidden
#define NS 16      // segments
#define NP 6       // plan slots
#define NHEAD 8
#define DHD 128    // head dim
#define PLAN_ELEMS (NB*NP*HH)   // 98304

// ---------------- device scratch (static, no allocs) ----------------
__device__ int   g_bounds[NB*(NS+1)];
__device__ float g_poolpart[4*NB*NS*HH];
__device__ float g_seg0[NB*NS*HH];
__device__ float g_qkv[NB*NS*3*HH];
__device__ float g_o[NB*NS*HH];
__device__ float g_tmp[NB*NS*HH];
__device__ float g_seg1[NB*NS*HH];
__device__ float g_hbuf[NB*NS*HH];
__device__ float g_logits[NB*NS];
__device__ float g_sal[NB*NS];
__device__ float g_wseg[NB*NS*HH];
__device__ float g_qh[64*HH];
__device__ float g_kv[NB*NS*2*HH];
__device__ float g_o2[NB*NP*HH];
__device__ float g_plan[NB*NP*HH];
__device__ float g_y[NB*NP*HH];
__device__ float g_qkvr[NB*NP*3*HH];
__device__ float g_o3[NB*NP*HH];
__device__ float g_ffn[NB*NP*4*HH];
__device__ float g_part[8*1024*1024];          // split-K partials (32MB) — max use 6.29M (qkv ks=8)
__device__ float g_entpart[NB];
__device__ float g_redpart[NB];

// ---------------- helpers ----------------
__device__ __forceinline__ unsigned smem_u32(const void* p) {
    unsigned a;
    asm("{ .reg .u64 t; cvta.to.shared.u64 t, %1; cvt.u32.u64 %0, t; }" : "=r"(a) : "l"(p));
    return a;
}
// pack two floats into bf16x2; if lo: pack the bf16 residuals instead
__device__ __forceinline__ unsigned pack_pair(float f0, float f1, bool lo) {
    if (lo) {
        f0 = f0 - __bfloat162float(__float2bfloat16(f0));
        f1 = f1 - __bfloat162float(__float2bfloat16(f1));
    }
    __nv_bfloat162 p = __floats2bfloat162_rn(f0, f1);   // .x = f0 (low half)
    return *reinterpret_cast<unsigned*>(&p);
}

// ---------------- lengths + segment bounds ----------------
__global__ void lengths_kernel(const int* __restrict__ mask) {
    int b = blockIdx.x;
    __shared__ int red[256];
    int t = threadIdx.x;
    int s = 0;
    for (int i = t; i < NT; i += 256) s += mask[b*NT + i];
    red[t] = s; __syncthreads();
    for (int o = 128; o > 0; o >>= 1) { if (t < o) red[t] += red[t+o]; __syncthreads(); }
    if (t == 0) {
        int L = red[0];
        for (int k = 0; k <= NS; k++) g_bounds[b*(NS+1) + k] = (k * L) / NS;
    }
}

// ---------------- segment pooling (split over 4 row-slices) ----------------
__global__ void segpool_partial(const float* __restrict__ ts) {
    int seg = blockIdx.x;            // 0..255
    int b = seg >> 4, s = seg & 15;
    int slice = blockIdx.y;          // 0..3
    int lo = g_bounds[b*(NS+1) + s], hi = g_bounds[b*(NS+1) + s + 1];
    int cnt = hi - lo;
    int chunk = (cnt + 3) >> 2;
    int r0 = lo + slice * chunk;
    int r1 = min(hi, r0 + chunk);
    int t = threadIdx.x;             // 256 threads, 4 cols each
    float4 acc = make_float4(0.f,0.f,0.f,0.f);
    const float* base = ts + (size_t)b * NT * HH;
    for (int r = r0; r < r1; r++) {
        float4 v = *(const float4*)(base + (size_t)r * HH + t * 4);
        acc.x += v.x; acc.y += v.y; acc.z += v.z; acc.w += v.w;
    }
    *(float4*)&g_poolpart[((size_t)slice * NB*NS + seg) * HH + t * 4] = acc;
}

__global__ void segpool_finish() {
    int idx = blockIdx.x * 256 + threadIdx.x;   // < 262144
    int seg = idx >> 10;
    int b = seg >> 4, s = seg & 15;
    float cnt = (float)(g_bounds[b*(NS+1)+s+1] - g_bounds[b*(NS+1)+s]);
    const int ST = NB*NS*HH;
    float v = g_poolpart[idx] + g_poolpart[ST + idx] + g_poolpart[2*ST + idx] + g_poolpart[3*ST + idx];
    g_seg0[idx] = v / fmaxf(cnt, 1.f);
}

// ---------------- mma.sync split-K GEMM ----------------
// P[z] over K'-slice z of A[M,K] @ W[N,K]^T in bf16 with error compensation:
// K' = 3K; phase 0: A_hi*W_hi, phase 1: A_lo*W_hi, phase 2: A_hi*W_lo.
// 128x128 block tile, BK=32, 256 threads = 8 warps (2M x 4N), warp tile 64x32.
#define SA 40   // padded smem row stride (bf16 elems) => 80B, conflict-free ldmatrix

__global__ void __launch_bounds__(256) gemm_mma_kernel(
    const float* __restrict__ A, const float* __restrict__ W,
    float* __restrict__ P, int M, int N, int K, int kslices)
{
    __shared__ __align__(16) __nv_bfloat16 As[128*SA];
    __shared__ __align__(16) __nv_bfloat16 Bs[128*SA];

    int tid = threadIdx.x;
    int wid = tid >> 5, lane = tid & 31;
    int m0 = blockIdx.x * 128, n0 = blockIdx.y * 128;
    int Kper = (3 * K) / kslices;        // multiple of 32
    int kstart = blockIdx.z * Kper;
    int nch = Kper >> 5;
    int wm = (wid & 1) * 64, wn = (wid >> 1) * 32;

    float acc[4][4][4];
#pragma unroll
    for (int a = 0; a < 4; a++)
#pragma unroll
        for (int b = 0; b < 4; b++)
#pragma unroll
            for (int c = 0; c < 4; c++) acc[a][b][c] = 0.f;

    int lrow = tid >> 1, lhalf = tid & 1;
    bool mval = (m0 + lrow) < M;
    const float* arow = A + (size_t)(m0 + lrow) * K + lhalf * 16;
    const float* wrow = W + (size_t)(n0 + lrow) * K + lhalf * 16;

    unsigned sAs = smem_u32(As), sBs = smem_u32(Bs);
    int g = lane >> 3, r = lane & 7;

    for (int c = 0; c < nch; c++) {
        int kpr = kstart + c * 32;
        int ph = kpr / K;
        int kb = kpr - ph * K;
        bool la = (ph == 1), lb = (ph == 2);

        // ---- fp32 -> bf16(hi/lo) convert + smem store ----
#pragma unroll
        for (int i = 0; i < 4; i++) {
            float4 v = mval ? *(const float4*)(arow + kb + i*4)
                            : make_float4(0.f,0.f,0.f,0.f);
            unsigned p0 = pack_pair(v.x, v.y, la), p1 = pack_pair(v.z, v.w, la);
            *(uint2*)&As[lrow*SA + lhalf*16 + i*4] = make_uint2(p0, p1);
        }
#pragma unroll
        for (int i = 0; i < 4; i++) {
            float4 v = *(const float4*)(wrow + kb + i*4);
            unsigned p0 = pack_pair(v.x, v.y, lb), p1 = pack_pair(v.z, v.w, lb);
            *(uint2*)&Bs[lrow*SA + lhalf*16 + i*4] = make_uint2(p0, p1);
        }
        __syncthreads();

        // ---- 2 k16-steps of HMMA ----
#pragma unroll
        for (int ks = 0; ks < 2; ks++) {
            unsigned af[4][4], bf[4][2];
#pragma unroll
            for (int mt = 0; mt < 4; mt++) {
                unsigned addr = sAs + (unsigned)(((wm + mt*16 + (g & 1)*8 + r) * SA
                                       + ks*16 + (g >> 1)*8) * 2);
                asm volatile("ldmatrix.sync.aligned.m8n8.x4.shared.b16 {%0,%1,%2,%3}, [%4];"
                    : "=r"(af[mt][0]), "=r"(af[mt][1]), "=r"(af[mt][2]), "=r"(af[mt][3])
                    : "r"(addr));
            }
#pragma unroll
            for (int np = 0; np < 2; np++) {
                unsigned t0,t1,t2,t3;
                unsigned addr = sBs + (unsigned)(((wn + np*16 + (g >> 1)*8 + r) * SA
                                       + ks*16 + (g & 1)*8) * 2);
                asm volatile("ldmatrix.sync.aligned.m8n8.x4.shared.b16 {%0,%1,%2,%3}, [%4];"
                    : "=r"(t0), "=r"(t1), "=r"(t2), "=r"(t3) : "r"(addr));
                bf[2*np][0] = t0; bf[2*np][1] = t1;
                bf[2*np+1][0] = t2; bf[2*np+1][1] = t3;
            }
#pragma unroll
            for (int mt = 0; mt < 4; mt++)
#pragma unroll
                for (int nt = 0; nt < 4; nt++) {
                    asm volatile(
                        "mma.sync.aligned.m16n8k16.row.col.f32.bf16.bf16.f32 "
                        "{%0,%1,%2,%3}, {%4,%5,%6,%7}, {%8,%9}, {%0,%1,%2,%3};"
                        : "+f"(acc[mt][nt][0]), "+f"(acc[mt][nt][1]),
                          "+f"(acc[mt][nt][2]), "+f"(acc[mt][nt][3])
                        : "r"(af[mt][0]), "r"(af[mt][1]), "r"(af[mt][2]), "r"(af[mt][3]),
                          "r"(bf[nt][0]), "r"(bf[nt][1]));
                }
        }
        __syncthreads();
    }

    // ---- write partials ----
    size_t base = (size_t)blockIdx.z * M * N;
#pragma unroll
    for (int mt = 0; mt < 4; mt++) {
        int m = m0 + wm + mt*16 + (lane >> 2);
#pragma unroll
        for (int nt = 0; nt < 4; nt++) {
            int n = n0 + wn + nt*8 + (lane & 3)*2;
            if (m < M)
                *(float2*)(P + base + (size_t)m * N + n)
                    = make_float2(acc[mt][nt][0], acc[mt][nt][1]);
            if (m + 8 < M)
                *(float2*)(P + base + (size_t)(m+8) * N + n)
                    = make_float2(acc[mt][nt][2], acc[mt][nt][3]);
        }
    }
}

// epilogue: out = [gelu]( sum_z P[z] + bias ) [+ res]
__global__ void epilogue_kernel(const float* __restrict__ P, const float* __restrict__ bias,
                                const float* __restrict__ res, float* __restrict__ out,
                                int M, int N, int kslices, int gelu)
{
    int idx = blockIdx.x * 256 + threadIdx.x;
    if (idx >= M * N) return;
    int n = idx % N;
    float v = 0.f;
    size_t MN = (size_t)M * N;
    for (int s = 0; s < kslices; s++) v += P[(size_t)s * MN + idx];
    v += bias[n];
    if (gelu) v = 0.5f * v * (1.f + erff(v * 0.70710678118654752f));
    if (res) v += res[idx];
    out[idx] = v;
}

// ---------------- generic small attention: one (b, head) per block ----------------
__global__ void attn_kernel(const float* __restrict__ qb, const float* __restrict__ kb,
                            const float* __restrict__ vb, float* __restrict__ ob,
                            int NQ, int NK,
                            int qRowStr, long long qBatStr,
                            int kRowStr, long long kBatStr,
                            int vRowStr, long long vBatStr,
                            int oRowStr, long long oBatStr)
{
    int b = blockIdx.x, h = blockIdx.y;
    const float* q = qb + b * qBatStr + h * DHD;
    const float* k = kb + b * kBatStr + h * DHD;
    const float* v = vb + b * vBatStr + h * DHD;
    float* o = ob + b * oBatStr + h * DHD;
    __shared__ float qs[16][DHD+1], ks[16][DHD+1], vs[16][DHD+1];
    __shared__ float pr[16][17];
    int t = threadIdx.x;  // 128
    for (int i = 0; i < NQ; i++) qs[i][t] = q[(size_t)i * qRowStr + t];
    for (int i = 0; i < NK; i++) { ks[i][t] = k[(size_t)i * kRowStr + t]; vs[i][t] = v[(size_t)i * vRowStr + t]; }
    __syncthreads();
    const float scale = 0.08838834764831843f;   // 1/sqrt(128)
    for (int p = t; p < NQ * NK; p += 128) {
        int qi = p / NK, ki = p - qi * NK;
        float acc = 0.f;
#pragma unroll 4
        for (int d = 0; d < DHD; d++) acc = fmaf(qs[qi][d], ks[ki][d], acc);
        pr[qi][ki] = acc * scale;
    }
    __syncthreads();
    if (t < NQ) {
        float mx = -1e30f;
        for (int kk = 0; kk < NK; kk++) mx = fmaxf(mx, pr[t][kk]);
        float sm = 0.f;
        for (int kk = 0; kk < NK; kk++) { float e = expf(pr[t][kk] - mx); pr[t][kk] = e; sm += e; }
        float inv = 1.f / sm;
        for (int kk = 0; kk < NK; kk++) pr[t][kk] *= inv;
    }
    __syncthreads();
    for (int j = t; j < NQ * DHD; j += 128) {
        int qi = j >> 7, d = j & 127;
        float acc = 0.f;
        for (int kk = 0; kk < NK; kk++) acc = fmaf(pr[qi][kk], vs[kk][d], acc);
        o[(size_t)qi * oRowStr + d] = acc;
    }
}

// ---------------- layernorm (two-pass, row per block) ----------------
__global__ void ln_kernel(const float* __restrict__ x,
                          const float* __restrict__ g, const float* __restrict__ be,
                          float* __restrict__ out)
{
    int r = blockIdx.x, t = threadIdx.x;   // 256 threads
    __shared__ float xs[HH];
    __shared__ float red[256];
    const float* xr = x + (size_t)r * HH;
    float s = 0.f;
    for (int i = t; i < HH; i += 256) { float v = xr[i]; xs[i] = v; s += v; }
    red[t] = s; __syncthreads();
    for (int o = 128; o > 0; o >>= 1) { if (t < o) red[t] += red[t+o]; __syncthreads(); }
    float mean = red[0] * (1.f / HH);
    __syncthreads();
    float s2 = 0.f;
    for (int i = t; i < HH; i += 256) { float d = xs[i] - mean; s2 += d * d; }
    red[t] = s2; __syncthreads();
    for (int o = 128; o > 0; o >>= 1) { if (t < o) red[t] += red[t+o]; __syncthreads(); }
    float inv = rsqrtf(red[0] * (1.f / HH) + 1e-5f);
    for (int i = t; i < HH; i += 256)
        out[(size_t)r * HH + i] = (xs[i] - mean) * inv * g[i] + be[i];
}

// ---------------- salience logits (dot with sal_w2) ----------------
__global__ void logits_kernel(const float* __restrict__ hbuf, const float* __restrict__ w,
                              const float* __restrict__ b2)
{
    int r = blockIdx.x, t = threadIdx.x;  // 128
    __shared__ float red[128];
    float s = 0.f;
    for (int i = t; i < HH; i += 128) s = fmaf(hbuf[(size_t)r * HH + i], w[i], s);
    red[t] = s; __syncthreads();
    for (int o = 64; o > 0; o >>= 1) { if (t < o) red[t] += red[t+o]; __syncthreads(); }
    if (t == 0) g_logits[r] = red[0] + b2[0];
}

// ---------------- salience softmax + entropy + weighted segments ----------------
__global__ void salience_kernel() {
    int b = blockIdx.x, t = threadIdx.x;  // 256
    __shared__ float sal_s[NS];
    if (t == 0) {
        float mx = -1e30f;
        for (int s = 0; s < NS; s++) mx = fmaxf(mx, g_logits[b*NS + s]);
        float sm = 0.f;
        for (int s = 0; s < NS; s++) { float e = expf(g_logits[b*NS + s] - mx); sal_s[s] = e; sm += e; }
        float inv = 1.f / sm, ent = 0.f;
        for (int s = 0; s < NS; s++) {
            sal_s[s] *= inv;
            g_sal[b*NS + s] = sal_s[s];
            ent -= sal_s[s] * logf(sal_s[s] + 1e-8f);
        }
        g_entpart[b] = ent;
    }
    __syncthreads();
    for (int i = t; i < NS * HH; i += 256) {
        int s = i >> 10;
        g_wseg[(size_t)b * NS * HH + i] = g_seg1[(size_t)b * NS * HH + i] * sal_s[s];
    }
}

// ---------------- redundancy ----------------
__global__ void red_kernel() {
    int b = blockIdx.x, t = threadIdx.x;  // 128
    __shared__ float ps[NP][HH+1];
    __shared__ float nrm[NP];
    __shared__ float parr[16];
    for (int i = t; i < NP * HH; i += 128) ps[i >> 10][i & 1023] = g_plan[(size_t)b * NP * HH + i];
    __syncthreads();
    if (t < NP) {
        float s = 0.f;
        for (int d = 0; d < HH; d++) s = fmaf(ps[t][d], ps[t][d], s);
        nrm[t] = fmaxf(sqrtf(s), 1e-12f);
    }
    __syncthreads();
    if (t < 15) {
        int i = 0, j = 0, c = t;
        for (i = 0; i < NP; i++) { int row = NP - 1 - i; if (c < row) { j = i + 1 + c; break; } c -= row; }
        float s = 0.f;
        for (int d = 0; d < HH; d++) s = fmaf(ps[i][d], ps[j][d], s);
        float sim = s / (nrm[i] * nrm[j]);
        parr[t] = 2.f * sim * sim;
    }
    __syncthreads();
    if (t == 0) {
        float s = 0.f;
        for (int p = 0; p < 15; p++) s += parr[p];
        g_redpart[b] = s;
    }
}

// ---------------- output assembly ----------------
__global__ void copy_plan_kernel(float* __restrict__ out, int n) {
    int i = blockIdx.x * 256 + threadIdx.x;
    if (i < n) out[i] = g_plan[i];
}

__global__ void finalize_kernel(float* __restrict__ out, int out_size) {
    int t = threadIdx.x;  // 256
    if (PLAN_ELEMS + t < out_size && t < NB*NS) out[PLAN_ELEMS + t] = g_sal[t];
    if (t == 0) {
        if (PLAN_ELEMS + 256 < out_size) {
            float e = 0.f;
            for (int b = 0; b < NB; b++) e += g_entpart[b];
            out[PLAN_ELEMS + 256] = e / (float)NB;
        }
        if (PLAN_ELEMS + 257 < out_size) {
            float r = 0.f;
            for (int b = 0; b < NB; b++) r += g_redpart[b];
            out[PLAN_ELEMS + 257] = r / (float)(NB * NP * (NP - 1));
        }
    }
}

// ---------------- host helper ----------------
// ks must divide 3K with (3K/ks) % 32 == 0; ks*M*N must fit g_part (8M floats)
static void run_gemm(const float* A, const float* W, int M, int N, int K, int ks,
                     const float* bias, const float* res, float* out, int gelu, float* part)
{
    dim3 grid((M + 127) / 128, N / 128, ks);
    gemm_mma_kernel<<<grid, 256>>>(A, W, part, M, N, K, ks);
    int tot = M * N;
    epilogue_kernel<<<(tot + 255) / 256, 256>>>(part, bias, res, out, M, N, ks, gelu);
}

extern "C" void kernel_launch(void* const* d_in, const int* in_sizes, int n_in,
                              void* d_out, int out_size)
{
    const float* ts       = (const float*)d_in[0];
    const int*   mask     = (const int*)  d_in[1];
    const float* sa_in_w  = (const float*)d_in[2];
    const float* sa_in_b  = (const float*)d_in[3];
    const float* sa_out_w = (const float*)d_in[4];
    const float* sa_out_b = (const float*)d_in[5];
    const float* ln_g     = (const float*)d_in[6];
    const float* ln_b     = (const float*)d_in[7];
    const float* sal_w1   = (const float*)d_in[8];
    const float* sal_b1   = (const float*)d_in[9];
    const float* sal_w2   = (const float*)d_in[10];
    const float* sal_b2   = (const float*)d_in[11];
    const float* plan_q   = (const float*)d_in[12];
    const float* qa_in_w  = (const float*)d_in[13];
    const float* qa_in_b  = (const float*)d_in[14];
    const float* qa_out_w = (const float*)d_in[15];
    const float* qa_out_b = (const float*)d_in[16];
    const float* r_in_w   = (const float*)d_in[17];
    const float* r_in_b   = (const float*)d_in[18];
    const float* r_out_w  = (const float*)d_in[19];
    const float* r_out_b  = (const float*)d_in[20];
    const float* r_ln1_g  = (const float*)d_in[21];
    const float* r_ln1_b  = (const float*)d_in[22];
    const float* r_ln2_g  = (const float*)d_in[23];
    const float* r_ln2_b  = (const float*)d_in[24];
    const float* r_w1     = (const float*)d_in[25];
    const float* r_b1     = (const float*)d_in[26];
    const float* r_w2     = (const float*)d_in[27];
    const float* r_b2     = (const float*)d_in[28];
    float* out = (float*)d_out;

    float *p_part, *p_seg0, *p_qkv, *p_o, *p_tmp, *p_seg1, *p_h, *p_qh, *p_kv,
          *p_o2, *p_plan, *p_y, *p_qkvr, *p_o3, *p_ffn, *p_wseg;
    cudaGetSymbolAddress((void**)&p_part, g_part);
    cudaGetSymbolAddress((void**)&p_seg0, g_seg0);
    cudaGetSymbolAddress((void**)&p_qkv,  g_qkv);
    cudaGetSymbolAddress((void**)&p_o,    g_o);
    cudaGetSymbolAddress((void**)&p_tmp,  g_tmp);
    cudaGetSymbolAddress((void**)&p_seg1, g_seg1);
    cudaGetSymbolAddress((void**)&p_h,    g_hbuf);
    cudaGetSymbolAddress((void**)&p_qh,   g_qh);
    cudaGetSymbolAddress((void**)&p_kv,   g_kv);
    cudaGetSymbolAddress((void**)&p_o2,   g_o2);
    cudaGetSymbolAddress((void**)&p_plan, g_plan);
    cudaGetSymbolAddress((void**)&p_y,    g_y);
    cudaGetSymbolAddress((void**)&p_qkvr, g_qkvr);
    cudaGetSymbolAddress((void**)&p_o3,   g_o3);
    cudaGetSymbolAddress((void**)&p_ffn,  g_ffn);
    cudaGetSymbolAddress((void**)&p_wseg, g_wseg);

    // 1) lengths + bounds, segment pooling
    lengths_kernel<<<16, 256>>>(mask);
    segpool_partial<<<dim3(NB*NS, 4), 256>>>(ts);
    segpool_finish<<<(NB*NS*HH)/256, 256>>>();

    // 2) segment self-attention
    run_gemm(p_seg0, sa_in_w, 256, 3*HH, HH, 8, sa_in_b, nullptr, p_qkv, 0, p_part);   // 384 blocks, P=6.29M
    attn_kernel<<<dim3(NB, NHEAD), 128>>>(p_qkv, p_qkv + HH, p_qkv + 2*HH, p_o,
                                          16, 16,
                                          3*HH, (long long)NS*3*HH,
                                          3*HH, (long long)NS*3*HH,
                                          3*HH, (long long)NS*3*HH,
                                          HH,   (long long)NS*HH);
    run_gemm(p_o, sa_out_w, 256, HH, HH, 8, sa_out_b, p_seg0, p_tmp, 0, p_part);       // 128 blocks
    ln_kernel<<<256, 256>>>(p_tmp, ln_g, ln_b, p_seg1);

    // 3) salience
    run_gemm(p_seg1, sal_w1, 256, HH, HH, 8, sal_b1, nullptr, p_h, 1, p_part);         // 128 blocks
    logits_kernel<<<256, 128>>>(p_h, sal_w2, sal_b2);
    salience_kernel<<<16, 256>>>();

    // 4) plan cross-attention (qh is batch-independent)
    run_gemm(plan_q, qa_in_w, NP, HH, HH, 8, qa_in_b, nullptr, p_qh, 0, p_part);       // 64 blocks
    run_gemm(p_wseg, qa_in_w + (size_t)HH*HH, 256, 2*HH, HH, 8, qa_in_b + HH, nullptr, p_kv, 0, p_part); // 256, P=4.19M
    attn_kernel<<<dim3(NB, NHEAD), 128>>>(p_qh, p_kv, p_kv + HH, p_o2,
                                          NP, 16,
                                          HH,   0LL,
                                          2*HH, (long long)NS*2*HH,
                                          2*HH, (long long)NS*2*HH,
                                          HH,   (long long)NP*HH);
    run_gemm(p_o2, qa_out_w, NB*NP, HH, HH, 12, qa_out_b, nullptr, p_plan, 0, p_part); // 96 blocks

    // 5) refinement transformer layers (norm_first)
    for (int l = 0; l < 2; l++) {
        ln_kernel<<<NB*NP, 256>>>(p_plan, r_ln1_g + l*HH, r_ln1_b + l*HH, p_y);
        run_gemm(p_y, r_in_w + (size_t)l*3*HH*HH, NB*NP, 3*HH, HH, 8,
                 r_in_b + l*3*HH, nullptr, p_qkvr, 0, p_part);                          // 192 blocks
        attn_kernel<<<dim3(NB, NHEAD), 128>>>(p_qkvr, p_qkvr + HH, p_qkvr + 2*HH, p_o3,
                                              NP, NP,
                                              3*HH, (long long)NP*3*HH,
                                              3*HH, (long long)NP*3*HH,
                                              3*HH, (long long)NP*3*HH,
                                              HH,   (long long)NP*HH);
        run_gemm(p_o3, r_out_w + (size_t)l*HH*HH, NB*NP, HH, HH, 12,
                 r_out_b + l*HH, p_plan, p_plan, 0, p_part);                            // 96 blocks
        ln_kernel<<<NB*NP, 256>>>(p_plan, r_ln2_g + l*HH, r_ln2_b + l*HH, p_y);
        run_gemm(p_y, r_w1 + (size_t)l*4*HH*HH, NB*NP, 4*HH, HH, 8,
                 r_b1 + l*4*HH, nullptr, p_ffn, 1, p_part);                             // 256 blocks
        run_gemm(p_ffn, r_w2 + (size_t)l*HH*4*HH, NB*NP, HH, 4*HH, 16,
                 r_b2 + l*HH, p_plan, p_plan, 0, p_part);                               // 128 blocks
    }

    // 6) outputs
    int ncopy = out_size < PLAN_ELEMS ? out_size : PLAN_ELEMS;
    copy_plan_kernel<<<(ncopy + 255) / 256, 256>>>(out, ncopy);
    red_kernel<<<16, 128>>>();
    finalize_kernel<<<1, 256>>>(out, out_size);
}

// round 9
// speedup vs baseline: 1.4063x; 1.4063x over previous
#include <cuda_runtime.h>
#include <cuda_bf16.h>
#include <math.h>

// ---------------- problem constants ----------------
#define NB 16      // batch
#define NT 4096    // tokens
#define HH 1024    // hidden
#define NS 16      // segments
#define NP 6       // plan slots
#define NHEAD 8
#define DHD 128    // head dim
#define PLAN_ELEMS (NB*NP*HH)   // 98304

// ---------------- device scratch (static, no allocs) ----------------
__device__ int   g_bounds[NB*(NS+1)];
__device__ float g_poolpart[4*NB*NS*HH];
__device__ float g_seg0[NB*NS*HH];
__device__ float g_qkv[NB*NS*3*HH];
__device__ float g_tmp[NB*NS*HH];
__device__ float g_seg1[NB*NS*HH];
__device__ float g_hbuf[NB*NS*HH];
__device__ float g_logits[NB*NS];
__device__ float g_sal[NB*NS];
__device__ float g_qh[NP*HH];
__device__ float g_kv[NB*NS*2*HH];
__device__ float g_plan[NB*NP*HH];
__device__ float g_qkvr[NB*NP*3*HH];
__device__ float g_ffn[NB*NP*4*HH];
__device__ float g_part[8*1024*1024];          // split-K partials (32MB)
__device__ float g_entpart[NB];
__device__ float g_redpart[NB];

// bf16 [hi(K)|lo(K)] operand buffers
__device__ __nv_bfloat16 g_bf_seg0[256*2048];
__device__ __nv_bfloat16 g_bf_o   [256*2048];
__device__ __nv_bfloat16 g_bf_seg1[256*2048];
__device__ __nv_bfloat16 g_bf_wseg[256*2048];
__device__ __nv_bfloat16 g_bf_pq  [NP*2048];
__device__ __nv_bfloat16 g_bf_o2  [96*2048];
__device__ __nv_bfloat16 g_bf_y   [96*2048];
__device__ __nv_bfloat16 g_bf_o3  [96*2048];
__device__ __nv_bfloat16 g_bf_ffn [96*8192];
__device__ __nv_bfloat16 g_wbf[69206016];      // all weights hi|lo (138MB)

// weight offsets into g_wbf (bf16 elems)
#define WOFF_SAIN   0LL
#define WOFF_SAOUT  6291456LL
#define WOFF_SAL1   8388608LL
#define WOFF_QAIN   10485760LL
#define WOFF_QAOUT  16777216LL
#define WOFF_RIN    18874368LL
#define WOFF_ROUT   31457280LL
#define WOFF_RW1    35651584LL
#define WOFF_RW2    52428800LL

// ---------------- helpers ----------------
__device__ __forceinline__ unsigned smem_u32(const void* p) {
    unsigned a;
    asm("{ .reg .u64 t; cvta.to.shared.u64 t, %1; cvt.u32.u64 %0, t; }" : "=r"(a) : "l"(p));
    return a;
}
__device__ __forceinline__ unsigned pack_pair(float f0, float f1, bool lo) {
    if (lo) {
        f0 = f0 - __bfloat162float(__float2bfloat16(f0));
        f1 = f1 - __bfloat162float(__float2bfloat16(f1));
    }
    __nv_bfloat162 p = __floats2bfloat162_rn(f0, f1);
    return *reinterpret_cast<unsigned*>(&p);
}
__device__ __forceinline__ void cp16(unsigned dst, const void* src, int sz) {
    asm volatile("cp.async.ca.shared.global [%0], [%1], 16, %2;"
                 :: "r"(dst), "l"(src), "r"(sz));
}
// write hi/lo pair for one scalar into [hi|lo] buffer
__device__ __forceinline__ void whl(__nv_bfloat16* t, size_t rowbase, int K, int k, float v) {
    __nv_bfloat16 h = __float2bfloat16(v);
    __nv_bfloat16 l = __float2bfloat16(v - __bfloat162float(h));
    t[rowbase + k] = h;
    t[rowbase + K + k] = l;
}

// ---------------- weight conversion (all tensors, one launch) ----------------
struct CvtTab {
    const float* src[10];
    __nv_bfloat16* dst[10];
    int n[10];
    int logK[10];
};
__global__ void convert_kernel(CvtTab tab) {
    int tsel = blockIdx.y;
    const float* s = tab.src[tsel];
    __nv_bfloat16* d = tab.dst[tsel];
    long long n = tab.n[tsel];
    int logK = tab.logK[tsel];
    int K = 1 << logK;
    long long stride = (long long)gridDim.x * blockDim.x * 4;
    for (long long idx = ((long long)blockIdx.x * blockDim.x + threadIdx.x) * 4;
         idx < n; idx += stride) {
        float4 v = *(const float4*)(s + idx);
        int k = (int)(idx & (K - 1));
        long long row = idx >> logK;
        __nv_bfloat16* dr = d + row * (2LL * K) + k;
        unsigned h0 = pack_pair(v.x, v.y, false), h1 = pack_pair(v.z, v.w, false);
        unsigned l0 = pack_pair(v.x, v.y, true),  l1 = pack_pair(v.z, v.w, true);
        *(uint2*)dr       = make_uint2(h0, h1);
        *(uint2*)(dr + K) = make_uint2(l0, l1);
    }
}

// ---------------- lengths + segment bounds ----------------
__global__ void lengths_kernel(const int* __restrict__ mask) {
    int b = blockIdx.x;
    __shared__ int red[256];
    int t = threadIdx.x;
    int s = 0;
    for (int i = t; i < NT; i += 256) s += mask[b*NT + i];
    red[t] = s; __syncthreads();
    for (int o = 128; o > 0; o >>= 1) { if (t < o) red[t] += red[t+o]; __syncthreads(); }
    if (t == 0) {
        int L = red[0];
        for (int k = 0; k <= NS; k++) g_bounds[b*(NS+1) + k] = (k * L) / NS;
    }
}

// ---------------- segment pooling ----------------
__global__ void segpool_partial(const float* __restrict__ ts) {
    int seg = blockIdx.x;
    int b = seg >> 4, s = seg & 15;
    int slice = blockIdx.y;
    int lo = g_bounds[b*(NS+1) + s], hi = g_bounds[b*(NS+1) + s + 1];
    int cnt = hi - lo;
    int chunk = (cnt + 3) >> 2;
    int r0 = lo + slice * chunk;
    int r1 = min(hi, r0 + chunk);
    int t = threadIdx.x;
    float4 acc = make_float4(0.f,0.f,0.f,0.f);
    const float* base = ts + (size_t)b * NT * HH;
    for (int r = r0; r < r1; r++) {
        float4 v = *(const float4*)(base + (size_t)r * HH + t * 4);
        acc.x += v.x; acc.y += v.y; acc.z += v.z; acc.w += v.w;
    }
    *(float4*)&g_poolpart[((size_t)slice * NB*NS + seg) * HH + t * 4] = acc;
}

__global__ void segpool_finish() {
    int idx = blockIdx.x * 256 + threadIdx.x;   // < 262144
    int seg = idx >> 10, k = idx & 1023;
    int b = seg >> 4, s = seg & 15;
    float cnt = (float)(g_bounds[b*(NS+1)+s+1] - g_bounds[b*(NS+1)+s]);
    const int ST = NB*NS*HH;
    float v = g_poolpart[idx] + g_poolpart[ST + idx] + g_poolpart[2*ST + idx] + g_poolpart[3*ST + idx];
    v /= fmaxf(cnt, 1.f);
    g_seg0[idx] = v;
    whl(g_bf_seg0, (size_t)seg * 2048, 1024, k, v);
}

// ---------------- bf16 split-K GEMM (mma.sync, cp.async double-buffered) ----------------
// Compensated: virtual K' = 3K; phase 0: A_hi*W_hi, 1: A_lo*W_hi, 2: A_hi*W_lo.
// A,W stored [rows, 2K] = [hi(K)|lo(K)]. 128x128 tile, BK=32, 256 thr, 8 warps 64x32.
#define SA 40   // padded smem row stride (bf16) => 80B

__global__ void __launch_bounds__(256) gemm_bf16_kernel(
    const __nv_bfloat16* __restrict__ A, const __nv_bfloat16* __restrict__ W,
    float* __restrict__ P, int M, int N, int K, int kslices)
{
    __shared__ __align__(16) __nv_bfloat16 As[2][128*SA];
    __shared__ __align__(16) __nv_bfloat16 Bs[2][128*SA];
    int tid = threadIdx.x, wid = tid >> 5, lane = tid & 31;
    int m0 = blockIdx.x * 128, n0 = blockIdx.y * 128;
    int K2 = 2 * K;
    int Kper = (3 * K) / kslices, kstart = blockIdx.z * Kper, nch = Kper >> 5;
    int wm = (wid & 1) * 64, wn = (wid >> 1) * 32;
    unsigned sA = smem_u32(As), sB = smem_u32(Bs);
    const unsigned STG = 128 * SA * 2;   // bytes per stage

    int r0 = tid >> 2, s0 = tid & 3;
    int f1 = tid + 256, r1 = f1 >> 2, s1 = f1 & 3;
    int szA0 = (m0 + r0 < M) ? 16 : 0, szA1 = (m0 + r1 < M) ? 16 : 0;
    const __nv_bfloat16* a0 = A + (size_t)(szA0 ? (m0 + r0) : 0) * K2 + s0 * 8;
    const __nv_bfloat16* a1 = A + (size_t)(szA1 ? (m0 + r1) : 0) * K2 + s1 * 8;
    const __nv_bfloat16* w0 = W + (size_t)(n0 + r0) * K2 + s0 * 8;
    const __nv_bfloat16* w1 = W + (size_t)(n0 + r1) * K2 + s1 * 8;
    unsigned dA0 = sA + (r0*SA + s0*8)*2, dA1 = sA + (r1*SA + s1*8)*2;
    unsigned dB0 = sB + (r0*SA + s0*8)*2, dB1 = sB + (r1*SA + s1*8)*2;

#define LOAD_STAGE(c, st) { \
    int kpr = kstart + (c)*32; int ph = kpr / K; int kb = kpr - ph*K; \
    int offA = (ph == 1) ? K : 0; int offW = (ph == 2) ? K : 0; \
    unsigned so = (unsigned)(st) * STG; \
    cp16(dA0 + so, a0 + offA + kb, szA0); cp16(dA1 + so, a1 + offA + kb, szA1); \
    cp16(dB0 + so, w0 + offW + kb, 16);   cp16(dB1 + so, w1 + offW + kb, 16); \
    asm volatile("cp.async.commit_group;"); }

    float acc[4][4][4];
#pragma unroll
    for (int a = 0; a < 4; a++)
#pragma unroll
        for (int b = 0; b < 4; b++)
#pragma unroll
            for (int c = 0; c < 4; c++) acc[a][b][c] = 0.f;

    LOAD_STAGE(0, 0);

    int g = lane >> 3, r = lane & 7;
    for (int c = 0; c < nch; c++) {
        if (c + 1 < nch) {
            LOAD_STAGE(c + 1, (c + 1) & 1);
            asm volatile("cp.async.wait_group 1;");
        } else {
            asm volatile("cp.async.wait_group 0;");
        }
        __syncthreads();
        unsigned bA = sA + (unsigned)(c & 1) * STG, bB = sB + (unsigned)(c & 1) * STG;
#pragma unroll
        for (int ks = 0; ks < 2; ks++) {
            unsigned af[4][4], bf[4][2];
#pragma unroll
            for (int mt = 0; mt < 4; mt++) {
                unsigned addr = bA + (unsigned)(((wm + mt*16 + (g & 1)*8 + r) * SA
                                       + ks*16 + (g >> 1)*8) * 2);
                asm volatile("ldmatrix.sync.aligned.m8n8.x4.shared.b16 {%0,%1,%2,%3}, [%4];"
                    : "=r"(af[mt][0]), "=r"(af[mt][1]), "=r"(af[mt][2]), "=r"(af[mt][3])
                    : "r"(addr));
            }
#pragma unroll
            for (int np = 0; np < 2; np++) {
                unsigned t0,t1,t2,t3;
                unsigned addr = bB + (unsigned)(((wn + np*16 + (g >> 1)*8 + r) * SA
                                       + ks*16 + (g & 1)*8) * 2);
                asm volatile("ldmatrix.sync.aligned.m8n8.x4.shared.b16 {%0,%1,%2,%3}, [%4];"
                    : "=r"(t0), "=r"(t1), "=r"(t2), "=r"(t3) : "r"(addr));
                bf[2*np][0] = t0; bf[2*np][1] = t1;
                bf[2*np+1][0] = t2; bf[2*np+1][1] = t3;
            }
#pragma unroll
            for (int mt = 0; mt < 4; mt++)
#pragma unroll
                for (int nt = 0; nt < 4; nt++) {
                    asm volatile(
                        "mma.sync.aligned.m16n8k16.row.col.f32.bf16.bf16.f32 "
                        "{%0,%1,%2,%3}, {%4,%5,%6,%7}, {%8,%9}, {%0,%1,%2,%3};"
                        : "+f"(acc[mt][nt][0]), "+f"(acc[mt][nt][1]),
                          "+f"(acc[mt][nt][2]), "+f"(acc[mt][nt][3])
                        : "r"(af[mt][0]), "r"(af[mt][1]), "r"(af[mt][2]), "r"(af[mt][3]),
                          "r"(bf[nt][0]), "r"(bf[nt][1]));
                }
        }
        __syncthreads();
    }

    size_t base = (size_t)blockIdx.z * M * N;
#pragma unroll
    for (int mt = 0; mt < 4; mt++) {
        int m = m0 + wm + mt*16 + (lane >> 2);
#pragma unroll
        for (int nt = 0; nt < 4; nt++) {
            int n = n0 + wn + nt*8 + (lane & 3)*2;
            if (m < M)
                *(float2*)(P + base + (size_t)m * N + n)
                    = make_float2(acc[mt][nt][0], acc[mt][nt][1]);
            if (m + 8 < M)
                *(float2*)(P + base + (size_t)(m+8) * N + n)
                    = make_float2(acc[mt][nt][2], acc[mt][nt][3]);
        }
    }
#undef LOAD_STAGE
}

// epilogue: out = [gelu]( sum_z P[z] + bias ) [+ res]; optional bf16 hi|lo out
__global__ void epilogue_kernel(const float* __restrict__ P, const float* __restrict__ bias,
                                const float* __restrict__ res, float* __restrict__ out,
                                __nv_bfloat16* __restrict__ tout,
                                int M, int N, int kslices, int gelu)
{
    int idx = blockIdx.x * 256 + threadIdx.x;
    if (idx >= M * N) return;
    int n = idx % N, m = idx / N;
    float v = 0.f;
    size_t MN = (size_t)M * N;
    for (int s = 0; s < kslices; s++) v += P[(size_t)s * MN + idx];
    v += bias[n];
    if (gelu) v = 0.5f * v * (1.f + erff(v * 0.70710678118654752f));
    if (res) v += res[idx];
    out[idx] = v;
    if (tout) whl(tout, (size_t)m * 2 * N, N, n, v);
}

// ---------------- small attention: one (b, head) per block; bf16 hi|lo output ----------------
__global__ void attn_kernel(const float* __restrict__ qb, const float* __restrict__ kb,
                            const float* __restrict__ vb, __nv_bfloat16* __restrict__ tout,
                            int NQ, int NK,
                            int qRowStr, long long qBatStr,
                            int kRowStr, long long kBatStr,
                            int vRowStr, long long vBatStr)
{
    int b = blockIdx.x, hd = blockIdx.y;
    const float* q = qb + b * qBatStr + hd * DHD;
    const float* k = kb + b * kBatStr + hd * DHD;
    const float* v = vb + b * vBatStr + hd * DHD;
    __shared__ float qs[16][DHD+1], ks[16][DHD+1], vs[16][DHD+1];
    __shared__ float pr[16][17];
    int t = threadIdx.x;  // 128
    for (int i = 0; i < NQ; i++) qs[i][t] = q[(size_t)i * qRowStr + t];
    for (int i = 0; i < NK; i++) { ks[i][t] = k[(size_t)i * kRowStr + t]; vs[i][t] = v[(size_t)i * vRowStr + t]; }
    __syncthreads();
    const float scale = 0.08838834764831843f;   // 1/sqrt(128)
    for (int p = t; p < NQ * NK; p += 128) {
        int qi = p / NK, ki = p - qi * NK;
        float acc = 0.f;
#pragma unroll 4
        for (int d = 0; d < DHD; d++) acc = fmaf(qs[qi][d], ks[ki][d], acc);
        pr[qi][ki] = acc * scale;
    }
    __syncthreads();
    if (t < NQ) {
        float mx = -1e30f;
        for (int kk = 0; kk < NK; kk++) mx = fmaxf(mx, pr[t][kk]);
        float sm = 0.f;
        for (int kk = 0; kk < NK; kk++) { float e = expf(pr[t][kk] - mx); pr[t][kk] = e; sm += e; }
        float inv = 1.f / sm;
        for (int kk = 0; kk < NK; kk++) pr[t][kk] *= inv;
    }
    __syncthreads();
    for (int j = t; j < NQ * DHD; j += 128) {
        int qi = j >> 7, d = j & 127;
        float acc = 0.f;
        for (int kk = 0; kk < NK; kk++) acc = fmaf(pr[qi][kk], vs[kk][d], acc);
        whl(tout, (size_t)(b * NQ + qi) * 2048, 1024, hd * DHD + d, acc);
    }
}

// ---------------- layernorm (row per block); fp32 + bf16 hi|lo out ----------------
__global__ void ln_kernel(const float* __restrict__ x,
                          const float* __restrict__ g, const float* __restrict__ be,
                          float* __restrict__ out, __nv_bfloat16* __restrict__ tout)
{
    int r = blockIdx.x, t = threadIdx.x;   // 256 threads
    __shared__ float xs[HH];
    __shared__ float red[256];
    const float* xr = x + (size_t)r * HH;
    float s = 0.f;
    for (int i = t; i < HH; i += 256) { float v = xr[i]; xs[i] = v; s += v; }
    red[t] = s; __syncthreads();
    for (int o = 128; o > 0; o >>= 1) { if (t < o) red[t] += red[t+o]; __syncthreads(); }
    float mean = red[0] * (1.f / HH);
    __syncthreads();
    float s2 = 0.f;
    for (int i = t; i < HH; i += 256) { float d = xs[i] - mean; s2 += d * d; }
    red[t] = s2; __syncthreads();
    for (int o = 128; o > 0; o >>= 1) { if (t < o) red[t] += red[t+o]; __syncthreads(); }
    float inv = rsqrtf(red[0] * (1.f / HH) + 1e-5f);
    for (int i = t; i < HH; i += 256) {
        float v = (xs[i] - mean) * inv * g[i] + be[i];
        out[(size_t)r * HH + i] = v;
        whl(tout, (size_t)r * 2048, 1024, i, v);
    }
}

// ---------------- salience logits ----------------
__global__ void logits_kernel(const float* __restrict__ hbuf, const float* __restrict__ w,
                              const float* __restrict__ b2)
{
    int r = blockIdx.x, t = threadIdx.x;  // 128
    __shared__ float red[128];
    float s = 0.f;
    for (int i = t; i < HH; i += 128) s = fmaf(hbuf[(size_t)r * HH + i], w[i], s);
    red[t] = s; __syncthreads();
    for (int o = 64; o > 0; o >>= 1) { if (t < o) red[t] += red[t+o]; __syncthreads(); }
    if (t == 0) g_logits[r] = red[0] + b2[0];
}

// ---------------- salience softmax + entropy + weighted segments (bf16 out) ----------------
__global__ void salience_kernel() {
    int b = blockIdx.x, t = threadIdx.x;  // 256
    __shared__ float sal_s[NS];
    if (t == 0) {
        float mx = -1e30f;
        for (int s = 0; s < NS; s++) mx = fmaxf(mx, g_logits[b*NS + s]);
        float sm = 0.f;
        for (int s = 0; s < NS; s++) { float e = expf(g_logits[b*NS + s] - mx); sal_s[s] = e; sm += e; }
        float inv = 1.f / sm, ent = 0.f;
        for (int s = 0; s < NS; s++) {
            sal_s[s] *= inv;
            g_sal[b*NS + s] = sal_s[s];
            ent -= sal_s[s] * logf(sal_s[s] + 1e-8f);
        }
        g_entpart[b] = ent;
    }
    __syncthreads();
    for (int i = t; i < NS * HH; i += 256) {
        int s = i >> 10, k = i & 1023;
        float v = g_seg1[(size_t)b * NS * HH + i] * sal_s[s];
        whl(g_bf_wseg, (size_t)(b * NS + s) * 2048, 1024, k, v);
    }
}

// ---------------- redundancy ----------------
__global__ void red_kernel() {
    int b = blockIdx.x, t = threadIdx.x;  // 128
    __shared__ float ps[NP][HH+1];
    __shared__ float nrm[NP];
    __shared__ float parr[16];
    for (int i = t; i < NP * HH; i += 128) ps[i >> 10][i & 1023] = g_plan[(size_t)b * NP * HH + i];
    __syncthreads();
    if (t < NP) {
        float s = 0.f;
        for (int d = 0; d < HH; d++) s = fmaf(ps[t][d], ps[t][d], s);
        nrm[t] = fmaxf(sqrtf(s), 1e-12f);
    }
    __syncthreads();
    if (t < 15) {
        int i = 0, j = 0, c = t;
        for (i = 0; i < NP; i++) { int row = NP - 1 - i; if (c < row) { j = i + 1 + c; break; } c -= row; }
        float s = 0.f;
        for (int d = 0; d < HH; d++) s = fmaf(ps[i][d], ps[j][d], s);
        float sim = s / (nrm[i] * nrm[j]);
        parr[t] = 2.f * sim * sim;
    }
    __syncthreads();
    if (t == 0) {
        float s = 0.f;
        for (int p = 0; p < 15; p++) s += parr[p];
        g_redpart[b] = s;
    }
}

// ---------------- output assembly ----------------
__global__ void copy_plan_kernel(float* __restrict__ out, int n) {
    int i = blockIdx.x * 256 + threadIdx.x;
    if (i < n) out[i] = g_plan[i];
}

__global__ void finalize_kernel(float* __restrict__ out, int out_size) {
    int t = threadIdx.x;  // 256
    if (PLAN_ELEMS + t < out_size && t < NB*NS) out[PLAN_ELEMS + t] = g_sal[t];
    if (t == 0) {
        if (PLAN_ELEMS + 256 < out_size) {
            float e = 0.f;
            for (int b = 0; b < NB; b++) e += g_entpart[b];
            out[PLAN_ELEMS + 256] = e / (float)NB;
        }
        if (PLAN_ELEMS + 257 < out_size) {
            float r = 0.f;
            for (int b = 0; b < NB; b++) r += g_redpart[b];
            out[PLAN_ELEMS + 257] = r / (float)(NB * NP * (NP - 1));
        }
    }
}

// ---------------- host helper ----------------
// ks: (3K/ks) % 32 == 0; ks*M*N <= 8M floats
static void run_gemm(const __nv_bfloat16* A, const __nv_bfloat16* W, int M, int N, int K, int ks,
                     const float* bias, const float* res, float* out, int gelu, float* part,
                     __nv_bfloat16* tout)
{
    dim3 grid((M + 127) / 128, N / 128, ks);
    gemm_bf16_kernel<<<grid, 256>>>(A, W, part, M, N, K, ks);
    int tot = M * N;
    epilogue_kernel<<<(tot + 255) / 256, 256>>>(part, bias, res, out, tout, M, N, ks, gelu);
}

extern "C" void kernel_launch(void* const* d_in, const int* in_sizes, int n_in,
                              void* d_out, int out_size)
{
    const float* ts       = (const float*)d_in[0];
    const int*   mask     = (const int*)  d_in[1];
    const float* sa_in_w  = (const float*)d_in[2];
    const float* sa_in_b  = (const float*)d_in[3];
    const float* sa_out_w = (const float*)d_in[4];
    const float* sa_out_b = (const float*)d_in[5];
    const float* ln_g     = (const float*)d_in[6];
    const float* ln_b     = (const float*)d_in[7];
    const float* sal_w1   = (const float*)d_in[8];
    const float* sal_b1   = (const float*)d_in[9];
    const float* sal_w2   = (const float*)d_in[10];
    const float* sal_b2   = (const float*)d_in[11];
    const float* plan_q   = (const float*)d_in[12];
    const float* qa_in_w  = (const float*)d_in[13];
    const float* qa_in_b  = (const float*)d_in[14];
    const float* qa_out_w = (const float*)d_in[15];
    const float* qa_out_b = (const float*)d_in[16];
    const float* r_in_w   = (const float*)d_in[17];
    const float* r_in_b   = (const float*)d_in[18];
    const float* r_out_w  = (const float*)d_in[19];
    const float* r_out_b  = (const float*)d_in[20];
    const float* r_ln1_g  = (const float*)d_in[21];
    const float* r_ln1_b  = (const float*)d_in[22];
    const float* r_ln2_g  = (const float*)d_in[23];
    const float* r_ln2_b  = (const float*)d_in[24];
    const float* r_w1     = (const float*)d_in[25];
    const float* r_b1     = (const float*)d_in[26];
    const float* r_w2     = (const float*)d_in[27];
    const float* r_b2     = (const float*)d_in[28];
    float* out = (float*)d_out;

    float *p_part, *p_seg0, *p_qkv, *p_tmp, *p_seg1, *p_h, *p_qh, *p_kv, *p_plan, *p_qkvr, *p_ffn;
    cudaGetSymbolAddress((void**)&p_part, g_part);
    cudaGetSymbolAddress((void**)&p_seg0, g_seg0);
    cudaGetSymbolAddress((void**)&p_qkv,  g_qkv);
    cudaGetSymbolAddress((void**)&p_tmp,  g_tmp);
    cudaGetSymbolAddress((void**)&p_seg1, g_seg1);
    cudaGetSymbolAddress((void**)&p_h,    g_hbuf);
    cudaGetSymbolAddress((void**)&p_qh,   g_qh);
    cudaGetSymbolAddress((void**)&p_kv,   g_kv);
    cudaGetSymbolAddress((void**)&p_plan, g_plan);
    cudaGetSymbolAddress((void**)&p_qkvr, g_qkvr);
    cudaGetSymbolAddress((void**)&p_ffn,  g_ffn);

    __nv_bfloat16 *t_seg0, *t_o, *t_seg1, *t_wseg, *t_pq, *t_o2, *t_y, *t_o3, *t_ffn, *wbf;
    cudaGetSymbolAddress((void**)&t_seg0, g_bf_seg0);
    cudaGetSymbolAddress((void**)&t_o,    g_bf_o);
    cudaGetSymbolAddress((void**)&t_seg1, g_bf_seg1);
    cudaGetSymbolAddress((void**)&t_wseg, g_bf_wseg);
    cudaGetSymbolAddress((void**)&t_pq,   g_bf_pq);
    cudaGetSymbolAddress((void**)&t_o2,   g_bf_o2);
    cudaGetSymbolAddress((void**)&t_y,    g_bf_y);
    cudaGetSymbolAddress((void**)&t_o3,   g_bf_o3);
    cudaGetSymbolAddress((void**)&t_ffn,  g_bf_ffn);
    cudaGetSymbolAddress((void**)&wbf,    g_wbf);

    // 0) convert all weights (+plan_q) to bf16 hi|lo
    CvtTab tab;
    tab.src[0]=sa_in_w;  tab.dst[0]=wbf+WOFF_SAIN;  tab.n[0]=3145728; tab.logK[0]=10;
    tab.src[1]=sa_out_w; tab.dst[1]=wbf+WOFF_SAOUT; tab.n[1]=1048576; tab.logK[1]=10;
    tab.src[2]=sal_w1;   tab.dst[2]=wbf+WOFF_SAL1;  tab.n[2]=1048576; tab.logK[2]=10;
    tab.src[3]=qa_in_w;  tab.dst[3]=wbf+WOFF_QAIN;  tab.n[3]=3145728; tab.logK[3]=10;
    tab.src[4]=qa_out_w; tab.dst[4]=wbf+WOFF_QAOUT; tab.n[4]=1048576; tab.logK[4]=10;
    tab.src[5]=r_in_w;   tab.dst[5]=wbf+WOFF_RIN;   tab.n[5]=6291456; tab.logK[5]=10;
    tab.src[6]=r_out_w;  tab.dst[6]=wbf+WOFF_ROUT;  tab.n[6]=2097152; tab.logK[6]=10;
    tab.src[7]=r_w1;     tab.dst[7]=wbf+WOFF_RW1;   tab.n[7]=8388608; tab.logK[7]=10;
    tab.src[8]=r_w2;     tab.dst[8]=wbf+WOFF_RW2;   tab.n[8]=8388608; tab.logK[8]=12;
    tab.src[9]=plan_q;   tab.dst[9]=t_pq;           tab.n[9]=6144;    tab.logK[9]=10;
    convert_kernel<<<dim3(2048, 10), 256>>>(tab);

    // 1) lengths + bounds, segment pooling
    lengths_kernel<<<16, 256>>>(mask);
    segpool_partial<<<dim3(NB*NS, 4), 256>>>(ts);
    segpool_finish<<<(NB*NS*HH)/256, 256>>>();

    // 2) segment self-attention
    run_gemm(t_seg0, wbf+WOFF_SAIN, 256, 3*HH, HH, 8, sa_in_b, nullptr, p_qkv, 0, p_part, nullptr);
    attn_kernel<<<dim3(NB, NHEAD), 128>>>(p_qkv, p_qkv + HH, p_qkv + 2*HH, t_o,
                                          16, 16,
                                          3*HH, (long long)NS*3*HH,
                                          3*HH, (long long)NS*3*HH,
                                          3*HH, (long long)NS*3*HH);
    run_gemm(t_o, wbf+WOFF_SAOUT, 256, HH, HH, 8, sa_out_b, p_seg0, p_tmp, 0, p_part, nullptr);
    ln_kernel<<<256, 256>>>(p_tmp, ln_g, ln_b, p_seg1, t_seg1);

    // 3) salience
    run_gemm(t_seg1, wbf+WOFF_SAL1, 256, HH, HH, 8, sal_b1, nullptr, p_h, 1, p_part, nullptr);
    logits_kernel<<<256, 128>>>(p_h, sal_w2, sal_b2);
    salience_kernel<<<16, 256>>>();

    // 4) plan cross-attention (qh is batch-independent)
    run_gemm(t_pq, wbf+WOFF_QAIN, NP, HH, HH, 16, qa_in_b, nullptr, p_qh, 0, p_part, nullptr);
    run_gemm(t_wseg, wbf+WOFF_QAIN + (size_t)HH*2*HH, 256, 2*HH, HH, 8,
             qa_in_b + HH, nullptr, p_kv, 0, p_part, nullptr);
    attn_kernel<<<dim3(NB, NHEAD), 128>>>(p_qh, p_kv, p_kv + HH, t_o2,
                                          NP, 16,
                                          HH,   0LL,
                                          2*HH, (long long)NS*2*HH,
                                          2*HH, (long long)NS*2*HH);
    run_gemm(t_o2, wbf+WOFF_QAOUT, NB*NP, HH, HH, 12, qa_out_b, nullptr, p_plan, 0, p_part, nullptr);

    // 5) refinement transformer layers (norm_first)
    for (int l = 0; l < 2; l++) {
        // fp32 LN output goes to scratch p_tmp — p_plan must stay intact (residual stream)
        ln_kernel<<<NB*NP, 256>>>(p_plan, r_ln1_g + l*HH, r_ln1_b + l*HH, p_tmp, t_y);
        run_gemm(t_y, wbf+WOFF_RIN + (size_t)l*6291456, NB*NP, 3*HH, HH, 8,
                 r_in_b + l*3*HH, nullptr, p_qkvr, 0, p_part, nullptr);
        attn_kernel<<<dim3(NB, NHEAD), 128>>>(p_qkvr, p_qkvr + HH, p_qkvr + 2*HH, t_o3,
                                              NP, NP,
                                              3*HH, (long long)NP*3*HH,
                                              3*HH, (long long)NP*3*HH,
                                              3*HH, (long long)NP*3*HH);
        run_gemm(t_o3, wbf+WOFF_ROUT + (size_t)l*2097152, NB*NP, HH, HH, 12,
                 r_out_b + l*HH, p_plan, p_plan, 0, p_part, nullptr);
        ln_kernel<<<NB*NP, 256>>>(p_plan, r_ln2_g + l*HH, r_ln2_b + l*HH, p_tmp, t_y);
        run_gemm(t_y, wbf+WOFF_RW1 + (size_t)l*8388608, NB*NP, 4*HH, HH, 8,
                 r_b1 + l*4*HH, nullptr, p_ffn, 1, p_part, t_ffn);
        run_gemm(t_ffn, wbf+WOFF_RW2 + (size_t)l*8388608, NB*NP, HH, 4*HH, 32,
                 r_b2 + l*HH, p_plan, p_plan, 0, p_part, nullptr);
    }

    // 6) outputs
    int ncopy = out_size < PLAN_ELEMS ? out_size : PLAN_ELEMS;
    copy_plan_kernel<<<(ncopy + 255) / 256, 256>>>(out, ncopy);
    red_kernel<<<16, 128>>>();
    finalize_kernel<<<1, 256>>>(out, out_size);
}

// round 10
// speedup vs baseline: 1.4910x; 1.0602x over previous
#include <cuda_runtime.h>
#include <cuda_bf16.h>
#include <math.h>

// ---------------- problem constants ----------------
#define NB 16      // batch
#define NT 4096    // tokens
#define HH 1024    // hidden
#define NS 16      // segments
#define NP 6       // plan slots
#define NHEAD 8
#define DHD 128    // head dim
#define PLAN_ELEMS (NB*NP*HH)   // 98304

// ---------------- device scratch (static, no allocs) ----------------
__device__ int   g_bounds[NB*(NS+1)];
__device__ float g_poolpart[4*NB*NS*HH];
__device__ float g_seg0[NB*NS*HH];
__device__ float g_qkv[NB*NS*3*HH];
__device__ float g_seg1[NB*NS*HH];
__device__ float g_logits[NB*NS];
__device__ float g_sal[NB*NS];
__device__ float g_qh[NP*HH];
__device__ float g_kv[NB*NS*2*HH];
__device__ float g_plan[NB*NP*HH];
__device__ float g_qkvr[NB*NP*3*HH];
__device__ float g_part[8*1024*1024];          // split-K partials (32MB)
__device__ float g_entpart[NB];
__device__ float g_redpart[NB];
__device__ int   g_red_cnt;

// bf16 [hi(K)|lo(K)] operand buffers
__device__ __nv_bfloat16 g_bf_seg0[256*2048];
__device__ __nv_bfloat16 g_bf_o   [256*2048];
__device__ __nv_bfloat16 g_bf_seg1[256*2048];
__device__ __nv_bfloat16 g_bf_wseg[256*2048];
__device__ __nv_bfloat16 g_bf_pq  [NP*2048];
__device__ __nv_bfloat16 g_bf_o2  [96*2048];
__device__ __nv_bfloat16 g_bf_y   [96*2048];
__device__ __nv_bfloat16 g_bf_o3  [96*2048];
__device__ __nv_bfloat16 g_bf_ffn [96*8192];
__device__ __nv_bfloat16 g_wbf[69206016];      // all weights hi|lo (138MB)

// weight offsets into g_wbf (bf16 elems)
#define WOFF_SAIN   0LL
#define WOFF_SAOUT  6291456LL
#define WOFF_SAL1   8388608LL
#define WOFF_QAIN   10485760LL
#define WOFF_QAOUT  16777216LL
#define WOFF_RIN    18874368LL
#define WOFF_ROUT   31457280LL
#define WOFF_RW1    35651584LL
#define WOFF_RW2    52428800LL

// ---------------- helpers ----------------
__device__ __forceinline__ unsigned smem_u32(const void* p) {
    unsigned a;
    asm("{ .reg .u64 t; cvta.to.shared.u64 t, %1; cvt.u32.u64 %0, t; }" : "=r"(a) : "l"(p));
    return a;
}
__device__ __forceinline__ unsigned pack_pair(float f0, float f1, bool lo) {
    if (lo) {
        f0 = f0 - __bfloat162float(__float2bfloat16(f0));
        f1 = f1 - __bfloat162float(__float2bfloat16(f1));
    }
    __nv_bfloat162 p = __floats2bfloat162_rn(f0, f1);
    return *reinterpret_cast<unsigned*>(&p);
}
__device__ __forceinline__ void cp16(unsigned dst, const void* src, int sz) {
    asm volatile("cp.async.ca.shared.global [%0], [%1], 16, %2;"
                 :: "r"(dst), "l"(src), "r"(sz));
}
__device__ __forceinline__ void whl(__nv_bfloat16* t, size_t rowbase, int K, int k, float v) {
    __nv_bfloat16 h = __float2bfloat16(v);
    __nv_bfloat16 l = __float2bfloat16(v - __bfloat162float(h));
    t[rowbase + k] = h;
    t[rowbase + K + k] = l;
}
// store 4 consecutive hi + 4 lo bf16 from a float4
__device__ __forceinline__ void whl4(__nv_bfloat16* t, size_t rowbase, int N, int col, float4 v) {
    unsigned h0 = pack_pair(v.x, v.y, false), h1 = pack_pair(v.z, v.w, false);
    unsigned l0 = pack_pair(v.x, v.y, true),  l1 = pack_pair(v.z, v.w, true);
    __nv_bfloat16* tr = t + rowbase + col;
    *(uint2*)tr       = make_uint2(h0, h1);
    *(uint2*)(tr + N) = make_uint2(l0, l1);
}
__device__ __forceinline__ float gelu_f(float v) {
    return 0.5f * v * (1.f + erff(v * 0.70710678118654752f));
}

// ---------------- weight conversion (all tensors, one launch) ----------------
struct CvtTab {
    const float* src[10];
    __nv_bfloat16* dst[10];
    int n[10];
    int logK[10];
};
__global__ void convert_kernel(CvtTab tab) {
    int tsel = blockIdx.y;
    const float* s = tab.src[tsel];
    __nv_bfloat16* d = tab.dst[tsel];
    long long n = tab.n[tsel];
    int logK = tab.logK[tsel];
    int K = 1 << logK;
    long long stride = (long long)gridDim.x * blockDim.x * 4;
    for (long long idx = ((long long)blockIdx.x * blockDim.x + threadIdx.x) * 4;
         idx < n; idx += stride) {
        float4 v = *(const float4*)(s + idx);
        int k = (int)(idx & (K - 1));
        long long row = idx >> logK;
        __nv_bfloat16* dr = d + row * (2LL * K) + k;
        unsigned h0 = pack_pair(v.x, v.y, false), h1 = pack_pair(v.z, v.w, false);
        unsigned l0 = pack_pair(v.x, v.y, true),  l1 = pack_pair(v.z, v.w, true);
        *(uint2*)dr       = make_uint2(h0, h1);
        *(uint2*)(dr + K) = make_uint2(l0, l1);
    }
}

// ---------------- lengths + segment bounds ----------------
__global__ void lengths_kernel(const int* __restrict__ mask) {
    int b = blockIdx.x;
    __shared__ int red[256];
    int t = threadIdx.x;
    int s = 0;
    for (int i = t; i < NT; i += 256) s += mask[b*NT + i];
    red[t] = s; __syncthreads();
    for (int o = 128; o > 0; o >>= 1) { if (t < o) red[t] += red[t+o]; __syncthreads(); }
    if (t == 0) {
        int L = red[0];
        for (int k = 0; k <= NS; k++) g_bounds[b*(NS+1) + k] = (k * L) / NS;
    }
}

// ---------------- segment pooling ----------------
__global__ void segpool_partial(const float* __restrict__ ts) {
    int seg = blockIdx.x;
    int b = seg >> 4, s = seg & 15;
    int slice = blockIdx.y;
    int lo = g_bounds[b*(NS+1) + s], hi = g_bounds[b*(NS+1) + s + 1];
    int cnt = hi - lo;
    int chunk = (cnt + 3) >> 2;
    int r0 = lo + slice * chunk;
    int r1 = min(hi, r0 + chunk);
    int t = threadIdx.x;
    float4 acc = make_float4(0.f,0.f,0.f,0.f);
    const float* base = ts + (size_t)b * NT * HH;
    for (int r = r0; r < r1; r++) {
        float4 v = *(const float4*)(base + (size_t)r * HH + t * 4);
        acc.x += v.x; acc.y += v.y; acc.z += v.z; acc.w += v.w;
    }
    *(float4*)&g_poolpart[((size_t)slice * NB*NS + seg) * HH + t * 4] = acc;
}

__global__ void segpool_finish() {
    int idx = blockIdx.x * 256 + threadIdx.x;   // < 262144
    int seg = idx >> 10, k = idx & 1023;
    int b = seg >> 4, s = seg & 15;
    float cnt = (float)(g_bounds[b*(NS+1)+s+1] - g_bounds[b*(NS+1)+s]);
    const int ST = NB*NS*HH;
    float v = g_poolpart[idx] + g_poolpart[ST + idx] + g_poolpart[2*ST + idx] + g_poolpart[3*ST + idx];
    v /= fmaxf(cnt, 1.f);
    g_seg0[idx] = v;
    whl(g_bf_seg0, (size_t)seg * 2048, 1024, k, v);
}

// ---------------- bf16 split-K GEMM (mma.sync, cp.async double-buffered) ----------------
// Compensated: virtual K' = 3K; phase 0: A_hi*W_hi, 1: A_lo*W_hi, 2: A_hi*W_lo.
// A,W stored [rows, 2K] = [hi(K)|lo(K)]. 128x128 tile, BK=32, 256 thr, 8 warps 64x32.
#define SA 40   // padded smem row stride (bf16) => 80B

__global__ void __launch_bounds__(256) gemm_bf16_kernel(
    const __nv_bfloat16* __restrict__ A, const __nv_bfloat16* __restrict__ W,
    float* __restrict__ P, int M, int N, int K, int kslices)
{
    __shared__ __align__(16) __nv_bfloat16 As[2][128*SA];
    __shared__ __align__(16) __nv_bfloat16 Bs[2][128*SA];
    int tid = threadIdx.x, wid = tid >> 5, lane = tid & 31;
    int m0 = blockIdx.x * 128, n0 = blockIdx.y * 128;
    int K2 = 2 * K;
    int Kper = (3 * K) / kslices, kstart = blockIdx.z * Kper, nch = Kper >> 5;
    int wm = (wid & 1) * 64, wn = (wid >> 1) * 32;
    unsigned sA = smem_u32(As), sB = smem_u32(Bs);
    const unsigned STG = 128 * SA * 2;   // bytes per stage

    int r0 = tid >> 2, s0 = tid & 3;
    int f1 = tid + 256, r1 = f1 >> 2, s1 = f1 & 3;
    int szA0 = (m0 + r0 < M) ? 16 : 0, szA1 = (m0 + r1 < M) ? 16 : 0;
    const __nv_bfloat16* a0 = A + (size_t)(szA0 ? (m0 + r0) : 0) * K2 + s0 * 8;
    const __nv_bfloat16* a1 = A + (size_t)(szA1 ? (m0 + r1) : 0) * K2 + s1 * 8;
    const __nv_bfloat16* w0 = W + (size_t)(n0 + r0) * K2 + s0 * 8;
    const __nv_bfloat16* w1 = W + (size_t)(n0 + r1) * K2 + s1 * 8;
    unsigned dA0 = sA + (r0*SA + s0*8)*2, dA1 = sA + (r1*SA + s1*8)*2;
    unsigned dB0 = sB + (r0*SA + s0*8)*2, dB1 = sB + (r1*SA + s1*8)*2;

#define LOAD_STAGE(c, st) { \
    int kpr = kstart + (c)*32; int ph = kpr / K; int kb = kpr - ph*K; \
    int offA = (ph == 1) ? K : 0; int offW = (ph == 2) ? K : 0; \
    unsigned so = (unsigned)(st) * STG; \
    cp16(dA0 + so, a0 + offA + kb, szA0); cp16(dA1 + so, a1 + offA + kb, szA1); \
    cp16(dB0 + so, w0 + offW + kb, 16);   cp16(dB1 + so, w1 + offW + kb, 16); \
    asm volatile("cp.async.commit_group;"); }

    float acc[4][4][4];
#pragma unroll
    for (int a = 0; a < 4; a++)
#pragma unroll
        for (int b = 0; b < 4; b++)
#pragma unroll
            for (int c = 0; c < 4; c++) acc[a][b][c] = 0.f;

    LOAD_STAGE(0, 0);

    int g = lane >> 3, r = lane & 7;
    for (int c = 0; c < nch; c++) {
        if (c + 1 < nch) {
            LOAD_STAGE(c + 1, (c + 1) & 1);
            asm volatile("cp.async.wait_group 1;");
        } else {
            asm volatile("cp.async.wait_group 0;");
        }
        __syncthreads();
        unsigned bA = sA + (unsigned)(c & 1) * STG, bB = sB + (unsigned)(c & 1) * STG;
#pragma unroll
        for (int ks = 0; ks < 2; ks++) {
            unsigned af[4][4], bf[4][2];
#pragma unroll
            for (int mt = 0; mt < 4; mt++) {
                unsigned addr = bA + (unsigned)(((wm + mt*16 + (g & 1)*8 + r) * SA
                                       + ks*16 + (g >> 1)*8) * 2);
                asm volatile("ldmatrix.sync.aligned.m8n8.x4.shared.b16 {%0,%1,%2,%3}, [%4];"
                    : "=r"(af[mt][0]), "=r"(af[mt][1]), "=r"(af[mt][2]), "=r"(af[mt][3])
                    : "r"(addr));
            }
#pragma unroll
            for (int np = 0; np < 2; np++) {
                unsigned t0,t1,t2,t3;
                unsigned addr = bB + (unsigned)(((wn + np*16 + (g >> 1)*8 + r) * SA
                                       + ks*16 + (g & 1)*8) * 2);
                asm volatile("ldmatrix.sync.aligned.m8n8.x4.shared.b16 {%0,%1,%2,%3}, [%4];"
                    : "=r"(t0), "=r"(t1), "=r"(t2), "=r"(t3) : "r"(addr));
                bf[2*np][0] = t0; bf[2*np][1] = t1;
                bf[2*np+1][0] = t2; bf[2*np+1][1] = t3;
            }
#pragma unroll
            for (int mt = 0; mt < 4; mt++)
#pragma unroll
                for (int nt = 0; nt < 4; nt++) {
                    asm volatile(
                        "mma.sync.aligned.m16n8k16.row.col.f32.bf16.bf16.f32 "
                        "{%0,%1,%2,%3}, {%4,%5,%6,%7}, {%8,%9}, {%0,%1,%2,%3};"
                        : "+f"(acc[mt][nt][0]), "+f"(acc[mt][nt][1]),
                          "+f"(acc[mt][nt][2]), "+f"(acc[mt][nt][3])
                        : "r"(af[mt][0]), "r"(af[mt][1]), "r"(af[mt][2]), "r"(af[mt][3]),
                          "r"(bf[nt][0]), "r"(bf[nt][1]));
                }
        }
        __syncthreads();
    }

    size_t base = (size_t)blockIdx.z * M * N;
#pragma unroll
    for (int mt = 0; mt < 4; mt++) {
        int m = m0 + wm + mt*16 + (lane >> 2);
#pragma unroll
        for (int nt = 0; nt < 4; nt++) {
            int n = n0 + wn + nt*8 + (lane & 3)*2;
            if (m < M)
                *(float2*)(P + base + (size_t)m * N + n)
                    = make_float2(acc[mt][nt][0], acc[mt][nt][1]);
            if (m + 8 < M)
                *(float2*)(P + base + (size_t)(m+8) * N + n)
                    = make_float2(acc[mt][nt][2], acc[mt][nt][3]);
        }
    }
#undef LOAD_STAGE
}

// ---------------- plain epilogue (vectorized): out = [gelu](sum P + bias)[+res] ----------------
__global__ void epilogue_kernel(const float* __restrict__ P, const float* __restrict__ bias,
                                const float* __restrict__ res, float* __restrict__ out,
                                float* __restrict__ out2, int out2_lim,
                                __nv_bfloat16* __restrict__ tout,
                                int M, int N, int kslices, int gelu)
{
    int idx = (blockIdx.x * 256 + threadIdx.x) * 4;
    if (idx >= M * N) return;
    int n = idx % N, m = idx / N;
    size_t MN = (size_t)M * N;
    float4 v = make_float4(0.f,0.f,0.f,0.f);
    for (int s = 0; s < kslices; s++) {
        float4 p = *(const float4*)(P + (size_t)s * MN + idx);
        v.x += p.x; v.y += p.y; v.z += p.z; v.w += p.w;
    }
    float4 b4 = *(const float4*)(bias + n);
    v.x += b4.x; v.y += b4.y; v.z += b4.z; v.w += b4.w;
    if (gelu) { v.x = gelu_f(v.x); v.y = gelu_f(v.y); v.z = gelu_f(v.z); v.w = gelu_f(v.w); }
    if (res) {
        float4 r4 = *(const float4*)(res + idx);
        v.x += r4.x; v.y += r4.y; v.z += r4.z; v.w += r4.w;
    }
    if (out)  *(float4*)(out + idx) = v;
    if (out2 && idx + 4 <= out2_lim) *(float4*)(out2 + idx) = v;
    if (tout) whl4(tout, (size_t)m * 2 * N, N, n, v);
}

// ---------------- fused epilogue + layernorm (N=1024; one block per row) ----------------
__global__ void epilogue_ln_kernel(const float* __restrict__ P, const float* __restrict__ bias,
                                   const float* __restrict__ res,
                                   const float* __restrict__ g, const float* __restrict__ be,
                                   float* __restrict__ epi_out, float* __restrict__ ln_out,
                                   __nv_bfloat16* __restrict__ tout,
                                   int M, int kslices)
{
    int m = blockIdx.x, t = threadIdx.x;      // 256 threads, 4 cols each
    __shared__ float red[256];
    int col = t * 4;
    size_t MN = (size_t)M * HH;
    const float* Pm = P + (size_t)m * HH + col;
    float4 v = make_float4(0.f,0.f,0.f,0.f);
    for (int s = 0; s < kslices; s++) {
        float4 p = *(const float4*)(Pm + (size_t)s * MN);
        v.x += p.x; v.y += p.y; v.z += p.z; v.w += p.w;
    }
    float4 b4 = *(const float4*)(bias + col);
    v.x += b4.x; v.y += b4.y; v.z += b4.z; v.w += b4.w;
    if (res) {
        float4 r4 = *(const float4*)(res + (size_t)m * HH + col);
        v.x += r4.x; v.y += r4.y; v.z += r4.z; v.w += r4.w;
    }
    if (epi_out) *(float4*)(epi_out + (size_t)m * HH + col) = v;

    red[t] = v.x + v.y + v.z + v.w; __syncthreads();
    for (int o = 128; o > 0; o >>= 1) { if (t < o) red[t] += red[t+o]; __syncthreads(); }
    float mean = red[0] * (1.f / HH);
    __syncthreads();
    float dx = v.x - mean, dy = v.y - mean, dz = v.z - mean, dw = v.w - mean;
    red[t] = dx*dx + dy*dy + dz*dz + dw*dw; __syncthreads();
    for (int o = 128; o > 0; o >>= 1) { if (t < o) red[t] += red[t+o]; __syncthreads(); }
    float inv = rsqrtf(red[0] * (1.f / HH) + 1e-5f);

    float4 g4 = *(const float4*)(g + col);
    float4 e4 = *(const float4*)(be + col);
    float4 o4;
    o4.x = dx * inv * g4.x + e4.x;
    o4.y = dy * inv * g4.y + e4.y;
    o4.z = dz * inv * g4.z + e4.z;
    o4.w = dw * inv * g4.w + e4.w;
    if (ln_out) *(float4*)(ln_out + (size_t)m * HH + col) = o4;
    whl4(tout, (size_t)m * 2048, 1024, col, o4);
}

// ---------------- fused gelu-epilogue + salience logits (N=1024; block per row) ----------------
__global__ void epilogue_logits_kernel(const float* __restrict__ P, const float* __restrict__ bias,
                                       const float* __restrict__ w2, const float* __restrict__ b2,
                                       int M, int kslices)
{
    int m = blockIdx.x, t = threadIdx.x;  // 256
    __shared__ float red[256];
    int col = t * 4;
    size_t MN = (size_t)M * HH;
    const float* Pm = P + (size_t)m * HH + col;
    float4 v = make_float4(0.f,0.f,0.f,0.f);
    for (int s = 0; s < kslices; s++) {
        float4 p = *(const float4*)(Pm + (size_t)s * MN);
        v.x += p.x; v.y += p.y; v.z += p.z; v.w += p.w;
    }
    float4 b4 = *(const float4*)(bias + col);
    v.x = gelu_f(v.x + b4.x); v.y = gelu_f(v.y + b4.y);
    v.z = gelu_f(v.z + b4.z); v.w = gelu_f(v.w + b4.w);
    float4 w = *(const float4*)(w2 + col);
    red[t] = v.x*w.x + v.y*w.y + v.z*w.z + v.w*w.w; __syncthreads();
    for (int o = 128; o > 0; o >>= 1) { if (t < o) red[t] += red[t+o]; __syncthreads(); }
    if (t == 0) g_logits[m] = red[0] + b2[0];
}

// ---------------- small attention: one (b, head) per block; bf16 hi|lo output ----------------
__global__ void attn_kernel(const float* __restrict__ qb, const float* __restrict__ kb,
                            const float* __restrict__ vb, __nv_bfloat16* __restrict__ tout,
                            int NQ, int NK,
                            int qRowStr, long long qBatStr,
                            int kRowStr, long long kBatStr,
                            int vRowStr, long long vBatStr)
{
    int b = blockIdx.x, hd = blockIdx.y;
    const float* q = qb + b * qBatStr + hd * DHD;
    const float* k = kb + b * kBatStr + hd * DHD;
    const float* v = vb + b * vBatStr + hd * DHD;
    __shared__ float qs[16][DHD+1], ks[16][DHD+1], vs[16][DHD+1];
    __shared__ float pr[16][17];
    int t = threadIdx.x;  // 128
    for (int i = 0; i < NQ; i++) qs[i][t] = q[(size_t)i * qRowStr + t];
    for (int i = 0; i < NK; i++) { ks[i][t] = k[(size_t)i * kRowStr + t]; vs[i][t] = v[(size_t)i * vRowStr + t]; }
    __syncthreads();
    const float scale = 0.08838834764831843f;   // 1/sqrt(128)
    for (int p = t; p < NQ * NK; p += 128) {
        int qi = p / NK, ki = p - qi * NK;
        float acc = 0.f;
#pragma unroll 4
        for (int d = 0; d < DHD; d++) acc = fmaf(qs[qi][d], ks[ki][d], acc);
        pr[qi][ki] = acc * scale;
    }
    __syncthreads();
    if (t < NQ) {
        float mx = -1e30f;
        for (int kk = 0; kk < NK; kk++) mx = fmaxf(mx, pr[t][kk]);
        float sm = 0.f;
        for (int kk = 0; kk < NK; kk++) { float e = expf(pr[t][kk] - mx); pr[t][kk] = e; sm += e; }
        float inv = 1.f / sm;
        for (int kk = 0; kk < NK; kk++) pr[t][kk] *= inv;
    }
    __syncthreads();
    for (int j = t; j < NQ * DHD; j += 128) {
        int qi = j >> 7, d = j & 127;
        float acc = 0.f;
        for (int kk = 0; kk < NK; kk++) acc = fmaf(pr[qi][kk], vs[kk][d], acc);
        whl(tout, (size_t)(b * NQ + qi) * 2048, 1024, hd * DHD + d, acc);
    }
}

// ---------------- salience softmax + entropy + weighted segments (bf16 out) ----------------
__global__ void salience_kernel() {
    int b = blockIdx.x, t = threadIdx.x;  // 256
    __shared__ float sal_s[NS];
    if (b == 0 && t == 0) g_red_cnt = 0;    // reset for fused red+finalize
    if (t == 0) {
        float mx = -1e30f;
        for (int s = 0; s < NS; s++) mx = fmaxf(mx, g_logits[b*NS + s]);
        float sm = 0.f;
        for (int s = 0; s < NS; s++) { float e = expf(g_logits[b*NS + s] - mx); sal_s[s] = e; sm += e; }
        float inv = 1.f / sm, ent = 0.f;
        for (int s = 0; s < NS; s++) {
            sal_s[s] *= inv;
            g_sal[b*NS + s] = sal_s[s];
            ent -= sal_s[s] * logf(sal_s[s] + 1e-8f);
        }
        g_entpart[b] = ent;
    }
    __syncthreads();
    for (int i = t; i < NS * HH; i += 256) {
        int s = i >> 10, k = i & 1023;
        float v = g_seg1[(size_t)b * NS * HH + i] * sal_s[s];
        whl(g_bf_wseg, (size_t)(b * NS + s) * 2048, 1024, k, v);
    }
}

// ---------------- redundancy + fused finalize (last block) ----------------
__global__ void red_kernel(float* __restrict__ out, int out_size) {
    int b = blockIdx.x, t = threadIdx.x;  // 128
    __shared__ float ps[NP][HH+1];
    __shared__ float nrm[NP];
    __shared__ float parr[16];
    __shared__ int lastflag;
    for (int i = t; i < NP * HH; i += 128) ps[i >> 10][i & 1023] = g_plan[(size_t)b * NP * HH + i];
    __syncthreads();
    if (t < NP) {
        float s = 0.f;
        for (int d = 0; d < HH; d++) s = fmaf(ps[t][d], ps[t][d], s);
        nrm[t] = fmaxf(sqrtf(s), 1e-12f);
    }
    __syncthreads();
    if (t < 15) {
        int i = 0, j = 0, c = t;
        for (i = 0; i < NP; i++) { int row = NP - 1 - i; if (c < row) { j = i + 1 + c; break; } c -= row; }
        float s = 0.f;
        for (int d = 0; d < HH; d++) s = fmaf(ps[i][d], ps[j][d], s);
        float sim = s / (nrm[i] * nrm[j]);
        parr[t] = 2.f * sim * sim;
    }
    __syncthreads();
    if (t == 0) {
        float s = 0.f;
        for (int p = 0; p < 15; p++) s += parr[p];
        g_redpart[b] = s;
        __threadfence();
        int old = atomicAdd(&g_red_cnt, 1);
        lastflag = (old == NB - 1);
    }
    __syncthreads();
    if (lastflag) {
        for (int i = t; i < NB*NS; i += 128)
            if (PLAN_ELEMS + i < out_size) out[PLAN_ELEMS + i] = g_sal[i];
        if (t == 0) {
            if (PLAN_ELEMS + 256 < out_size) {
                float e = 0.f;
                for (int bb = 0; bb < NB; bb++) e += g_entpart[bb];
                out[PLAN_ELEMS + 256] = e / (float)NB;
            }
            if (PLAN_ELEMS + 257 < out_size) {
                float r = 0.f;
                for (int bb = 0; bb < NB; bb++) r += g_redpart[bb];
                out[PLAN_ELEMS + 257] = r / (float)(NB * NP * (NP - 1));
            }
        }
    }
}

// ---------------- host helpers ----------------
static void gemm(const __nv_bfloat16* A, const __nv_bfloat16* W, int M, int N, int K, int ks,
                 float* part)
{
    dim3 grid((M + 127) / 128, N / 128, ks);
    gemm_bf16_kernel<<<grid, 256>>>(A, W, part, M, N, K, ks);
}
static void epi(const float* P, const float* bias, const float* res, float* out,
                float* out2, int out2_lim, __nv_bfloat16* tout, int M, int N, int ks, int gelu)
{
    int blocks = (M * N + 1023) / 1024;
    epilogue_kernel<<<blocks, 256>>>(P, bias, res, out, out2, out2_lim, tout, M, N, ks, gelu);
}

extern "C" void kernel_launch(void* const* d_in, const int* in_sizes, int n_in,
                              void* d_out, int out_size)
{
    const float* ts       = (const float*)d_in[0];
    const int*   mask     = (const int*)  d_in[1];
    const float* sa_in_w  = (const float*)d_in[2];
    const float* sa_in_b  = (const float*)d_in[3];
    const float* sa_out_w = (const float*)d_in[4];
    const float* sa_out_b = (const float*)d_in[5];
    const float* ln_g     = (const float*)d_in[6];
    const float* ln_b     = (const float*)d_in[7];
    const float* sal_w1   = (const float*)d_in[8];
    const float* sal_b1   = (const float*)d_in[9];
    const float* sal_w2   = (const float*)d_in[10];
    const float* sal_b2   = (const float*)d_in[11];
    const float* plan_q   = (const float*)d_in[12];
    const float* qa_in_w  = (const float*)d_in[13];
    const float* qa_in_b  = (const float*)d_in[14];
    const float* qa_out_w = (const float*)d_in[15];
    const float* qa_out_b = (const float*)d_in[16];
    const float* r_in_w   = (const float*)d_in[17];
    const float* r_in_b   = (const float*)d_in[18];
    const float* r_out_w  = (const float*)d_in[19];
    const float* r_out_b  = (const float*)d_in[20];
    const float* r_ln1_g  = (const float*)d_in[21];
    const float* r_ln1_b  = (const float*)d_in[22];
    const float* r_ln2_g  = (const float*)d_in[23];
    const float* r_ln2_b  = (const float*)d_in[24];
    const float* r_w1     = (const float*)d_in[25];
    const float* r_b1     = (const float*)d_in[26];
    const float* r_w2     = (const float*)d_in[27];
    const float* r_b2     = (const float*)d_in[28];
    float* out = (float*)d_out;

    float *p_part, *p_seg0, *p_qkv, *p_seg1, *p_qh, *p_kv, *p_plan, *p_qkvr;
    cudaGetSymbolAddress((void**)&p_part, g_part);
    cudaGetSymbolAddress((void**)&p_seg0, g_seg0);
    cudaGetSymbolAddress((void**)&p_qkv,  g_qkv);
    cudaGetSymbolAddress((void**)&p_seg1, g_seg1);
    cudaGetSymbolAddress((void**)&p_qh,   g_qh);
    cudaGetSymbolAddress((void**)&p_kv,   g_kv);
    cudaGetSymbolAddress((void**)&p_plan, g_plan);
    cudaGetSymbolAddress((void**)&p_qkvr, g_qkvr);

    __nv_bfloat16 *t_seg0, *t_o, *t_seg1, *t_wseg, *t_pq, *t_o2, *t_y, *t_o3, *t_ffn, *wbf;
    cudaGetSymbolAddress((void**)&t_seg0, g_bf_seg0);
    cudaGetSymbolAddress((void**)&t_o,    g_bf_o);
    cudaGetSymbolAddress((void**)&t_seg1, g_bf_seg1);
    cudaGetSymbolAddress((void**)&t_wseg, g_bf_wseg);
    cudaGetSymbolAddress((void**)&t_pq,   g_bf_pq);
    cudaGetSymbolAddress((void**)&t_o2,   g_bf_o2);
    cudaGetSymbolAddress((void**)&t_y,    g_bf_y);
    cudaGetSymbolAddress((void**)&t_o3,   g_bf_o3);
    cudaGetSymbolAddress((void**)&t_ffn,  g_bf_ffn);
    cudaGetSymbolAddress((void**)&wbf,    g_wbf);

    // 0) convert all weights (+plan_q) to bf16 hi|lo
    CvtTab tab;
    tab.src[0]=sa_in_w;  tab.dst[0]=wbf+WOFF_SAIN;  tab.n[0]=3145728; tab.logK[0]=10;
    tab.src[1]=sa_out_w; tab.dst[1]=wbf+WOFF_SAOUT; tab.n[1]=1048576; tab.logK[1]=10;
    tab.src[2]=sal_w1;   tab.dst[2]=wbf+WOFF_SAL1;  tab.n[2]=1048576; tab.logK[2]=10;
    tab.src[3]=qa_in_w;  tab.dst[3]=wbf+WOFF_QAIN;  tab.n[3]=3145728; tab.logK[3]=10;
    tab.src[4]=qa_out_w; tab.dst[4]=wbf+WOFF_QAOUT; tab.n[4]=1048576; tab.logK[4]=10;
    tab.src[5]=r_in_w;   tab.dst[5]=wbf+WOFF_RIN;   tab.n[5]=6291456; tab.logK[5]=10;
    tab.src[6]=r_out_w;  tab.dst[6]=wbf+WOFF_ROUT;  tab.n[6]=2097152; tab.logK[6]=10;
    tab.src[7]=r_w1;     tab.dst[7]=wbf+WOFF_RW1;   tab.n[7]=8388608; tab.logK[7]=10;
    tab.src[8]=r_w2;     tab.dst[8]=wbf+WOFF_RW2;   tab.n[8]=8388608; tab.logK[8]=12;
    tab.src[9]=plan_q;   tab.dst[9]=t_pq;           tab.n[9]=6144;    tab.logK[9]=10;
    convert_kernel<<<dim3(2048, 10), 256>>>(tab);

    // 1) lengths + bounds, segment pooling
    lengths_kernel<<<16, 256>>>(mask);
    segpool_partial<<<dim3(NB*NS, 4), 256>>>(ts);
    segpool_finish<<<(NB*NS*HH)/256, 256>>>();

    // 2) segment self-attention
    gemm(t_seg0, wbf+WOFF_SAIN, 256, 3*HH, HH, 8, p_part);
    epi(p_part, sa_in_b, nullptr, p_qkv, nullptr, 0, nullptr, 256, 3*HH, 8, 0);
    attn_kernel<<<dim3(NB, NHEAD), 128>>>(p_qkv, p_qkv + HH, p_qkv + 2*HH, t_o,
                                          16, 16,
                                          3*HH, (long long)NS*3*HH,
                                          3*HH, (long long)NS*3*HH,
                                          3*HH, (long long)NS*3*HH);
    gemm(t_o, wbf+WOFF_SAOUT, 256, HH, HH, 8, p_part);
    epilogue_ln_kernel<<<256, 256>>>(p_part, sa_out_b, p_seg0, ln_g, ln_b,
                                     nullptr, p_seg1, t_seg1, 256, 8);

    // 3) salience (gelu-epilogue + logits fused)
    gemm(t_seg1, wbf+WOFF_SAL1, 256, HH, HH, 8, p_part);
    epilogue_logits_kernel<<<256, 256>>>(p_part, sal_b1, sal_w2, sal_b2, 256, 8);
    salience_kernel<<<16, 256>>>();

    // 4) plan cross-attention (qh batch-independent)
    gemm(t_pq, wbf+WOFF_QAIN, NP, HH, HH, 16, p_part);
    epi(p_part, qa_in_b, nullptr, p_qh, nullptr, 0, nullptr, NP, HH, 16, 0);
    gemm(t_wseg, wbf+WOFF_QAIN + (size_t)HH*2*HH, 256, 2*HH, HH, 8, p_part);
    epi(p_part, qa_in_b + HH, nullptr, p_kv, nullptr, 0, nullptr, 256, 2*HH, 8, 0);
    attn_kernel<<<dim3(NB, NHEAD), 128>>>(p_qh, p_kv, p_kv + HH, t_o2,
                                          NP, 16,
                                          HH,   0LL,
                                          2*HH, (long long)NS*2*HH,
                                          2*HH, (long long)NS*2*HH);
    gemm(t_o2, wbf+WOFF_QAOUT, NB*NP, HH, HH, 12, p_part);
    // fused: plan = epi result; t_y = LN1(l=0)(plan)
    epilogue_ln_kernel<<<NB*NP, 256>>>(p_part, qa_out_b, nullptr, r_ln1_g, r_ln1_b,
                                       p_plan, nullptr, t_y, NB*NP, 12);

    // 5) refinement transformer layers (norm_first)
    for (int l = 0; l < 2; l++) {
        gemm(t_y, wbf+WOFF_RIN + (size_t)l*6291456, NB*NP, 3*HH, HH, 8, p_part);
        epi(p_part, r_in_b + l*3*HH, nullptr, p_qkvr, nullptr, 0, nullptr, NB*NP, 3*HH, 8, 0);
        attn_kernel<<<dim3(NB, NHEAD), 128>>>(p_qkvr, p_qkvr + HH, p_qkvr + 2*HH, t_o3,
                                              NP, NP,
                                              3*HH, (long long)NP*3*HH,
                                              3*HH, (long long)NP*3*HH,
                                              3*HH, (long long)NP*3*HH);
        gemm(t_o3, wbf+WOFF_ROUT + (size_t)l*2097152, NB*NP, HH, HH, 12, p_part);
        // fused: plan += attn_out; t_y = LN2(l)(plan)
        epilogue_ln_kernel<<<NB*NP, 256>>>(p_part, r_out_b + l*HH, p_plan,
                                           r_ln2_g + l*HH, r_ln2_b + l*HH,
                                           p_plan, nullptr, t_y, NB*NP, 12);
        gemm(t_y, wbf+WOFF_RW1 + (size_t)l*8388608, NB*NP, 4*HH, HH, 8, p_part);
        epi(p_part, r_b1 + l*4*HH, nullptr, nullptr, nullptr, 0, t_ffn, NB*NP, 4*HH, 8, 1);
        gemm(t_ffn, wbf+WOFF_RW2 + (size_t)l*8388608, NB*NP, HH, 4*HH, 32, p_part);
        if (l == 0) {
            // fused: plan += ffn; t_y = LN1(l=1)(plan)
            epilogue_ln_kernel<<<NB*NP, 256>>>(p_part, r_b2, p_plan,
                                               r_ln1_g + HH, r_ln1_b + HH,
                                               p_plan, nullptr, t_y, NB*NP, 32);
        } else {
            // final: plan += ffn; also write plan region of d_out directly
            int lim = out_size < PLAN_ELEMS ? out_size : PLAN_ELEMS;
            epi(p_part, r_b2 + HH, p_plan, p_plan, out, lim, nullptr, NB*NP, HH, 32, 0);
        }
    }

    // 6) redundancy + finalize (fused)
    red_kernel<<<16, 128>>>(out, out_size);
}

// round 11
// speedup vs baseline: 1.4925x; 1.0010x over previous
#include <cuda_runtime.h>
#include <cuda_bf16.h>
#include <math.h>

// ---------------- problem constants ----------------
#define NB 16      // batch
#define NT 4096    // tokens
#define HH 1024    // hidden
#define NS 16      // segments
#define NP 6       // plan slots
#define NHEAD 8
#define DHD 128    // head dim
#define PLAN_ELEMS (NB*NP*HH)   // 98304

// ---------------- device scratch (static, no allocs) ----------------
__device__ int   g_bounds[NB*(NS+1)];
__device__ float g_seg0[NB*NS*HH];
__device__ float g_qkv[NB*NS*3*HH];
__device__ float g_seg1[NB*NS*HH];
__device__ float g_logits[NB*NS];
__device__ float g_sal[NB*NS];
__device__ float g_qh[NP*HH];
__device__ float g_kv[NB*NS*2*HH];
__device__ float g_plan[NB*NP*HH];
__device__ float g_qkvr[NB*NP*3*HH];
__device__ float g_part[8*1024*1024];          // split-K partials (32MB)
__device__ float g_entpart[NB];
__device__ float g_redpart[NB];
__device__ int   g_red_cnt;

// bf16 [hi(K)|lo(K)] operand buffers
__device__ __nv_bfloat16 g_bf_seg0[256*2048];
__device__ __nv_bfloat16 g_bf_o   [256*2048];
__device__ __nv_bfloat16 g_bf_seg1[256*2048];
__device__ __nv_bfloat16 g_bf_wseg[256*2048];
__device__ __nv_bfloat16 g_bf_pq  [NP*2048];
__device__ __nv_bfloat16 g_bf_o2  [96*2048];
__device__ __nv_bfloat16 g_bf_y   [96*2048];
__device__ __nv_bfloat16 g_bf_o3  [96*2048];
__device__ __nv_bfloat16 g_bf_ffn [96*8192];
__device__ __nv_bfloat16 g_wbf[69206016];      // all weights hi|lo (138MB)

// weight offsets into g_wbf (bf16 elems)
#define WOFF_SAIN   0LL
#define WOFF_SAOUT  6291456LL
#define WOFF_SAL1   8388608LL
#define WOFF_QAIN   10485760LL
#define WOFF_QAOUT  16777216LL
#define WOFF_RIN    18874368LL
#define WOFF_ROUT   31457280LL
#define WOFF_RW1    35651584LL
#define WOFF_RW2    52428800LL

// ---------------- helpers ----------------
__device__ __forceinline__ unsigned smem_u32(const void* p) {
    unsigned a;
    asm("{ .reg .u64 t; cvta.to.shared.u64 t, %1; cvt.u32.u64 %0, t; }" : "=r"(a) : "l"(p));
    return a;
}
__device__ __forceinline__ unsigned pack_pair(float f0, float f1, bool lo) {
    if (lo) {
        f0 = f0 - __bfloat162float(__float2bfloat16(f0));
        f1 = f1 - __bfloat162float(__float2bfloat16(f1));
    }
    __nv_bfloat162 p = __floats2bfloat162_rn(f0, f1);
    return *reinterpret_cast<unsigned*>(&p);
}
__device__ __forceinline__ void cp16(unsigned dst, const void* src, int sz) {
    asm volatile("cp.async.ca.shared.global [%0], [%1], 16, %2;"
                 :: "r"(dst), "l"(src), "r"(sz));
}
__device__ __forceinline__ void whl(__nv_bfloat16* t, size_t rowbase, int K, int k, float v) {
    __nv_bfloat16 h = __float2bfloat16(v);
    __nv_bfloat16 l = __float2bfloat16(v - __bfloat162float(h));
    t[rowbase + k] = h;
    t[rowbase + K + k] = l;
}
__device__ __forceinline__ void whl4(__nv_bfloat16* t, size_t rowbase, int N, int col, float4 v) {
    unsigned h0 = pack_pair(v.x, v.y, false), h1 = pack_pair(v.z, v.w, false);
    unsigned l0 = pack_pair(v.x, v.y, true),  l1 = pack_pair(v.z, v.w, true);
    __nv_bfloat16* tr = t + rowbase + col;
    *(uint2*)tr       = make_uint2(h0, h1);
    *(uint2*)(tr + N) = make_uint2(l0, l1);
}
__device__ __forceinline__ float gelu_f(float v) {
    return 0.5f * v * (1.f + erff(v * 0.70710678118654752f));
}

// ---------------- weight conversion (all tensors, one launch) ----------------
struct CvtTab {
    const float* src[10];
    __nv_bfloat16* dst[10];
    int n[10];
    int logK[10];
};
__global__ void convert_kernel(CvtTab tab) {
    int tsel = blockIdx.y;
    const float* s = tab.src[tsel];
    __nv_bfloat16* d = tab.dst[tsel];
    long long n = tab.n[tsel];
    int logK = tab.logK[tsel];
    int K = 1 << logK;
    long long stride = (long long)gridDim.x * blockDim.x * 4;
    for (long long idx = ((long long)blockIdx.x * blockDim.x + threadIdx.x) * 4;
         idx < n; idx += stride) {
        float4 v = *(const float4*)(s + idx);
        int k = (int)(idx & (K - 1));
        long long row = idx >> logK;
        __nv_bfloat16* dr = d + row * (2LL * K) + k;
        unsigned h0 = pack_pair(v.x, v.y, false), h1 = pack_pair(v.z, v.w, false);
        unsigned l0 = pack_pair(v.x, v.y, true),  l1 = pack_pair(v.z, v.w, true);
        *(uint2*)dr       = make_uint2(h0, h1);
        *(uint2*)(dr + K) = make_uint2(l0, l1);
    }
}

// ---------------- lengths + segment bounds ----------------
__global__ void lengths_kernel(const int* __restrict__ mask) {
    int b = blockIdx.x;
    __shared__ int red[256];
    int t = threadIdx.x;
    int s = 0;
    for (int i = t; i < NT; i += 256) s += mask[b*NT + i];
    red[t] = s; __syncthreads();
    for (int o = 128; o > 0; o >>= 1) { if (t < o) red[t] += red[t+o]; __syncthreads(); }
    if (t == 0) {
        int L = red[0];
        for (int k = 0; k <= NS; k++) g_bounds[b*(NS+1) + k] = (k * L) / NS;
    }
}

// ---------------- fused segment pooling (single kernel, 4-row unrolled) ----------------
__global__ void segpool_kernel(const float* __restrict__ ts) {
    int seg = blockIdx.x;                 // 0..255
    int b = seg >> 4, s = seg & 15;
    int lo = g_bounds[b*(NS+1) + s], hi = g_bounds[b*(NS+1) + s + 1];
    int cnt = hi - lo;
    int t = threadIdx.x;                  // 256 threads, 4 cols each
    const float* base = ts + (size_t)b * NT * HH + t * 4;
    float4 a0 = make_float4(0.f,0.f,0.f,0.f), a1 = a0, a2 = a0, a3 = a0;
    int r = lo;
    for (; r + 4 <= hi; r += 4) {
        float4 v0 = *(const float4*)(base + (size_t)(r+0) * HH);
        float4 v1 = *(const float4*)(base + (size_t)(r+1) * HH);
        float4 v2 = *(const float4*)(base + (size_t)(r+2) * HH);
        float4 v3 = *(const float4*)(base + (size_t)(r+3) * HH);
        a0.x += v0.x; a0.y += v0.y; a0.z += v0.z; a0.w += v0.w;
        a1.x += v1.x; a1.y += v1.y; a1.z += v1.z; a1.w += v1.w;
        a2.x += v2.x; a2.y += v2.y; a2.z += v2.z; a2.w += v2.w;
        a3.x += v3.x; a3.y += v3.y; a3.z += v3.z; a3.w += v3.w;
    }
    for (; r < hi; r++) {
        float4 v = *(const float4*)(base + (size_t)r * HH);
        a0.x += v.x; a0.y += v.y; a0.z += v.z; a0.w += v.w;
    }
    float inv = 1.f / fmaxf((float)cnt, 1.f);
    float4 v;
    v.x = (a0.x + a1.x + a2.x + a3.x) * inv;
    v.y = (a0.y + a1.y + a2.y + a3.y) * inv;
    v.z = (a0.z + a1.z + a2.z + a3.z) * inv;
    v.w = (a0.w + a1.w + a2.w + a3.w) * inv;
    *(float4*)&g_seg0[(size_t)seg * HH + t*4] = v;
    whl4(g_bf_seg0, (size_t)seg * 2048, 1024, t*4, v);
}

// ---------------- bf16 split-K GEMM (compensated, 4-tile smem, cp.async 2-stage) ----------------
// D = A_hi*W_hi + A_lo*W_hi + A_hi*W_lo.  A,W stored [rows, 2K] = [hi(K)|lo(K)].
// 128x128 tile, BK=32, 256 thr, 8 warps 64x32. Per k-chunk loads all 4 operand
// tiles once; 3 phase passes run from smem. Dynamic smem: 2 stages x 4 x 10240B = 80KB.
#define SA 40   // padded smem row stride (bf16) => 80B
#define MATB (128*SA*2)        // 10240 bytes per tile
#define STGB (4*MATB)          // 40960 bytes per stage

__global__ void __launch_bounds__(256) gemm_bf16_kernel(
    const __nv_bfloat16* __restrict__ A, const __nv_bfloat16* __restrict__ W,
    float* __restrict__ P, int M, int N, int K, int kslices)
{
    extern __shared__ __align__(16) unsigned char smem[];
    int tid = threadIdx.x, wid = tid >> 5, lane = tid & 31;
    int m0 = blockIdx.x * 128, n0 = blockIdx.y * 128;
    int K2 = 2 * K;
    int Kper = K / kslices, kstart = blockIdx.z * Kper, nch = Kper >> 5;
    int wm = (wid & 1) * 64, wn = (wid >> 1) * 32;
    unsigned sm = smem_u32(smem);

    int r0 = tid >> 2, s0 = tid & 3;
    int f1 = tid + 256, r1 = f1 >> 2, s1 = f1 & 3;
    int szA0 = (m0 + r0 < M) ? 16 : 0, szA1 = (m0 + r1 < M) ? 16 : 0;
    const __nv_bfloat16* a0 = A + (size_t)(szA0 ? (m0 + r0) : 0) * K2 + s0 * 8;
    const __nv_bfloat16* a1 = A + (size_t)(szA1 ? (m0 + r1) : 0) * K2 + s1 * 8;
    const __nv_bfloat16* w0 = W + (size_t)(n0 + r0) * K2 + s0 * 8;
    const __nv_bfloat16* w1 = W + (size_t)(n0 + r1) * K2 + s1 * 8;
    unsigned o0 = (unsigned)(r0*SA + s0*8)*2, o1 = (unsigned)(r1*SA + s1*8)*2;

#define LOAD_STAGE(c, st) { \
    int kb = kstart + (c)*32; \
    unsigned so = sm + (unsigned)(st) * STGB; \
    cp16(so + o0,          a0 + kb,     szA0); cp16(so + o1,          a1 + kb,     szA1); \
    cp16(so + MATB + o0,   a0 + K + kb, szA0); cp16(so + MATB + o1,   a1 + K + kb, szA1); \
    cp16(so + 2*MATB + o0, w0 + kb,     16);   cp16(so + 2*MATB + o1, w1 + kb,     16); \
    cp16(so + 3*MATB + o0, w0 + K + kb, 16);   cp16(so + 3*MATB + o1, w1 + K + kb, 16); \
    asm volatile("cp.async.commit_group;"); }

    float acc[4][4][4];
#pragma unroll
    for (int a = 0; a < 4; a++)
#pragma unroll
        for (int b = 0; b < 4; b++)
#pragma unroll
            for (int c = 0; c < 4; c++) acc[a][b][c] = 0.f;

    LOAD_STAGE(0, 0);

    int g = lane >> 3, r = lane & 7;
    for (int c = 0; c < nch; c++) {
        if (c + 1 < nch) {
            LOAD_STAGE(c + 1, (c + 1) & 1);
            asm volatile("cp.async.wait_group 1;");
        } else {
            asm volatile("cp.async.wait_group 0;");
        }
        __syncthreads();
        unsigned st = sm + (unsigned)(c & 1) * STGB;
#pragma unroll
        for (int ph = 0; ph < 3; ph++) {
            unsigned bA = st + ((ph == 1) ? MATB : 0u);
            unsigned bB = st + 2u*MATB + ((ph == 2) ? MATB : 0u);
#pragma unroll
            for (int ks = 0; ks < 2; ks++) {
                unsigned af[4][4], bf[4][2];
#pragma unroll
                for (int mt = 0; mt < 4; mt++) {
                    unsigned addr = bA + (unsigned)(((wm + mt*16 + (g & 1)*8 + r) * SA
                                           + ks*16 + (g >> 1)*8) * 2);
                    asm volatile("ldmatrix.sync.aligned.m8n8.x4.shared.b16 {%0,%1,%2,%3}, [%4];"
                        : "=r"(af[mt][0]), "=r"(af[mt][1]), "=r"(af[mt][2]), "=r"(af[mt][3])
                        : "r"(addr));
                }
#pragma unroll
                for (int np = 0; np < 2; np++) {
                    unsigned t0,t1,t2,t3;
                    unsigned addr = bB + (unsigned)(((wn + np*16 + (g >> 1)*8 + r) * SA
                                           + ks*16 + (g & 1)*8) * 2);
                    asm volatile("ldmatrix.sync.aligned.m8n8.x4.shared.b16 {%0,%1,%2,%3}, [%4];"
                        : "=r"(t0), "=r"(t1), "=r"(t2), "=r"(t3) : "r"(addr));
                    bf[2*np][0] = t0; bf[2*np][1] = t1;
                    bf[2*np+1][0] = t2; bf[2*np+1][1] = t3;
                }
#pragma unroll
                for (int mt = 0; mt < 4; mt++)
#pragma unroll
                    for (int nt = 0; nt < 4; nt++) {
                        asm volatile(
                            "mma.sync.aligned.m16n8k16.row.col.f32.bf16.bf16.f32 "
                            "{%0,%1,%2,%3}, {%4,%5,%6,%7}, {%8,%9}, {%0,%1,%2,%3};"
                            : "+f"(acc[mt][nt][0]), "+f"(acc[mt][nt][1]),
                              "+f"(acc[mt][nt][2]), "+f"(acc[mt][nt][3])
                            : "r"(af[mt][0]), "r"(af[mt][1]), "r"(af[mt][2]), "r"(af[mt][3]),
                              "r"(bf[nt][0]), "r"(bf[nt][1]));
                    }
            }
        }
        __syncthreads();
    }

    size_t base = (size_t)blockIdx.z * M * N;
#pragma unroll
    for (int mt = 0; mt < 4; mt++) {
        int m = m0 + wm + mt*16 + (lane >> 2);
#pragma unroll
        for (int nt = 0; nt < 4; nt++) {
            int n = n0 + wn + nt*8 + (lane & 3)*2;
            if (m < M)
                *(float2*)(P + base + (size_t)m * N + n)
                    = make_float2(acc[mt][nt][0], acc[mt][nt][1]);
            if (m + 8 < M)
                *(float2*)(P + base + (size_t)(m+8) * N + n)
                    = make_float2(acc[mt][nt][2], acc[mt][nt][3]);
        }
    }
#undef LOAD_STAGE
}

// ---------------- plain epilogue (vectorized) ----------------
__global__ void epilogue_kernel(const float* __restrict__ P, const float* __restrict__ bias,
                                const float* __restrict__ res, float* __restrict__ out,
                                float* __restrict__ out2, int out2_lim,
                                __nv_bfloat16* __restrict__ tout,
                                int M, int N, int kslices, int gelu)
{
    int idx = (blockIdx.x * 256 + threadIdx.x) * 4;
    if (idx >= M * N) return;
    int n = idx % N, m = idx / N;
    size_t MN = (size_t)M * N;
    float4 v = make_float4(0.f,0.f,0.f,0.f);
    for (int s = 0; s < kslices; s++) {
        float4 p = *(const float4*)(P + (size_t)s * MN + idx);
        v.x += p.x; v.y += p.y; v.z += p.z; v.w += p.w;
    }
    float4 b4 = *(const float4*)(bias + n);
    v.x += b4.x; v.y += b4.y; v.z += b4.z; v.w += b4.w;
    if (gelu) { v.x = gelu_f(v.x); v.y = gelu_f(v.y); v.z = gelu_f(v.z); v.w = gelu_f(v.w); }
    if (res) {
        float4 r4 = *(const float4*)(res + idx);
        v.x += r4.x; v.y += r4.y; v.z += r4.z; v.w += r4.w;
    }
    if (out)  *(float4*)(out + idx) = v;
    if (out2 && idx + 4 <= out2_lim) *(float4*)(out2 + idx) = v;
    if (tout) whl4(tout, (size_t)m * 2 * N, N, n, v);
}

// ---------------- fused epilogue + layernorm (N=1024; one block per row) ----------------
__global__ void epilogue_ln_kernel(const float* __restrict__ P, const float* __restrict__ bias,
                                   const float* __restrict__ res,
                                   const float* __restrict__ g, const float* __restrict__ be,
                                   float* __restrict__ epi_out, float* __restrict__ ln_out,
                                   __nv_bfloat16* __restrict__ tout,
                                   int M, int kslices)
{
    int m = blockIdx.x, t = threadIdx.x;      // 256 threads, 4 cols each
    __shared__ float red[256];
    int col = t * 4;
    size_t MN = (size_t)M * HH;
    const float* Pm = P + (size_t)m * HH + col;
    float4 v = make_float4(0.f,0.f,0.f,0.f);
    for (int s = 0; s < kslices; s++) {
        float4 p = *(const float4*)(Pm + (size_t)s * MN);
        v.x += p.x; v.y += p.y; v.z += p.z; v.w += p.w;
    }
    float4 b4 = *(const float4*)(bias + col);
    v.x += b4.x; v.y += b4.y; v.z += b4.z; v.w += b4.w;
    if (res) {
        float4 r4 = *(const float4*)(res + (size_t)m * HH + col);
        v.x += r4.x; v.y += r4.y; v.z += r4.z; v.w += r4.w;
    }
    if (epi_out) *(float4*)(epi_out + (size_t)m * HH + col) = v;

    red[t] = v.x + v.y + v.z + v.w; __syncthreads();
    for (int o = 128; o > 0; o >>= 1) { if (t < o) red[t] += red[t+o]; __syncthreads(); }
    float mean = red[0] * (1.f / HH);
    __syncthreads();
    float dx = v.x - mean, dy = v.y - mean, dz = v.z - mean, dw = v.w - mean;
    red[t] = dx*dx + dy*dy + dz*dz + dw*dw; __syncthreads();
    for (int o = 128; o > 0; o >>= 1) { if (t < o) red[t] += red[t+o]; __syncthreads(); }
    float inv = rsqrtf(red[0] * (1.f / HH) + 1e-5f);

    float4 g4 = *(const float4*)(g + col);
    float4 e4 = *(const float4*)(be + col);
    float4 o4;
    o4.x = dx * inv * g4.x + e4.x;
    o4.y = dy * inv * g4.y + e4.y;
    o4.z = dz * inv * g4.z + e4.z;
    o4.w = dw * inv * g4.w + e4.w;
    if (ln_out) *(float4*)(ln_out + (size_t)m * HH + col) = o4;
    whl4(tout, (size_t)m * 2048, 1024, col, o4);
}

// ---------------- fused gelu-epilogue + salience logits ----------------
__global__ void epilogue_logits_kernel(const float* __restrict__ P, const float* __restrict__ bias,
                                       const float* __restrict__ w2, const float* __restrict__ b2,
                                       int M, int kslices)
{
    int m = blockIdx.x, t = threadIdx.x;  // 256
    __shared__ float red[256];
    int col = t * 4;
    size_t MN = (size_t)M * HH;
    const float* Pm = P + (size_t)m * HH + col;
    float4 v = make_float4(0.f,0.f,0.f,0.f);
    for (int s = 0; s < kslices; s++) {
        float4 p = *(const float4*)(Pm + (size_t)s * MN);
        v.x += p.x; v.y += p.y; v.z += p.z; v.w += p.w;
    }
    float4 b4 = *(const float4*)(bias + col);
    v.x = gelu_f(v.x + b4.x); v.y = gelu_f(v.y + b4.y);
    v.z = gelu_f(v.z + b4.z); v.w = gelu_f(v.w + b4.w);
    float4 w = *(const float4*)(w2 + col);
    red[t] = v.x*w.x + v.y*w.y + v.z*w.z + v.w*w.w; __syncthreads();
    for (int o = 128; o > 0; o >>= 1) { if (t < o) red[t] += red[t+o]; __syncthreads(); }
    if (t == 0) g_logits[m] = red[0] + b2[0];
}

// ---------------- small attention: one (b, head) per block; bf16 hi|lo output ----------------
__global__ void attn_kernel(const float* __restrict__ qb, const float* __restrict__ kb,
                            const float* __restrict__ vb, __nv_bfloat16* __restrict__ tout,
                            int NQ, int NK,
                            int qRowStr, long long qBatStr,
                            int kRowStr, long long kBatStr,
                            int vRowStr, long long vBatStr)
{
    int b = blockIdx.x, hd = blockIdx.y;
    const float* q = qb + b * qBatStr + hd * DHD;
    const float* k = kb + b * kBatStr + hd * DHD;
    const float* v = vb + b * vBatStr + hd * DHD;
    __shared__ float qs[16][DHD+1], ks[16][DHD+1], vs[16][DHD+1];
    __shared__ float pr[16][17];
    int t = threadIdx.x;  // 128
    for (int i = 0; i < NQ; i++) qs[i][t] = q[(size_t)i * qRowStr + t];
    for (int i = 0; i < NK; i++) { ks[i][t] = k[(size_t)i * kRowStr + t]; vs[i][t] = v[(size_t)i * vRowStr + t]; }
    __syncthreads();
    const float scale = 0.08838834764831843f;   // 1/sqrt(128)
    for (int p = t; p < NQ * NK; p += 128) {
        int qi = p / NK, ki = p - qi * NK;
        float acc = 0.f;
#pragma unroll 4
        for (int d = 0; d < DHD; d++) acc = fmaf(qs[qi][d], ks[ki][d], acc);
        pr[qi][ki] = acc * scale;
    }
    __syncthreads();
    if (t < NQ) {
        float mx = -1e30f;
        for (int kk = 0; kk < NK; kk++) mx = fmaxf(mx, pr[t][kk]);
        float sm = 0.f;
        for (int kk = 0; kk < NK; kk++) { float e = expf(pr[t][kk] - mx); pr[t][kk] = e; sm += e; }
        float inv = 1.f / sm;
        for (int kk = 0; kk < NK; kk++) pr[t][kk] *= inv;
    }
    __syncthreads();
    for (int j = t; j < NQ * DHD; j += 128) {
        int qi = j >> 7, d = j & 127;
        float acc = 0.f;
        for (int kk = 0; kk < NK; kk++) acc = fmaf(pr[qi][kk], vs[kk][d], acc);
        whl(tout, (size_t)(b * NQ + qi) * 2048, 1024, hd * DHD + d, acc);
    }
}

// ---------------- salience softmax + entropy + weighted segments (bf16 out) ----------------
__global__ void salience_kernel() {
    int b = blockIdx.x, t = threadIdx.x;  // 256
    __shared__ float sal_s[NS];
    if (b == 0 && t == 0) g_red_cnt = 0;    // reset for fused red+finalize
    if (t == 0) {
        float mx = -1e30f;
        for (int s = 0; s < NS; s++) mx = fmaxf(mx, g_logits[b*NS + s]);
        float sm = 0.f;
        for (int s = 0; s < NS; s++) { float e = expf(g_logits[b*NS + s] - mx); sal_s[s] = e; sm += e; }
        float inv = 1.f / sm, ent = 0.f;
        for (int s = 0; s < NS; s++) {
            sal_s[s] *= inv;
            g_sal[b*NS + s] = sal_s[s];
            ent -= sal_s[s] * logf(sal_s[s] + 1e-8f);
        }
        g_entpart[b] = ent;
    }
    __syncthreads();
    for (int i = t; i < NS * HH; i += 256) {
        int s = i >> 10, k = i & 1023;
        float v = g_seg1[(size_t)b * NS * HH + i] * sal_s[s];
        whl(g_bf_wseg, (size_t)(b * NS + s) * 2048, 1024, k, v);
    }
}

// ---------------- redundancy + fused finalize (last block) ----------------
__global__ void red_kernel(float* __restrict__ out, int out_size) {
    int b = blockIdx.x, t = threadIdx.x;  // 128
    __shared__ float ps[NP][HH+1];
    __shared__ float nrm[NP];
    __shared__ float parr[16];
    __shared__ int lastflag;
    for (int i = t; i < NP * HH; i += 128) ps[i >> 10][i & 1023] = g_plan[(size_t)b * NP * HH + i];
    __syncthreads();
    if (t < NP) {
        float s = 0.f;
        for (int d = 0; d < HH; d++) s = fmaf(ps[t][d], ps[t][d], s);
        nrm[t] = fmaxf(sqrtf(s), 1e-12f);
    }
    __syncthreads();
    if (t < 15) {
        int i = 0, j = 0, c = t;
        for (i = 0; i < NP; i++) { int row = NP - 1 - i; if (c < row) { j = i + 1 + c; break; } c -= row; }
        float s = 0.f;
        for (int d = 0; d < HH; d++) s = fmaf(ps[i][d], ps[j][d], s);
        float sim = s / (nrm[i] * nrm[j]);
        parr[t] = 2.f * sim * sim;
    }
    __syncthreads();
    if (t == 0) {
        float s = 0.f;
        for (int p = 0; p < 15; p++) s += parr[p];
        g_redpart[b] = s;
        __threadfence();
        int old = atomicAdd(&g_red_cnt, 1);
        lastflag = (old == NB - 1);
    }
    __syncthreads();
    if (lastflag) {
        for (int i = t; i < NB*NS; i += 128)
            if (PLAN_ELEMS + i < out_size) out[PLAN_ELEMS + i] = g_sal[i];
        if (t == 0) {
            if (PLAN_ELEMS + 256 < out_size) {
                float e = 0.f;
                for (int bb = 0; bb < NB; bb++) e += g_entpart[bb];
                out[PLAN_ELEMS + 256] = e / (float)NB;
            }
            if (PLAN_ELEMS + 257 < out_size) {
                float r = 0.f;
                for (int bb = 0; bb < NB; bb++) r += g_redpart[bb];
                out[PLAN_ELEMS + 257] = r / (float)(NB * NP * (NP - 1));
            }
        }
    }
}

// ---------------- host helpers ----------------
// ks: (K/ks) % 32 == 0; ks*M*N <= 8M floats
static void gemm(const __nv_bfloat16* A, const __nv_bfloat16* W, int M, int N, int K, int ks,
                 float* part)
{
    dim3 grid((M + 127) / 128, N / 128, ks);
    gemm_bf16_kernel<<<grid, 256, 2*STGB>>>(A, W, part, M, N, K, ks);
}
static void epi(const float* P, const float* bias, const float* res, float* out,
                float* out2, int out2_lim, __nv_bfloat16* tout, int M, int N, int ks, int gelu)
{
    int blocks = (M * N + 1023) / 1024;
    epilogue_kernel<<<blocks, 256>>>(P, bias, res, out, out2, out2_lim, tout, M, N, ks, gelu);
}

extern "C" void kernel_launch(void* const* d_in, const int* in_sizes, int n_in,
                              void* d_out, int out_size)
{
    const float* ts       = (const float*)d_in[0];
    const int*   mask     = (const int*)  d_in[1];
    const float* sa_in_w  = (const float*)d_in[2];
    const float* sa_in_b  = (const float*)d_in[3];
    const float* sa_out_w = (const float*)d_in[4];
    const float* sa_out_b = (const float*)d_in[5];
    const float* ln_g     = (const float*)d_in[6];
    const float* ln_b     = (const float*)d_in[7];
    const float* sal_w1   = (const float*)d_in[8];
    const float* sal_b1   = (const float*)d_in[9];
    const float* sal_w2   = (const float*)d_in[10];
    const float* sal_b2   = (const float*)d_in[11];
    const float* plan_q   = (const float*)d_in[12];
    const float* qa_in_w  = (const float*)d_in[13];
    const float* qa_in_b  = (const float*)d_in[14];
    const float* qa_out_w = (const float*)d_in[15];
    const float* qa_out_b = (const float*)d_in[16];
    const float* r_in_w   = (const float*)d_in[17];
    const float* r_in_b   = (const float*)d_in[18];
    const float* r_out_w  = (const float*)d_in[19];
    const float* r_out_b  = (const float*)d_in[20];
    const float* r_ln1_g  = (const float*)d_in[21];
    const float* r_ln1_b  = (const float*)d_in[22];
    const float* r_ln2_g  = (const float*)d_in[23];
    const float* r_ln2_b  = (const float*)d_in[24];
    const float* r_w1     = (const float*)d_in[25];
    const float* r_b1     = (const float*)d_in[26];
    const float* r_w2     = (const float*)d_in[27];
    const float* r_b2     = (const float*)d_in[28];
    float* out = (float*)d_out;

    static int smem_set = 0;
    if (!smem_set) {
        cudaFuncSetAttribute(gemm_bf16_kernel,
                             cudaFuncAttributeMaxDynamicSharedMemorySize, 2*STGB);
        smem_set = 1;
    }

    float *p_part, *p_qkv, *p_seg1, *p_qh, *p_kv, *p_plan, *p_qkvr, *p_seg0;
    cudaGetSymbolAddress((void**)&p_part, g_part);
    cudaGetSymbolAddress((void**)&p_seg0, g_seg0);
    cudaGetSymbolAddress((void**)&p_qkv,  g_qkv);
    cudaGetSymbolAddress((void**)&p_seg1, g_seg1);
    cudaGetSymbolAddress((void**)&p_qh,   g_qh);
    cudaGetSymbolAddress((void**)&p_kv,   g_kv);
    cudaGetSymbolAddress((void**)&p_plan, g_plan);
    cudaGetSymbolAddress((void**)&p_qkvr, g_qkvr);

    __nv_bfloat16 *t_seg0, *t_o, *t_seg1, *t_wseg, *t_pq, *t_o2, *t_y, *t_o3, *t_ffn, *wbf;
    cudaGetSymbolAddress((void**)&t_seg0, g_bf_seg0);
    cudaGetSymbolAddress((void**)&t_o,    g_bf_o);
    cudaGetSymbolAddress((void**)&t_seg1, g_bf_seg1);
    cudaGetSymbolAddress((void**)&t_wseg, g_bf_wseg);
    cudaGetSymbolAddress((void**)&t_pq,   g_bf_pq);
    cudaGetSymbolAddress((void**)&t_o2,   g_bf_o2);
    cudaGetSymbolAddress((void**)&t_y,    g_bf_y);
    cudaGetSymbolAddress((void**)&t_o3,   g_bf_o3);
    cudaGetSymbolAddress((void**)&t_ffn,  g_bf_ffn);
    cudaGetSymbolAddress((void**)&wbf,    g_wbf);

    // 0) convert all weights (+plan_q) to bf16 hi|lo
    CvtTab tab;
    tab.src[0]=sa_in_w;  tab.dst[0]=wbf+WOFF_SAIN;  tab.n[0]=3145728; tab.logK[0]=10;
    tab.src[1]=sa_out_w; tab.dst[1]=wbf+WOFF_SAOUT; tab.n[1]=1048576; tab.logK[1]=10;
    tab.src[2]=sal_w1;   tab.dst[2]=wbf+WOFF_SAL1;  tab.n[2]=1048576; tab.logK[2]=10;
    tab.src[3]=qa_in_w;  tab.dst[3]=wbf+WOFF_QAIN;  tab.n[3]=3145728; tab.logK[3]=10;
    tab.src[4]=qa_out_w; tab.dst[4]=wbf+WOFF_QAOUT; tab.n[4]=1048576; tab.logK[4]=10;
    tab.src[5]=r_in_w;   tab.dst[5]=wbf+WOFF_RIN;   tab.n[5]=6291456; tab.logK[5]=10;
    tab.src[6]=r_out_w;  tab.dst[6]=wbf+WOFF_ROUT;  tab.n[6]=2097152; tab.logK[6]=10;
    tab.src[7]=r_w1;     tab.dst[7]=wbf+WOFF_RW1;   tab.n[7]=8388608; tab.logK[7]=10;
    tab.src[8]=r_w2;     tab.dst[8]=wbf+WOFF_RW2;   tab.n[8]=8388608; tab.logK[8]=12;
    tab.src[9]=plan_q;   tab.dst[9]=t_pq;           tab.n[9]=6144;    tab.logK[9]=10;
    convert_kernel<<<dim3(2048, 10), 256>>>(tab);

    // 1) lengths + bounds, fused segment pooling
    lengths_kernel<<<16, 256>>>(mask);
    segpool_kernel<<<NB*NS, 256>>>(ts);

    // 2) segment self-attention
    gemm(t_seg0, wbf+WOFF_SAIN, 256, 3*HH, HH, 8, p_part);
    epi(p_part, sa_in_b, nullptr, p_qkv, nullptr, 0, nullptr, 256, 3*HH, 8, 0);
    attn_kernel<<<dim3(NB, NHEAD), 128>>>(p_qkv, p_qkv + HH, p_qkv + 2*HH, t_o,
                                          16, 16,
                                          3*HH, (long long)NS*3*HH,
                                          3*HH, (long long)NS*3*HH,
                                          3*HH, (long long)NS*3*HH);
    gemm(t_o, wbf+WOFF_SAOUT, 256, HH, HH, 16, p_part);
    epilogue_ln_kernel<<<256, 256>>>(p_part, sa_out_b, p_seg0, ln_g, ln_b,
                                     nullptr, p_seg1, t_seg1, 256, 16);

    // 3) salience (gelu-epilogue + logits fused)
    gemm(t_seg1, wbf+WOFF_SAL1, 256, HH, HH, 16, p_part);
    epilogue_logits_kernel<<<256, 256>>>(p_part, sal_b1, sal_w2, sal_b2, 256, 16);
    salience_kernel<<<16, 256>>>();

    // 4) plan cross-attention (qh batch-independent)
    gemm(t_pq, wbf+WOFF_QAIN, NP, HH, HH, 32, p_part);
    epi(p_part, qa_in_b, nullptr, p_qh, nullptr, 0, nullptr, NP, HH, 32, 0);
    gemm(t_wseg, wbf+WOFF_QAIN + (size_t)HH*2*HH, 256, 2*HH, HH, 8, p_part);
    epi(p_part, qa_in_b + HH, nullptr, p_kv, nullptr, 0, nullptr, 256, 2*HH, 8, 0);
    attn_kernel<<<dim3(NB, NHEAD), 128>>>(p_qh, p_kv, p_kv + HH, t_o2,
                                          NP, 16,
                                          HH,   0LL,
                                          2*HH, (long long)NS*2*HH,
                                          2*HH, (long long)NS*2*HH);
    gemm(t_o2, wbf+WOFF_QAOUT, NB*NP, HH, HH, 16, p_part);
    epilogue_ln_kernel<<<NB*NP, 256>>>(p_part, qa_out_b, nullptr, r_ln1_g, r_ln1_b,
                                       p_plan, nullptr, t_y, NB*NP, 16);

    // 5) refinement transformer layers (norm_first)
    for (int l = 0; l < 2; l++) {
        gemm(t_y, wbf+WOFF_RIN + (size_t)l*6291456, NB*NP, 3*HH, HH, 8, p_part);
        epi(p_part, r_in_b + l*3*HH, nullptr, p_qkvr, nullptr, 0, nullptr, NB*NP, 3*HH, 8, 0);
        attn_kernel<<<dim3(NB, NHEAD), 128>>>(p_qkvr, p_qkvr + HH, p_qkvr + 2*HH, t_o3,
                                              NP, NP,
                                              3*HH, (long long)NP*3*HH,
                                              3*HH, (long long)NP*3*HH,
                                              3*HH, (long long)NP*3*HH);
        gemm(t_o3, wbf+WOFF_ROUT + (size_t)l*2097152, NB*NP, HH, HH, 16, p_part);
        epilogue_ln_kernel<<<NB*NP, 256>>>(p_part, r_out_b + l*HH, p_plan,
                                           r_ln2_g + l*HH, r_ln2_b + l*HH,
                                           p_plan, nullptr, t_y, NB*NP, 16);
        gemm(t_y, wbf+WOFF_RW1 + (size_t)l*8388608, NB*NP, 4*HH, HH, 8, p_part);
        epi(p_part, r_b1 + l*4*HH, nullptr, nullptr, nullptr, 0, t_ffn, NB*NP, 4*HH, 8, 1);
        gemm(t_ffn, wbf+WOFF_RW2 + (size_t)l*8388608, NB*NP, HH, 4*HH, 32, p_part);
        if (l == 0) {
            epilogue_ln_kernel<<<NB*NP, 256>>>(p_part, r_b2, p_plan,
                                               r_ln1_g + HH, r_ln1_b + HH,
                                               p_plan, nullptr, t_y, NB*NP, 32);
        } else {
            int lim = out_size < PLAN_ELEMS ? out_size : PLAN_ELEMS;
            epi(p_part, r_b2 + HH, p_plan, p_plan, out, lim, nullptr, NB*NP, HH, 32, 0);
        }
    }

    // 6) redundancy + finalize (fused)
    red_kernel<<<16, 128>>>(out, out_size);
}

// round 12
// speedup vs baseline: 1.4956x; 1.0020x over previous
#include <cuda_runtime.h>
#include <cuda_bf16.h>
#include <math.h>

// ---------------- problem constants ----------------
#define NB 16      // batch
#define NT 4096    // tokens
#define HH 1024    // hidden
#define NS 16      // segments
#define NP 6       // plan slots
#define NHEAD 8
#define DHD 128    // head dim
#define PLAN_ELEMS (NB*NP*HH)   // 98304

// ---------------- device scratch (static, no allocs) ----------------
__device__ int   g_bounds[NB*(NS+1)];
__device__ float g_seg0[NB*NS*HH];
__device__ float g_qkv[NB*NS*3*HH];
__device__ float g_seg1[NB*NS*HH];
__device__ float g_logits[NB*NS];
__device__ float g_sal[NB*NS];
__device__ float g_qh[NP*HH];
__device__ float g_kv[NB*NS*2*HH];
__device__ float g_plan[NB*NP*HH];
__device__ float g_qkvr[NB*NP*3*HH];
__device__ float g_part[8*1024*1024];          // split-K partials (32MB)
__device__ float g_entpart[NB];
__device__ float g_redpart[NB];
__device__ int   g_red_cnt;

// bf16 [hi(K)|lo(K)] operand buffers
__device__ __nv_bfloat16 g_bf_seg0[256*2048];
__device__ __nv_bfloat16 g_bf_o   [256*2048];
__device__ __nv_bfloat16 g_bf_seg1[256*2048];
__device__ __nv_bfloat16 g_bf_wseg[256*2048];
__device__ __nv_bfloat16 g_bf_pq  [NP*2048];
__device__ __nv_bfloat16 g_bf_o2  [96*2048];
__device__ __nv_bfloat16 g_bf_y   [96*2048];
__device__ __nv_bfloat16 g_bf_o3  [96*2048];
__device__ __nv_bfloat16 g_bf_ffn [96*8192];
__device__ __nv_bfloat16 g_wbf[69206016];      // all weights hi|lo (138MB)

// weight offsets into g_wbf (bf16 elems)
#define WOFF_SAIN   0LL
#define WOFF_SAOUT  6291456LL
#define WOFF_SAL1   8388608LL
#define WOFF_QAIN   10485760LL
#define WOFF_QAOUT  16777216LL
#define WOFF_RIN    18874368LL
#define WOFF_ROUT   31457280LL
#define WOFF_RW1    35651584LL
#define WOFF_RW2    52428800LL

// ---------------- helpers ----------------
__device__ __forceinline__ unsigned smem_u32(const void* p) {
    unsigned a;
    asm("{ .reg .u64 t; cvta.to.shared.u64 t, %1; cvt.u32.u64 %0, t; }" : "=r"(a) : "l"(p));
    return a;
}
__device__ __forceinline__ unsigned pack_pair(float f0, float f1, bool lo) {
    if (lo) {
        f0 = f0 - __bfloat162float(__float2bfloat16(f0));
        f1 = f1 - __bfloat162float(__float2bfloat16(f1));
    }
    __nv_bfloat162 p = __floats2bfloat162_rn(f0, f1);
    return *reinterpret_cast<unsigned*>(&p);
}
__device__ __forceinline__ void cp16(unsigned dst, const void* src, int sz) {
    asm volatile("cp.async.ca.shared.global [%0], [%1], 16, %2;"
                 :: "r"(dst), "l"(src), "r"(sz));
}
__device__ __forceinline__ void whl(__nv_bfloat16* t, size_t rowbase, int K, int k, float v) {
    __nv_bfloat16 h = __float2bfloat16(v);
    __nv_bfloat16 l = __float2bfloat16(v - __bfloat162float(h));
    t[rowbase + k] = h;
    t[rowbase + K + k] = l;
}
__device__ __forceinline__ void whl4(__nv_bfloat16* t, size_t rowbase, int N, int col, float4 v) {
    unsigned h0 = pack_pair(v.x, v.y, false), h1 = pack_pair(v.z, v.w, false);
    unsigned l0 = pack_pair(v.x, v.y, true),  l1 = pack_pair(v.z, v.w, true);
    __nv_bfloat16* tr = t + rowbase + col;
    *(uint2*)tr       = make_uint2(h0, h1);
    *(uint2*)(tr + N) = make_uint2(l0, l1);
}
__device__ __forceinline__ float gelu_f(float v) {
    return 0.5f * v * (1.f + erff(v * 0.70710678118654752f));
}

// ---------------- weight conversion (all tensors, one launch) ----------------
struct CvtTab {
    const float* src[10];
    __nv_bfloat16* dst[10];
    int n[10];
    int logK[10];
};
__global__ void convert_kernel(CvtTab tab) {
    int tsel = blockIdx.y;
    const float* s = tab.src[tsel];
    __nv_bfloat16* d = tab.dst[tsel];
    long long n = tab.n[tsel];
    int logK = tab.logK[tsel];
    int K = 1 << logK;
    long long stride = (long long)gridDim.x * blockDim.x * 4;
    for (long long idx = ((long long)blockIdx.x * blockDim.x + threadIdx.x) * 4;
         idx < n; idx += stride) {
        float4 v = *(const float4*)(s + idx);
        int k = (int)(idx & (K - 1));
        long long row = idx >> logK;
        __nv_bfloat16* dr = d + row * (2LL * K) + k;
        unsigned h0 = pack_pair(v.x, v.y, false), h1 = pack_pair(v.z, v.w, false);
        unsigned l0 = pack_pair(v.x, v.y, true),  l1 = pack_pair(v.z, v.w, true);
        *(uint2*)dr       = make_uint2(h0, h1);
        *(uint2*)(dr + K) = make_uint2(l0, l1);
    }
}

// ---------------- lengths + segment bounds ----------------
__global__ void lengths_kernel(const int* __restrict__ mask) {
    int b = blockIdx.x;
    __shared__ int red[256];
    int t = threadIdx.x;
    int s = 0;
    for (int i = t; i < NT; i += 256) s += mask[b*NT + i];
    red[t] = s; __syncthreads();
    for (int o = 128; o > 0; o >>= 1) { if (t < o) red[t] += red[t+o]; __syncthreads(); }
    if (t == 0) {
        int L = red[0];
        for (int k = 0; k <= NS; k++) g_bounds[b*(NS+1) + k] = (k * L) / NS;
    }
}

// ---------------- fused segment pooling (single kernel, 4-row unrolled) ----------------
__global__ void segpool_kernel(const float* __restrict__ ts) {
    int seg = blockIdx.x;                 // 0..255
    int b = seg >> 4, s = seg & 15;
    int lo = g_bounds[b*(NS+1) + s], hi = g_bounds[b*(NS+1) + s + 1];
    int cnt = hi - lo;
    int t = threadIdx.x;                  // 256 threads, 4 cols each
    const float* base = ts + (size_t)b * NT * HH + t * 4;
    float4 a0 = make_float4(0.f,0.f,0.f,0.f), a1 = a0, a2 = a0, a3 = a0;
    int r = lo;
    for (; r + 4 <= hi; r += 4) {
        float4 v0 = *(const float4*)(base + (size_t)(r+0) * HH);
        float4 v1 = *(const float4*)(base + (size_t)(r+1) * HH);
        float4 v2 = *(const float4*)(base + (size_t)(r+2) * HH);
        float4 v3 = *(const float4*)(base + (size_t)(r+3) * HH);
        a0.x += v0.x; a0.y += v0.y; a0.z += v0.z; a0.w += v0.w;
        a1.x += v1.x; a1.y += v1.y; a1.z += v1.z; a1.w += v1.w;
        a2.x += v2.x; a2.y += v2.y; a2.z += v2.z; a2.w += v2.w;
        a3.x += v3.x; a3.y += v3.y; a3.z += v3.z; a3.w += v3.w;
    }
    for (; r < hi; r++) {
        float4 v = *(const float4*)(base + (size_t)r * HH);
        a0.x += v.x; a0.y += v.y; a0.z += v.z; a0.w += v.w;
    }
    float inv = 1.f / fmaxf((float)cnt, 1.f);
    float4 v;
    v.x = (a0.x + a1.x + a2.x + a3.x) * inv;
    v.y = (a0.y + a1.y + a2.y + a3.y) * inv;
    v.z = (a0.z + a1.z + a2.z + a3.z) * inv;
    v.w = (a0.w + a1.w + a2.w + a3.w) * inv;
    *(float4*)&g_seg0[(size_t)seg * HH + t*4] = v;
    whl4(g_bf_seg0, (size_t)seg * 2048, 1024, t*4, v);
}

// ---------------- bf16 split-K GEMM (compensated, 4-tile smem, cp.async 2-stage) ----------------
// D = A_hi*W_hi + A_lo*W_hi + A_hi*W_lo.  A,W stored [rows, 2K] = [hi(K)|lo(K)].
// 128x128 tile, BK=32, 256 thr, 8 warps 64x32. Per k-chunk loads all 4 operand
// tiles once; 3 phase passes run from smem. Dynamic smem: 2 stages x 4 x 10240B = 80KB.
#define SA 40   // padded smem row stride (bf16) => 80B
#define MATB (128*SA*2)        // 10240 bytes per tile
#define STGB (4*MATB)          // 40960 bytes per stage

__global__ void __launch_bounds__(256) gemm_bf16_kernel(
    const __nv_bfloat16* __restrict__ A, const __nv_bfloat16* __restrict__ W,
    float* __restrict__ P, int M, int N, int K, int kslices)
{
    extern __shared__ __align__(16) unsigned char smem[];
    int tid = threadIdx.x, wid = tid >> 5, lane = tid & 31;
    int m0 = blockIdx.x * 128, n0 = blockIdx.y * 128;
    int K2 = 2 * K;
    int Kper = K / kslices, kstart = blockIdx.z * Kper, nch = Kper >> 5;
    int wm = (wid & 1) * 64, wn = (wid >> 1) * 32;
    unsigned sm = smem_u32(smem);

    int r0 = tid >> 2, s0 = tid & 3;
    int f1 = tid + 256, r1 = f1 >> 2, s1 = f1 & 3;
    int szA0 = (m0 + r0 < M) ? 16 : 0, szA1 = (m0 + r1 < M) ? 16 : 0;
    const __nv_bfloat16* a0 = A + (size_t)(szA0 ? (m0 + r0) : 0) * K2 + s0 * 8;
    const __nv_bfloat16* a1 = A + (size_t)(szA1 ? (m0 + r1) : 0) * K2 + s1 * 8;
    const __nv_bfloat16* w0 = W + (size_t)(n0 + r0) * K2 + s0 * 8;
    const __nv_bfloat16* w1 = W + (size_t)(n0 + r1) * K2 + s1 * 8;
    unsigned o0 = (unsigned)(r0*SA + s0*8)*2, o1 = (unsigned)(r1*SA + s1*8)*2;

#define LOAD_STAGE(c, st) { \
    int kb = kstart + (c)*32; \
    unsigned so = sm + (unsigned)(st) * STGB; \
    cp16(so + o0,          a0 + kb,     szA0); cp16(so + o1,          a1 + kb,     szA1); \
    cp16(so + MATB + o0,   a0 + K + kb, szA0); cp16(so + MATB + o1,   a1 + K + kb, szA1); \
    cp16(so + 2*MATB + o0, w0 + kb,     16);   cp16(so + 2*MATB + o1, w1 + kb,     16); \
    cp16(so + 3*MATB + o0, w0 + K + kb, 16);   cp16(so + 3*MATB + o1, w1 + K + kb, 16); \
    asm volatile("cp.async.commit_group;"); }

    float acc[4][4][4];
#pragma unroll
    for (int a = 0; a < 4; a++)
#pragma unroll
        for (int b = 0; b < 4; b++)
#pragma unroll
            for (int c = 0; c < 4; c++) acc[a][b][c] = 0.f;

    LOAD_STAGE(0, 0);

    int g = lane >> 3, r = lane & 7;
    for (int c = 0; c < nch; c++) {
        if (c + 1 < nch) {
            LOAD_STAGE(c + 1, (c + 1) & 1);
            asm volatile("cp.async.wait_group 1;");
        } else {
            asm volatile("cp.async.wait_group 0;");
        }
        __syncthreads();
        unsigned st = sm + (unsigned)(c & 1) * STGB;
#pragma unroll
        for (int ph = 0; ph < 3; ph++) {
            unsigned bA = st + ((ph == 1) ? MATB : 0u);
            unsigned bB = st + 2u*MATB + ((ph == 2) ? MATB : 0u);
#pragma unroll
            for (int ks = 0; ks < 2; ks++) {
                unsigned af[4][4], bf[4][2];
#pragma unroll
                for (int mt = 0; mt < 4; mt++) {
                    unsigned addr = bA + (unsigned)(((wm + mt*16 + (g & 1)*8 + r) * SA
                                           + ks*16 + (g >> 1)*8) * 2);
                    asm volatile("ldmatrix.sync.aligned.m8n8.x4.shared.b16 {%0,%1,%2,%3}, [%4];"
                        : "=r"(af[mt][0]), "=r"(af[mt][1]), "=r"(af[mt][2]), "=r"(af[mt][3])
                        : "r"(addr));
                }
#pragma unroll
                for (int np = 0; np < 2; np++) {
                    unsigned t0,t1,t2,t3;
                    unsigned addr = bB + (unsigned)(((wn + np*16 + (g >> 1)*8 + r) * SA
                                           + ks*16 + (g & 1)*8) * 2);
                    asm volatile("ldmatrix.sync.aligned.m8n8.x4.shared.b16 {%0,%1,%2,%3}, [%4];"
                        : "=r"(t0), "=r"(t1), "=r"(t2), "=r"(t3) : "r"(addr));
                    bf[2*np][0] = t0; bf[2*np][1] = t1;
                    bf[2*np+1][0] = t2; bf[2*np+1][1] = t3;
                }
#pragma unroll
                for (int mt = 0; mt < 4; mt++)
#pragma unroll
                    for (int nt = 0; nt < 4; nt++) {
                        asm volatile(
                            "mma.sync.aligned.m16n8k16.row.col.f32.bf16.bf16.f32 "
                            "{%0,%1,%2,%3}, {%4,%5,%6,%7}, {%8,%9}, {%0,%1,%2,%3};"
                            : "+f"(acc[mt][nt][0]), "+f"(acc[mt][nt][1]),
                              "+f"(acc[mt][nt][2]), "+f"(acc[mt][nt][3])
                            : "r"(af[mt][0]), "r"(af[mt][1]), "r"(af[mt][2]), "r"(af[mt][3]),
                              "r"(bf[nt][0]), "r"(bf[nt][1]));
                    }
            }
        }
        __syncthreads();
    }

    size_t base = (size_t)blockIdx.z * M * N;
#pragma unroll
    for (int mt = 0; mt < 4; mt++) {
        int m = m0 + wm + mt*16 + (lane >> 2);
#pragma unroll
        for (int nt = 0; nt < 4; nt++) {
            int n = n0 + wn + nt*8 + (lane & 3)*2;
            if (m < M)
                *(float2*)(P + base + (size_t)m * N + n)
                    = make_float2(acc[mt][nt][0], acc[mt][nt][1]);
            if (m + 8 < M)
                *(float2*)(P + base + (size_t)(m+8) * N + n)
                    = make_float2(acc[mt][nt][2], acc[mt][nt][3]);
        }
    }
#undef LOAD_STAGE
}

// ---------------- plain epilogue (vectorized) ----------------
__global__ void epilogue_kernel(const float* __restrict__ P, const float* __restrict__ bias,
                                const float* __restrict__ res, float* __restrict__ out,
                                float* __restrict__ out2, int out2_lim,
                                __nv_bfloat16* __restrict__ tout,
                                int M, int N, int kslices, int gelu)
{
    int idx = (blockIdx.x * 256 + threadIdx.x) * 4;
    if (idx >= M * N) return;
    int n = idx % N, m = idx / N;
    size_t MN = (size_t)M * N;
    float4 v = make_float4(0.f,0.f,0.f,0.f);
    for (int s = 0; s < kslices; s++) {
        float4 p = *(const float4*)(P + (size_t)s * MN + idx);
        v.x += p.x; v.y += p.y; v.z += p.z; v.w += p.w;
    }
    float4 b4 = *(const float4*)(bias + n);
    v.x += b4.x; v.y += b4.y; v.z += b4.z; v.w += b4.w;
    if (gelu) { v.x = gelu_f(v.x); v.y = gelu_f(v.y); v.z = gelu_f(v.z); v.w = gelu_f(v.w); }
    if (res) {
        float4 r4 = *(const float4*)(res + idx);
        v.x += r4.x; v.y += r4.y; v.z += r4.z; v.w += r4.w;
    }
    if (out)  *(float4*)(out + idx) = v;
    if (out2 && idx + 4 <= out2_lim) *(float4*)(out2 + idx) = v;
    if (tout) whl4(tout, (size_t)m * 2 * N, N, n, v);
}

// ---------------- fused epilogue + layernorm (N=1024; one block per row) ----------------
__global__ void epilogue_ln_kernel(const float* __restrict__ P, const float* __restrict__ bias,
                                   const float* __restrict__ res,
                                   const float* __restrict__ g, const float* __restrict__ be,
                                   float* __restrict__ epi_out, float* __restrict__ ln_out,
                                   __nv_bfloat16* __restrict__ tout,
                                   int M, int kslices)
{
    int m = blockIdx.x, t = threadIdx.x;      // 256 threads, 4 cols each
    __shared__ float red[256];
    int col = t * 4;
    size_t MN = (size_t)M * HH;
    const float* Pm = P + (size_t)m * HH + col;
    float4 v = make_float4(0.f,0.f,0.f,0.f);
    for (int s = 0; s < kslices; s++) {
        float4 p = *(const float4*)(Pm + (size_t)s * MN);
        v.x += p.x; v.y += p.y; v.z += p.z; v.w += p.w;
    }
    float4 b4 = *(const float4*)(bias + col);
    v.x += b4.x; v.y += b4.y; v.z += b4.z; v.w += b4.w;
    if (res) {
        float4 r4 = *(const float4*)(res + (size_t)m * HH + col);
        v.x += r4.x; v.y += r4.y; v.z += r4.z; v.w += r4.w;
    }
    if (epi_out) *(float4*)(epi_out + (size_t)m * HH + col) = v;

    red[t] = v.x + v.y + v.z + v.w; __syncthreads();
    for (int o = 128; o > 0; o >>= 1) { if (t < o) red[t] += red[t+o]; __syncthreads(); }
    float mean = red[0] * (1.f / HH);
    __syncthreads();
    float dx = v.x - mean, dy = v.y - mean, dz = v.z - mean, dw = v.w - mean;
    red[t] = dx*dx + dy*dy + dz*dz + dw*dw; __syncthreads();
    for (int o = 128; o > 0; o >>= 1) { if (t < o) red[t] += red[t+o]; __syncthreads(); }
    float inv = rsqrtf(red[0] * (1.f / HH) + 1e-5f);

    float4 g4 = *(const float4*)(g + col);
    float4 e4 = *(const float4*)(be + col);
    float4 o4;
    o4.x = dx * inv * g4.x + e4.x;
    o4.y = dy * inv * g4.y + e4.y;
    o4.z = dz * inv * g4.z + e4.z;
    o4.w = dw * inv * g4.w + e4.w;
    if (ln_out) *(float4*)(ln_out + (size_t)m * HH + col) = o4;
    whl4(tout, (size_t)m * 2048, 1024, col, o4);
}

// ---------------- fused gelu-epilogue + salience logits ----------------
__global__ void epilogue_logits_kernel(const float* __restrict__ P, const float* __restrict__ bias,
                                       const float* __restrict__ w2, const float* __restrict__ b2,
                                       int M, int kslices)
{
    int m = blockIdx.x, t = threadIdx.x;  // 256
    __shared__ float red[256];
    int col = t * 4;
    size_t MN = (size_t)M * HH;
    const float* Pm = P + (size_t)m * HH + col;
    float4 v = make_float4(0.f,0.f,0.f,0.f);
    for (int s = 0; s < kslices; s++) {
        float4 p = *(const float4*)(Pm + (size_t)s * MN);
        v.x += p.x; v.y += p.y; v.z += p.z; v.w += p.w;
    }
    float4 b4 = *(const float4*)(bias + col);
    v.x = gelu_f(v.x + b4.x); v.y = gelu_f(v.y + b4.y);
    v.z = gelu_f(v.z + b4.z); v.w = gelu_f(v.w + b4.w);
    float4 w = *(const float4*)(w2 + col);
    red[t] = v.x*w.x + v.y*w.y + v.z*w.z + v.w*w.w; __syncthreads();
    for (int o = 128; o > 0; o >>= 1) { if (t < o) red[t] += red[t+o]; __syncthreads(); }
    if (t == 0) g_logits[m] = red[0] + b2[0];
}

// ---------------- small attention: one (b, head) per block; bf16 hi|lo output ----------------
__global__ void attn_kernel(const float* __restrict__ qb, const float* __restrict__ kb,
                            const float* __restrict__ vb, __nv_bfloat16* __restrict__ tout,
                            int NQ, int NK,
                            int qRowStr, long long qBatStr,
                            int kRowStr, long long kBatStr,
                            int vRowStr, long long vBatStr)
{
    int b = blockIdx.x, hd = blockIdx.y;
    const float* q = qb + b * qBatStr + hd * DHD;
    const float* k = kb + b * kBatStr + hd * DHD;
    const float* v = vb + b * vBatStr + hd * DHD;
    __shared__ float qs[16][DHD+1], ks[16][DHD+1], vs[16][DHD+1];
    __shared__ float pr[16][17];
    int t = threadIdx.x;  // 128
    for (int i = 0; i < NQ; i++) qs[i][t] = q[(size_t)i * qRowStr + t];
    for (int i = 0; i < NK; i++) { ks[i][t] = k[(size_t)i * kRowStr + t]; vs[i][t] = v[(size_t)i * vRowStr + t]; }
    __syncthreads();
    const float scale = 0.08838834764831843f;   // 1/sqrt(128)
    for (int p = t; p < NQ * NK; p += 128) {
        int qi = p / NK, ki = p - qi * NK;
        float acc = 0.f;
#pragma unroll 4
        for (int d = 0; d < DHD; d++) acc = fmaf(qs[qi][d], ks[ki][d], acc);
        pr[qi][ki] = acc * scale;
    }
    __syncthreads();
    if (t < NQ) {
        float mx = -1e30f;
        for (int kk = 0; kk < NK; kk++) mx = fmaxf(mx, pr[t][kk]);
        float sm = 0.f;
        for (int kk = 0; kk < NK; kk++) { float e = expf(pr[t][kk] - mx); pr[t][kk] = e; sm += e; }
        float inv = 1.f / sm;
        for (int kk = 0; kk < NK; kk++) pr[t][kk] *= inv;
    }
    __syncthreads();
    for (int j = t; j < NQ * DHD; j += 128) {
        int qi = j >> 7, d = j & 127;
        float acc = 0.f;
        for (int kk = 0; kk < NK; kk++) acc = fmaf(pr[qi][kk], vs[kk][d], acc);
        whl(tout, (size_t)(b * NQ + qi) * 2048, 1024, hd * DHD + d, acc);
    }
}

// ---------------- salience softmax + entropy + weighted segments (bf16 out) ----------------
__global__ void salience_kernel() {
    int b = blockIdx.x, t = threadIdx.x;  // 256
    __shared__ float sal_s[NS];
    if (b == 0 && t == 0) g_red_cnt = 0;    // reset for fused red+finalize
    if (t == 0) {
        float mx = -1e30f;
        for (int s = 0; s < NS; s++) mx = fmaxf(mx, g_logits[b*NS + s]);
        float sm = 0.f;
        for (int s = 0; s < NS; s++) { float e = expf(g_logits[b*NS + s] - mx); sal_s[s] = e; sm += e; }
        float inv = 1.f / sm, ent = 0.f;
        for (int s = 0; s < NS; s++) {
            sal_s[s] *= inv;
            g_sal[b*NS + s] = sal_s[s];
            ent -= sal_s[s] * logf(sal_s[s] + 1e-8f);
        }
        g_entpart[b] = ent;
    }
    __syncthreads();
    for (int i = t; i < NS * HH; i += 256) {
        int s = i >> 10, k = i & 1023;
        float v = g_seg1[(size_t)b * NS * HH + i] * sal_s[s];
        whl(g_bf_wseg, (size_t)(b * NS + s) * 2048, 1024, k, v);
    }
}

// ---------------- redundancy + fused finalize (last block) ----------------
__global__ void red_kernel(float* __restrict__ out, int out_size) {
    int b = blockIdx.x, t = threadIdx.x;  // 128
    __shared__ float ps[NP][HH+1];
    __shared__ float nrm[NP];
    __shared__ float parr[16];
    __shared__ int lastflag;
    for (int i = t; i < NP * HH; i += 128) ps[i >> 10][i & 1023] = g_plan[(size_t)b * NP * HH + i];
    __syncthreads();
    if (t < NP) {
        float s = 0.f;
        for (int d = 0; d < HH; d++) s = fmaf(ps[t][d], ps[t][d], s);
        nrm[t] = fmaxf(sqrtf(s), 1e-12f);
    }
    __syncthreads();
    if (t < 15) {
        int i = 0, j = 0, c = t;
        for (i = 0; i < NP; i++) { int row = NP - 1 - i; if (c < row) { j = i + 1 + c; break; } c -= row; }
        float s = 0.f;
        for (int d = 0; d < HH; d++) s = fmaf(ps[i][d], ps[j][d], s);
        float sim = s / (nrm[i] * nrm[j]);
        parr[t] = 2.f * sim * sim;
    }
    __syncthreads();
    if (t == 0) {
        float s = 0.f;
        for (int p = 0; p < 15; p++) s += parr[p];
        g_redpart[b] = s;
        __threadfence();
        int old = atomicAdd(&g_red_cnt, 1);
        lastflag = (old == NB - 1);
    }
    __syncthreads();
    if (lastflag) {
        for (int i = t; i < NB*NS; i += 128)
            if (PLAN_ELEMS + i < out_size) out[PLAN_ELEMS + i] = g_sal[i];
        if (t == 0) {
            if (PLAN_ELEMS + 256 < out_size) {
                float e = 0.f;
                for (int bb = 0; bb < NB; bb++) e += g_entpart[bb];
                out[PLAN_ELEMS + 256] = e / (float)NB;
            }
            if (PLAN_ELEMS + 257 < out_size) {
                float r = 0.f;
                for (int bb = 0; bb < NB; bb++) r += g_redpart[bb];
                out[PLAN_ELEMS + 257] = r / (float)(NB * NP * (NP - 1));
            }
        }
    }
}

// ---------------- host helpers ----------------
// ks: (K/ks) % 32 == 0; ks*M*N <= 8M floats
static void gemm(const __nv_bfloat16* A, const __nv_bfloat16* W, int M, int N, int K, int ks,
                 float* part)
{
    dim3 grid((M + 127) / 128, N / 128, ks);
    gemm_bf16_kernel<<<grid, 256, 2*STGB>>>(A, W, part, M, N, K, ks);
}
static void epi(const float* P, const float* bias, const float* res, float* out,
                float* out2, int out2_lim, __nv_bfloat16* tout, int M, int N, int ks, int gelu)
{
    int blocks = (M * N + 1023) / 1024;
    epilogue_kernel<<<blocks, 256>>>(P, bias, res, out, out2, out2_lim, tout, M, N, ks, gelu);
}

extern "C" void kernel_launch(void* const* d_in, const int* in_sizes, int n_in,
                              void* d_out, int out_size)
{
    const float* ts       = (const float*)d_in[0];
    const int*   mask     = (const int*)  d_in[1];
    const float* sa_in_w  = (const float*)d_in[2];
    const float* sa_in_b  = (const float*)d_in[3];
    const float* sa_out_w = (const float*)d_in[4];
    const float* sa_out_b = (const float*)d_in[5];
    const float* ln_g     = (const float*)d_in[6];
    const float* ln_b     = (const float*)d_in[7];
    const float* sal_w1   = (const float*)d_in[8];
    const float* sal_b1   = (const float*)d_in[9];
    const float* sal_w2   = (const float*)d_in[10];
    const float* sal_b2   = (const float*)d_in[11];
    const float* plan_q   = (const float*)d_in[12];
    const float* qa_in_w  = (const float*)d_in[13];
    const float* qa_in_b  = (const float*)d_in[14];
    const float* qa_out_w = (const float*)d_in[15];
    const float* qa_out_b = (const float*)d_in[16];
    const float* r_in_w   = (const float*)d_in[17];
    const float* r_in_b   = (const float*)d_in[18];
    const float* r_out_w  = (const float*)d_in[19];
    const float* r_out_b  = (const float*)d_in[20];
    const float* r_ln1_g  = (const float*)d_in[21];
    const float* r_ln1_b  = (const float*)d_in[22];
    const float* r_ln2_g  = (const float*)d_in[23];
    const float* r_ln2_b  = (const float*)d_in[24];
    const float* r_w1     = (const float*)d_in[25];
    const float* r_b1     = (const float*)d_in[26];
    const float* r_w2     = (const float*)d_in[27];
    const float* r_b2     = (const float*)d_in[28];
    float* out = (float*)d_out;

    static int smem_set = 0;
    if (!smem_set) {
        cudaFuncSetAttribute(gemm_bf16_kernel,
                             cudaFuncAttributeMaxDynamicSharedMemorySize, 2*STGB);
        smem_set = 1;
    }

    float *p_part, *p_qkv, *p_seg1, *p_qh, *p_kv, *p_plan, *p_qkvr, *p_seg0;
    cudaGetSymbolAddress((void**)&p_part, g_part);
    cudaGetSymbolAddress((void**)&p_seg0, g_seg0);
    cudaGetSymbolAddress((void**)&p_qkv,  g_qkv);
    cudaGetSymbolAddress((void**)&p_seg1, g_seg1);
    cudaGetSymbolAddress((void**)&p_qh,   g_qh);
    cudaGetSymbolAddress((void**)&p_kv,   g_kv);
    cudaGetSymbolAddress((void**)&p_plan, g_plan);
    cudaGetSymbolAddress((void**)&p_qkvr, g_qkvr);

    __nv_bfloat16 *t_seg0, *t_o, *t_seg1, *t_wseg, *t_pq, *t_o2, *t_y, *t_o3, *t_ffn, *wbf;
    cudaGetSymbolAddress((void**)&t_seg0, g_bf_seg0);
    cudaGetSymbolAddress((void**)&t_o,    g_bf_o);
    cudaGetSymbolAddress((void**)&t_seg1, g_bf_seg1);
    cudaGetSymbolAddress((void**)&t_wseg, g_bf_wseg);
    cudaGetSymbolAddress((void**)&t_pq,   g_bf_pq);
    cudaGetSymbolAddress((void**)&t_o2,   g_bf_o2);
    cudaGetSymbolAddress((void**)&t_y,    g_bf_y);
    cudaGetSymbolAddress((void**)&t_o3,   g_bf_o3);
    cudaGetSymbolAddress((void**)&t_ffn,  g_bf_ffn);
    cudaGetSymbolAddress((void**)&wbf,    g_wbf);

    // 0) convert all weights (+plan_q) to bf16 hi|lo
    CvtTab tab;
    tab.src[0]=sa_in_w;  tab.dst[0]=wbf+WOFF_SAIN;  tab.n[0]=3145728; tab.logK[0]=10;
    tab.src[1]=sa_out_w; tab.dst[1]=wbf+WOFF_SAOUT; tab.n[1]=1048576; tab.logK[1]=10;
    tab.src[2]=sal_w1;   tab.dst[2]=wbf+WOFF_SAL1;  tab.n[2]=1048576; tab.logK[2]=10;
    tab.src[3]=qa_in_w;  tab.dst[3]=wbf+WOFF_QAIN;  tab.n[3]=3145728; tab.logK[3]=10;
    tab.src[4]=qa_out_w; tab.dst[4]=wbf+WOFF_QAOUT; tab.n[4]=1048576; tab.logK[4]=10;
    tab.src[5]=r_in_w;   tab.dst[5]=wbf+WOFF_RIN;   tab.n[5]=6291456; tab.logK[5]=10;
    tab.src[6]=r_out_w;  tab.dst[6]=wbf+WOFF_ROUT;  tab.n[6]=2097152; tab.logK[6]=10;
    tab.src[7]=r_w1;     tab.dst[7]=wbf+WOFF_RW1;   tab.n[7]=8388608; tab.logK[7]=10;
    tab.src[8]=r_w2;     tab.dst[8]=wbf+WOFF_RW2;   tab.n[8]=8388608; tab.logK[8]=12;
    tab.src[9]=plan_q;   tab.dst[9]=t_pq;           tab.n[9]=6144;    tab.logK[9]=10;
    convert_kernel<<<dim3(2048, 10), 256>>>(tab);

    // 1) lengths + bounds, fused segment pooling
    lengths_kernel<<<16, 256>>>(mask);
    segpool_kernel<<<NB*NS, 256>>>(ts);

    // 2) segment self-attention
    gemm(t_seg0, wbf+WOFF_SAIN, 256, 3*HH, HH, 8, p_part);
    epi(p_part, sa_in_b, nullptr, p_qkv, nullptr, 0, nullptr, 256, 3*HH, 8, 0);
    attn_kernel<<<dim3(NB, NHEAD), 128>>>(p_qkv, p_qkv + HH, p_qkv + 2*HH, t_o,
                                          16, 16,
                                          3*HH, (long long)NS*3*HH,
                                          3*HH, (long long)NS*3*HH,
                                          3*HH, (long long)NS*3*HH);
    gemm(t_o, wbf+WOFF_SAOUT, 256, HH, HH, 16, p_part);
    epilogue_ln_kernel<<<256, 256>>>(p_part, sa_out_b, p_seg0, ln_g, ln_b,
                                     nullptr, p_seg1, t_seg1, 256, 16);

    // 3) salience (gelu-epilogue + logits fused)
    gemm(t_seg1, wbf+WOFF_SAL1, 256, HH, HH, 16, p_part);
    epilogue_logits_kernel<<<256, 256>>>(p_part, sal_b1, sal_w2, sal_b2, 256, 16);
    salience_kernel<<<16, 256>>>();

    // 4) plan cross-attention (qh batch-independent)
    gemm(t_pq, wbf+WOFF_QAIN, NP, HH, HH, 32, p_part);
    epi(p_part, qa_in_b, nullptr, p_qh, nullptr, 0, nullptr, NP, HH, 32, 0);
    gemm(t_wseg, wbf+WOFF_QAIN + (size_t)HH*2*HH, 256, 2*HH, HH, 8, p_part);
    epi(p_part, qa_in_b + HH, nullptr, p_kv, nullptr, 0, nullptr, 256, 2*HH, 8, 0);
    attn_kernel<<<dim3(NB, NHEAD), 128>>>(p_qh, p_kv, p_kv + HH, t_o2,
                                          NP, 16,
                                          HH,   0LL,
                                          2*HH, (long long)NS*2*HH,
                                          2*HH, (long long)NS*2*HH);
    gemm(t_o2, wbf+WOFF_QAOUT, NB*NP, HH, HH, 16, p_part);
    epilogue_ln_kernel<<<NB*NP, 256>>>(p_part, qa_out_b, nullptr, r_ln1_g, r_ln1_b,
                                       p_plan, nullptr, t_y, NB*NP, 16);

    // 5) refinement transformer layers (norm_first)
    for (int l = 0; l < 2; l++) {
        gemm(t_y, wbf+WOFF_RIN + (size_t)l*6291456, NB*NP, 3*HH, HH, 8, p_part);
        epi(p_part, r_in_b + l*3*HH, nullptr, p_qkvr, nullptr, 0, nullptr, NB*NP, 3*HH, 8, 0);
        attn_kernel<<<dim3(NB, NHEAD), 128>>>(p_qkvr, p_qkvr + HH, p_qkvr + 2*HH, t_o3,
                                              NP, NP,
                                              3*HH, (long long)NP*3*HH,
                                              3*HH, (long long)NP*3*HH,
                                              3*HH, (long long)NP*3*HH);
        gemm(t_o3, wbf+WOFF_ROUT + (size_t)l*2097152, NB*NP, HH, HH, 16, p_part);
        epilogue_ln_kernel<<<NB*NP, 256>>>(p_part, r_out_b + l*HH, p_plan,
                                           r_ln2_g + l*HH, r_ln2_b + l*HH,
                                           p_plan, nullptr, t_y, NB*NP, 16);
        gemm(t_y, wbf+WOFF_RW1 + (size_t)l*8388608, NB*NP, 4*HH, HH, 8, p_part);
        epi(p_part, r_b1 + l*4*HH, nullptr, nullptr, nullptr, 0, t_ffn, NB*NP, 4*HH, 8, 1);
        gemm(t_ffn, wbf+WOFF_RW2 + (size_t)l*8388608, NB*NP, HH, 4*HH, 32, p_part);
        if (l == 0) {
            epilogue_ln_kernel<<<NB*NP, 256>>>(p_part, r_b2, p_plan,
                                               r_ln1_g + HH, r_ln1_b + HH,
                                               p_plan, nullptr, t_y, NB*NP, 32);
        } else {
            int lim = out_size < PLAN_ELEMS ? out_size : PLAN_ELEMS;
            epi(p_part, r_b2 + HH, p_plan, p_plan, out, lim, nullptr, NB*NP, HH, 32, 0);
        }
    }

    // 6) redundancy + finalize (fused)
    red_kernel<<<16, 128>>>(out, out_size);
}

// round 13
// speedup vs baseline: 1.5742x; 1.0526x over previous
#include <cuda_runtime.h>
#include <cuda_bf16.h>
#include <math.h>

// ---------------- problem constants ----------------
#define NB 16      // batch
#define NT 4096    // tokens
#define HH 1024    // hidden
#define NS 16      // segments
#define NP 6       // plan slots
#define NHEAD 8
#define DHD 128    // head dim
#define PLAN_ELEMS (NB*NP*HH)   // 98304

// ---------------- device scratch (static, no allocs) ----------------
__device__ int   g_bounds[NB*(NS+1)];
__device__ float g_seg0[NB*NS*HH];
__device__ float g_qkv[NB*NS*3*HH];
__device__ float g_seg1[NB*NS*HH];
__device__ float g_logits[NB*NS];
__device__ float g_sal[NB*NS];
__device__ float g_qh[NP*HH];
__device__ float g_kv[NB*NS*2*HH];
__device__ float g_plan[NB*NP*HH];
__device__ float g_qkvr[NB*NP*3*HH];
__device__ float g_part[8*1024*1024];          // split-K partials (32MB)
__device__ float g_entpart[NB];
__device__ float g_redpart[NB];
__device__ int   g_red_cnt;

// bf16 [hi(K)|lo(K)] operand buffers
__device__ __nv_bfloat16 g_bf_seg0[256*2048];
__device__ __nv_bfloat16 g_bf_o   [256*2048];
__device__ __nv_bfloat16 g_bf_seg1[256*2048];
__device__ __nv_bfloat16 g_bf_wseg[256*2048];
__device__ __nv_bfloat16 g_bf_pq  [NP*2048];
__device__ __nv_bfloat16 g_bf_o2  [96*2048];
__device__ __nv_bfloat16 g_bf_y   [96*2048];
__device__ __nv_bfloat16 g_bf_o3  [96*2048];
__device__ __nv_bfloat16 g_bf_ffn [96*8192];
__device__ __nv_bfloat16 g_wbf[69206016];      // all weights hi|lo (138MB)

// weight offsets into g_wbf (bf16 elems)
#define WOFF_SAIN   0LL
#define WOFF_SAOUT  6291456LL
#define WOFF_SAL1   8388608LL
#define WOFF_QAIN   10485760LL
#define WOFF_QAOUT  16777216LL
#define WOFF_RIN    18874368LL
#define WOFF_ROUT   31457280LL
#define WOFF_RW1    35651584LL
#define WOFF_RW2    52428800LL

// ---------------- helpers ----------------
__device__ __forceinline__ unsigned smem_u32(const void* p) {
    unsigned a;
    asm("{ .reg .u64 t; cvta.to.shared.u64 t, %1; cvt.u32.u64 %0, t; }" : "=r"(a) : "l"(p));
    return a;
}
__device__ __forceinline__ unsigned pack_pair(float f0, float f1, bool lo) {
    if (lo) {
        f0 = f0 - __bfloat162float(__float2bfloat16(f0));
        f1 = f1 - __bfloat162float(__float2bfloat16(f1));
    }
    __nv_bfloat162 p = __floats2bfloat162_rn(f0, f1);
    return *reinterpret_cast<unsigned*>(&p);
}
__device__ __forceinline__ void cp16(unsigned dst, const void* src, int sz) {
    asm volatile("cp.async.ca.shared.global [%0], [%1], 16, %2;"
                 :: "r"(dst), "l"(src), "r"(sz));
}
__device__ __forceinline__ void whl(__nv_bfloat16* t, size_t rowbase, int K, int k, float v) {
    __nv_bfloat16 h = __float2bfloat16(v);
    __nv_bfloat16 l = __float2bfloat16(v - __bfloat162float(h));
    t[rowbase + k] = h;
    t[rowbase + K + k] = l;
}
__device__ __forceinline__ void whl4(__nv_bfloat16* t, size_t rowbase, int N, int col, float4 v) {
    unsigned h0 = pack_pair(v.x, v.y, false), h1 = pack_pair(v.z, v.w, false);
    unsigned l0 = pack_pair(v.x, v.y, true),  l1 = pack_pair(v.z, v.w, true);
    __nv_bfloat16* tr = t + rowbase + col;
    *(uint2*)tr       = make_uint2(h0, h1);
    *(uint2*)(tr + N) = make_uint2(l0, l1);
}
__device__ __forceinline__ float gelu_f(float v) {
    return 0.5f * v * (1.f + erff(v * 0.70710678118654752f));
}

// ---------------- weight conversion (all tensors, one launch) ----------------
struct CvtTab {
    const float* src[10];
    __nv_bfloat16* dst[10];
    int n[10];
    int logK[10];
};
__global__ void convert_kernel(CvtTab tab) {
    int tsel = blockIdx.y;
    const float* s = tab.src[tsel];
    __nv_bfloat16* d = tab.dst[tsel];
    long long n = tab.n[tsel];
    int logK = tab.logK[tsel];
    int K = 1 << logK;
    long long stride = (long long)gridDim.x * blockDim.x * 4;
    for (long long idx = ((long long)blockIdx.x * blockDim.x + threadIdx.x) * 4;
         idx < n; idx += stride) {
        float4 v = *(const float4*)(s + idx);
        int k = (int)(idx & (K - 1));
        long long row = idx >> logK;
        __nv_bfloat16* dr = d + row * (2LL * K) + k;
        unsigned h0 = pack_pair(v.x, v.y, false), h1 = pack_pair(v.z, v.w, false);
        unsigned l0 = pack_pair(v.x, v.y, true),  l1 = pack_pair(v.z, v.w, true);
        *(uint2*)dr       = make_uint2(h0, h1);
        *(uint2*)(dr + K) = make_uint2(l0, l1);
    }
}

// ---------------- lengths + segment bounds ----------------
__global__ void lengths_kernel(const int* __restrict__ mask) {
    int b = blockIdx.x;
    __shared__ int red[256];
    int t = threadIdx.x;
    int s = 0;
    for (int i = t; i < NT; i += 256) s += mask[b*NT + i];
    red[t] = s; __syncthreads();
    for (int o = 128; o > 0; o >>= 1) { if (t < o) red[t] += red[t+o]; __syncthreads(); }
    if (t == 0) {
        int L = red[0];
        for (int k = 0; k <= NS; k++) g_bounds[b*(NS+1) + k] = (k * L) / NS;
    }
}

// ---------------- fused segment pooling (single kernel, 4-row unrolled) ----------------
__global__ void segpool_kernel(const float* __restrict__ ts) {
    int seg = blockIdx.x;                 // 0..255
    int b = seg >> 4, s = seg & 15;
    int lo = g_bounds[b*(NS+1) + s], hi = g_bounds[b*(NS+1) + s + 1];
    int cnt = hi - lo;
    int t = threadIdx.x;                  // 256 threads, 4 cols each
    const float* base = ts + (size_t)b * NT * HH + t * 4;
    float4 a0 = make_float4(0.f,0.f,0.f,0.f), a1 = a0, a2 = a0, a3 = a0;
    int r = lo;
    for (; r + 4 <= hi; r += 4) {
        float4 v0 = *(const float4*)(base + (size_t)(r+0) * HH);
        float4 v1 = *(const float4*)(base + (size_t)(r+1) * HH);
        float4 v2 = *(const float4*)(base + (size_t)(r+2) * HH);
        float4 v3 = *(const float4*)(base + (size_t)(r+3) * HH);
        a0.x += v0.x; a0.y += v0.y; a0.z += v0.z; a0.w += v0.w;
        a1.x += v1.x; a1.y += v1.y; a1.z += v1.z; a1.w += v1.w;
        a2.x += v2.x; a2.y += v2.y; a2.z += v2.z; a2.w += v2.w;
        a3.x += v3.x; a3.y += v3.y; a3.z += v3.z; a3.w += v3.w;
    }
    for (; r < hi; r++) {
        float4 v = *(const float4*)(base + (size_t)r * HH);
        a0.x += v.x; a0.y += v.y; a0.z += v.z; a0.w += v.w;
    }
    float inv = 1.f / fmaxf((float)cnt, 1.f);
    float4 v;
    v.x = (a0.x + a1.x + a2.x + a3.x) * inv;
    v.y = (a0.y + a1.y + a2.y + a3.y) * inv;
    v.z = (a0.z + a1.z + a2.z + a3.z) * inv;
    v.w = (a0.w + a1.w + a2.w + a3.w) * inv;
    *(float4*)&g_seg0[(size_t)seg * HH + t*4] = v;
    whl4(g_bf_seg0, (size_t)seg * 2048, 1024, t*4, v);
}

// ---------------- bf16 split-K GEMM (compensated, fragment-reuse, cp.async 2-stage) ----------------
// D = A_hi*W_hi + A_lo*W_hi + A_hi*W_lo.  A,W stored [rows, 2K] = [hi(K)|lo(K)].
// 128x128 tile, BK=32, 256 thr, 8 warps 64x32. Per k16 step: load af_hi/af_lo/bf_hi/bf_lo
// fragments ONCE, run the 3 phase mma groups from registers.
#define SA 40   // padded smem row stride (bf16) => 80B
#define MATB (128*SA*2)        // 10240 bytes per tile
#define STGB (4*MATB)          // 40960 bytes per stage

__global__ void __launch_bounds__(256) gemm_bf16_kernel(
    const __nv_bfloat16* __restrict__ A, const __nv_bfloat16* __restrict__ W,
    float* __restrict__ P, int M, int N, int K, int kslices)
{
    extern __shared__ __align__(16) unsigned char smem[];
    int tid = threadIdx.x, wid = tid >> 5, lane = tid & 31;
    int m0 = blockIdx.x * 128, n0 = blockIdx.y * 128;
    int K2 = 2 * K;
    int Kper = K / kslices, kstart = blockIdx.z * Kper, nch = Kper >> 5;
    int wm = (wid & 1) * 64, wn = (wid >> 1) * 32;
    unsigned sm = smem_u32(smem);

    int r0 = tid >> 2, s0 = tid & 3;
    int f1 = tid + 256, r1 = f1 >> 2, s1 = f1 & 3;
    int szA0 = (m0 + r0 < M) ? 16 : 0, szA1 = (m0 + r1 < M) ? 16 : 0;
    const __nv_bfloat16* a0 = A + (size_t)(szA0 ? (m0 + r0) : 0) * K2 + s0 * 8;
    const __nv_bfloat16* a1 = A + (size_t)(szA1 ? (m0 + r1) : 0) * K2 + s1 * 8;
    const __nv_bfloat16* w0 = W + (size_t)(n0 + r0) * K2 + s0 * 8;
    const __nv_bfloat16* w1 = W + (size_t)(n0 + r1) * K2 + s1 * 8;
    unsigned o0 = (unsigned)(r0*SA + s0*8)*2, o1 = (unsigned)(r1*SA + s1*8)*2;

#define LOAD_STAGE(c, st) { \
    int kb = kstart + (c)*32; \
    unsigned so = sm + (unsigned)(st) * STGB; \
    cp16(so + o0,          a0 + kb,     szA0); cp16(so + o1,          a1 + kb,     szA1); \
    cp16(so + MATB + o0,   a0 + K + kb, szA0); cp16(so + MATB + o1,   a1 + K + kb, szA1); \
    cp16(so + 2*MATB + o0, w0 + kb,     16);   cp16(so + 2*MATB + o1, w1 + kb,     16); \
    cp16(so + 3*MATB + o0, w0 + K + kb, 16);   cp16(so + 3*MATB + o1, w1 + K + kb, 16); \
    asm volatile("cp.async.commit_group;"); }

    float acc[4][4][4];
#pragma unroll
    for (int a = 0; a < 4; a++)
#pragma unroll
        for (int b = 0; b < 4; b++)
#pragma unroll
            for (int c = 0; c < 4; c++) acc[a][b][c] = 0.f;

    LOAD_STAGE(0, 0);

    int g = lane >> 3, r = lane & 7;
    for (int c = 0; c < nch; c++) {
        if (c + 1 < nch) {
            LOAD_STAGE(c + 1, (c + 1) & 1);
            asm volatile("cp.async.wait_group 1;");
        } else {
            asm volatile("cp.async.wait_group 0;");
        }
        __syncthreads();
        unsigned st = sm + (unsigned)(c & 1) * STGB;
#pragma unroll
        for (int ks = 0; ks < 2; ks++) {
            unsigned afh[4][4], afl[4][4], bfh[4][2], bfl[4][2];
#pragma unroll
            for (int mt = 0; mt < 4; mt++) {
                unsigned roff = (unsigned)(((wm + mt*16 + (g & 1)*8 + r) * SA
                                   + ks*16 + (g >> 1)*8) * 2);
                asm volatile("ldmatrix.sync.aligned.m8n8.x4.shared.b16 {%0,%1,%2,%3}, [%4];"
                    : "=r"(afh[mt][0]), "=r"(afh[mt][1]), "=r"(afh[mt][2]), "=r"(afh[mt][3])
                    : "r"(st + roff));
                asm volatile("ldmatrix.sync.aligned.m8n8.x4.shared.b16 {%0,%1,%2,%3}, [%4];"
                    : "=r"(afl[mt][0]), "=r"(afl[mt][1]), "=r"(afl[mt][2]), "=r"(afl[mt][3])
                    : "r"(st + MATB + roff));
            }
#pragma unroll
            for (int np = 0; np < 2; np++) {
                unsigned roff = (unsigned)(((wn + np*16 + (g >> 1)*8 + r) * SA
                                   + ks*16 + (g & 1)*8) * 2);
                unsigned t0,t1,t2,t3;
                asm volatile("ldmatrix.sync.aligned.m8n8.x4.shared.b16 {%0,%1,%2,%3}, [%4];"
                    : "=r"(t0), "=r"(t1), "=r"(t2), "=r"(t3) : "r"(st + 2u*MATB + roff));
                bfh[2*np][0] = t0; bfh[2*np][1] = t1;
                bfh[2*np+1][0] = t2; bfh[2*np+1][1] = t3;
                asm volatile("ldmatrix.sync.aligned.m8n8.x4.shared.b16 {%0,%1,%2,%3}, [%4];"
                    : "=r"(t0), "=r"(t1), "=r"(t2), "=r"(t3) : "r"(st + 3u*MATB + roff));
                bfl[2*np][0] = t0; bfl[2*np][1] = t1;
                bfl[2*np+1][0] = t2; bfl[2*np+1][1] = t3;
            }
#define MMA16(AF, BF) \
_Pragma("unroll") \
            for (int mt = 0; mt < 4; mt++) \
_Pragma("unroll") \
                for (int nt = 0; nt < 4; nt++) { \
                    asm volatile( \
                        "mma.sync.aligned.m16n8k16.row.col.f32.bf16.bf16.f32 " \
                        "{%0,%1,%2,%3}, {%4,%5,%6,%7}, {%8,%9}, {%0,%1,%2,%3};" \
                        : "+f"(acc[mt][nt][0]), "+f"(acc[mt][nt][1]), \
                          "+f"(acc[mt][nt][2]), "+f"(acc[mt][nt][3]) \
                        : "r"(AF[mt][0]), "r"(AF[mt][1]), "r"(AF[mt][2]), "r"(AF[mt][3]), \
                          "r"(BF[nt][0]), "r"(BF[nt][1])); \
                }
            MMA16(afh, bfh)
            MMA16(afl, bfh)
            MMA16(afh, bfl)
#undef MMA16
        }
        __syncthreads();
    }

    size_t base = (size_t)blockIdx.z * M * N;
#pragma unroll
    for (int mt = 0; mt < 4; mt++) {
        int m = m0 + wm + mt*16 + (lane >> 2);
#pragma unroll
        for (int nt = 0; nt < 4; nt++) {
            int n = n0 + wn + nt*8 + (lane & 3)*2;
            if (m < M)
                *(float2*)(P + base + (size_t)m * N + n)
                    = make_float2(acc[mt][nt][0], acc[mt][nt][1]);
            if (m + 8 < M)
                *(float2*)(P + base + (size_t)(m+8) * N + n)
                    = make_float2(acc[mt][nt][2], acc[mt][nt][3]);
        }
    }
#undef LOAD_STAGE
}

// ---------------- plain epilogue (vectorized) ----------------
__global__ void epilogue_kernel(const float* __restrict__ P, const float* __restrict__ bias,
                                const float* __restrict__ res, float* __restrict__ out,
                                float* __restrict__ out2, int out2_lim,
                                __nv_bfloat16* __restrict__ tout,
                                int M, int N, int kslices, int gelu)
{
    int idx = (blockIdx.x * 256 + threadIdx.x) * 4;
    if (idx >= M * N) return;
    int n = idx % N, m = idx / N;
    size_t MN = (size_t)M * N;
    float4 v = make_float4(0.f,0.f,0.f,0.f);
    for (int s = 0; s < kslices; s++) {
        float4 p = *(const float4*)(P + (size_t)s * MN + idx);
        v.x += p.x; v.y += p.y; v.z += p.z; v.w += p.w;
    }
    float4 b4 = *(const float4*)(bias + n);
    v.x += b4.x; v.y += b4.y; v.z += b4.z; v.w += b4.w;
    if (gelu) { v.x = gelu_f(v.x); v.y = gelu_f(v.y); v.z = gelu_f(v.z); v.w = gelu_f(v.w); }
    if (res) {
        float4 r4 = *(const float4*)(res + idx);
        v.x += r4.x; v.y += r4.y; v.z += r4.z; v.w += r4.w;
    }
    if (out)  *(float4*)(out + idx) = v;
    if (out2 && idx + 4 <= out2_lim) *(float4*)(out2 + idx) = v;
    if (tout) whl4(tout, (size_t)m * 2 * N, N, n, v);
}

// ---------------- fused epilogue + layernorm (N=1024; one block per row) ----------------
__global__ void epilogue_ln_kernel(const float* __restrict__ P, const float* __restrict__ bias,
                                   const float* __restrict__ res,
                                   const float* __restrict__ g, const float* __restrict__ be,
                                   float* __restrict__ epi_out, float* __restrict__ ln_out,
                                   __nv_bfloat16* __restrict__ tout,
                                   int M, int kslices)
{
    int m = blockIdx.x, t = threadIdx.x;      // 256 threads, 4 cols each
    __shared__ float red[256];
    int col = t * 4;
    size_t MN = (size_t)M * HH;
    const float* Pm = P + (size_t)m * HH + col;
    float4 v = make_float4(0.f,0.f,0.f,0.f);
    for (int s = 0; s < kslices; s++) {
        float4 p = *(const float4*)(Pm + (size_t)s * MN);
        v.x += p.x; v.y += p.y; v.z += p.z; v.w += p.w;
    }
    float4 b4 = *(const float4*)(bias + col);
    v.x += b4.x; v.y += b4.y; v.z += b4.z; v.w += b4.w;
    if (res) {
        float4 r4 = *(const float4*)(res + (size_t)m * HH + col);
        v.x += r4.x; v.y += r4.y; v.z += r4.z; v.w += r4.w;
    }
    if (epi_out) *(float4*)(epi_out + (size_t)m * HH + col) = v;

    red[t] = v.x + v.y + v.z + v.w; __syncthreads();
    for (int o = 128; o > 0; o >>= 1) { if (t < o) red[t] += red[t+o]; __syncthreads(); }
    float mean = red[0] * (1.f / HH);
    __syncthreads();
    float dx = v.x - mean, dy = v.y - mean, dz = v.z - mean, dw = v.w - mean;
    red[t] = dx*dx + dy*dy + dz*dz + dw*dw; __syncthreads();
    for (int o = 128; o > 0; o >>= 1) { if (t < o) red[t] += red[t+o]; __syncthreads(); }
    float inv = rsqrtf(red[0] * (1.f / HH) + 1e-5f);

    float4 g4 = *(const float4*)(g + col);
    float4 e4 = *(const float4*)(be + col);
    float4 o4;
    o4.x = dx * inv * g4.x + e4.x;
    o4.y = dy * inv * g4.y + e4.y;
    o4.z = dz * inv * g4.z + e4.z;
    o4.w = dw * inv * g4.w + e4.w;
    if (ln_out) *(float4*)(ln_out + (size_t)m * HH + col) = o4;
    whl4(tout, (size_t)m * 2048, 1024, col, o4);
}

// ---------------- fused gelu-epilogue + salience logits ----------------
__global__ void epilogue_logits_kernel(const float* __restrict__ P, const float* __restrict__ bias,
                                       const float* __restrict__ w2, const float* __restrict__ b2,
                                       int M, int kslices)
{
    int m = blockIdx.x, t = threadIdx.x;  // 256
    __shared__ float red[256];
    int col = t * 4;
    size_t MN = (size_t)M * HH;
    const float* Pm = P + (size_t)m * HH + col;
    float4 v = make_float4(0.f,0.f,0.f,0.f);
    for (int s = 0; s < kslices; s++) {
        float4 p = *(const float4*)(Pm + (size_t)s * MN);
        v.x += p.x; v.y += p.y; v.z += p.z; v.w += p.w;
    }
    float4 b4 = *(const float4*)(bias + col);
    v.x = gelu_f(v.x + b4.x); v.y = gelu_f(v.y + b4.y);
    v.z = gelu_f(v.z + b4.z); v.w = gelu_f(v.w + b4.w);
    float4 w = *(const float4*)(w2 + col);
    red[t] = v.x*w.x + v.y*w.y + v.z*w.z + v.w*w.w; __syncthreads();
    for (int o = 128; o > 0; o >>= 1) { if (t < o) red[t] += red[t+o]; __syncthreads(); }
    if (t == 0) g_logits[m] = red[0] + b2[0];
}

// ---------------- small attention: one (b, head) per block; bf16 hi|lo output ----------------
__global__ void attn_kernel(const float* __restrict__ qb, const float* __restrict__ kb,
                            const float* __restrict__ vb, __nv_bfloat16* __restrict__ tout,
                            int NQ, int NK,
                            int qRowStr, long long qBatStr,
                            int kRowStr, long long kBatStr,
                            int vRowStr, long long vBatStr)
{
    int b = blockIdx.x, hd = blockIdx.y;
    const float* q = qb + b * qBatStr + hd * DHD;
    const float* k = kb + b * kBatStr + hd * DHD;
    const float* v = vb + b * vBatStr + hd * DHD;
    __shared__ float qs[16][DHD+1], ks[16][DHD+1], vs[16][DHD+1];
    __shared__ float pr[16][17];
    int t = threadIdx.x;  // 128
    for (int i = 0; i < NQ; i++) qs[i][t] = q[(size_t)i * qRowStr + t];
    for (int i = 0; i < NK; i++) { ks[i][t] = k[(size_t)i * kRowStr + t]; vs[i][t] = v[(size_t)i * vRowStr + t]; }
    __syncthreads();
    const float scale = 0.08838834764831843f;   // 1/sqrt(128)
    for (int p = t; p < NQ * NK; p += 128) {
        int qi = p / NK, ki = p - qi * NK;
        float acc = 0.f;
#pragma unroll 4
        for (int d = 0; d < DHD; d++) acc = fmaf(qs[qi][d], ks[ki][d], acc);
        pr[qi][ki] = acc * scale;
    }
    __syncthreads();
    if (t < NQ) {
        float mx = -1e30f;
        for (int kk = 0; kk < NK; kk++) mx = fmaxf(mx, pr[t][kk]);
        float sm = 0.f;
        for (int kk = 0; kk < NK; kk++) { float e = expf(pr[t][kk] - mx); pr[t][kk] = e; sm += e; }
        float inv = 1.f / sm;
        for (int kk = 0; kk < NK; kk++) pr[t][kk] *= inv;
    }
    __syncthreads();
    for (int j = t; j < NQ * DHD; j += 128) {
        int qi = j >> 7, d = j & 127;
        float acc = 0.f;
        for (int kk = 0; kk < NK; kk++) acc = fmaf(pr[qi][kk], vs[kk][d], acc);
        whl(tout, (size_t)(b * NQ + qi) * 2048, 1024, hd * DHD + d, acc);
    }
}

// ---------------- salience softmax + entropy + weighted segments (bf16 out) ----------------
__global__ void salience_kernel() {
    int b = blockIdx.x, t = threadIdx.x;  // 256
    __shared__ float sal_s[NS];
    if (b == 0 && t == 0) g_red_cnt = 0;    // reset for fused red+finalize
    if (t == 0) {
        float mx = -1e30f;
        for (int s = 0; s < NS; s++) mx = fmaxf(mx, g_logits[b*NS + s]);
        float sm = 0.f;
        for (int s = 0; s < NS; s++) { float e = expf(g_logits[b*NS + s] - mx); sal_s[s] = e; sm += e; }
        float inv = 1.f / sm, ent = 0.f;
        for (int s = 0; s < NS; s++) {
            sal_s[s] *= inv;
            g_sal[b*NS + s] = sal_s[s];
            ent -= sal_s[s] * logf(sal_s[s] + 1e-8f);
        }
        g_entpart[b] = ent;
    }
    __syncthreads();
    for (int i = t; i < NS * HH; i += 256) {
        int s = i >> 10, k = i & 1023;
        float v = g_seg1[(size_t)b * NS * HH + i] * sal_s[s];
        whl(g_bf_wseg, (size_t)(b * NS + s) * 2048, 1024, k, v);
    }
}

// ---------------- redundancy + fused finalize (last block) ----------------
__global__ void red_kernel(float* __restrict__ out, int out_size) {
    int b = blockIdx.x, t = threadIdx.x;  // 128
    __shared__ float ps[NP][HH+1];
    __shared__ float nrm[NP];
    __shared__ float parr[16];
    __shared__ int lastflag;
    for (int i = t; i < NP * HH; i += 128) ps[i >> 10][i & 1023] = g_plan[(size_t)b * NP * HH + i];
    __syncthreads();
    if (t < NP) {
        float s = 0.f;
        for (int d = 0; d < HH; d++) s = fmaf(ps[t][d], ps[t][d], s);
        nrm[t] = fmaxf(sqrtf(s), 1e-12f);
    }
    __syncthreads();
    if (t < 15) {
        int i = 0, j = 0, c = t;
        for (i = 0; i < NP; i++) { int row = NP - 1 - i; if (c < row) { j = i + 1 + c; break; } c -= row; }
        float s = 0.f;
        for (int d = 0; d < HH; d++) s = fmaf(ps[i][d], ps[j][d], s);
        float sim = s / (nrm[i] * nrm[j]);
        parr[t] = 2.f * sim * sim;
    }
    __syncthreads();
    if (t == 0) {
        float s = 0.f;
        for (int p = 0; p < 15; p++) s += parr[p];
        g_redpart[b] = s;
        __threadfence();
        int old = atomicAdd(&g_red_cnt, 1);
        lastflag = (old == NB - 1);
    }
    __syncthreads();
    if (lastflag) {
        for (int i = t; i < NB*NS; i += 128)
            if (PLAN_ELEMS + i < out_size) out[PLAN_ELEMS + i] = g_sal[i];
        if (t == 0) {
            if (PLAN_ELEMS + 256 < out_size) {
                float e = 0.f;
                for (int bb = 0; bb < NB; bb++) e += g_entpart[bb];
                out[PLAN_ELEMS + 256] = e / (float)NB;
            }
            if (PLAN_ELEMS + 257 < out_size) {
                float r = 0.f;
                for (int bb = 0; bb < NB; bb++) r += g_redpart[bb];
                out[PLAN_ELEMS + 257] = r / (float)(NB * NP * (NP - 1));
            }
        }
    }
}

// ---------------- host helpers ----------------
// ks: (K/ks) % 32 == 0; ks*M*N <= 8M floats
static void gemm(const __nv_bfloat16* A, const __nv_bfloat16* W, int M, int N, int K, int ks,
                 float* part)
{
    dim3 grid((M + 127) / 128, N / 128, ks);
    gemm_bf16_kernel<<<grid, 256, 2*STGB>>>(A, W, part, M, N, K, ks);
}
static void epi(const float* P, const float* bias, const float* res, float* out,
                float* out2, int out2_lim, __nv_bfloat16* tout, int M, int N, int ks, int gelu)
{
    int blocks = (M * N + 1023) / 1024;
    epilogue_kernel<<<blocks, 256>>>(P, bias, res, out, out2, out2_lim, tout, M, N, ks, gelu);
}

extern "C" void kernel_launch(void* const* d_in, const int* in_sizes, int n_in,
                              void* d_out, int out_size)
{
    const float* ts       = (const float*)d_in[0];
    const int*   mask     = (const int*)  d_in[1];
    const float* sa_in_w  = (const float*)d_in[2];
    const float* sa_in_b  = (const float*)d_in[3];
    const float* sa_out_w = (const float*)d_in[4];
    const float* sa_out_b = (const float*)d_in[5];
    const float* ln_g     = (const float*)d_in[6];
    const float* ln_b     = (const float*)d_in[7];
    const float* sal_w1   = (const float*)d_in[8];
    const float* sal_b1   = (const float*)d_in[9];
    const float* sal_w2   = (const float*)d_in[10];
    const float* sal_b2   = (const float*)d_in[11];
    const float* plan_q   = (const float*)d_in[12];
    const float* qa_in_w  = (const float*)d_in[13];
    const float* qa_in_b  = (const float*)d_in[14];
    const float* qa_out_w = (const float*)d_in[15];
    const float* qa_out_b = (const float*)d_in[16];
    const float* r_in_w   = (const float*)d_in[17];
    const float* r_in_b   = (const float*)d_in[18];
    const float* r_out_w  = (const float*)d_in[19];
    const float* r_out_b  = (const float*)d_in[20];
    const float* r_ln1_g  = (const float*)d_in[21];
    const float* r_ln1_b  = (const float*)d_in[22];
    const float* r_ln2_g  = (const float*)d_in[23];
    const float* r_ln2_b  = (const float*)d_in[24];
    const float* r_w1     = (const float*)d_in[25];
    const float* r_b1     = (const float*)d_in[26];
    const float* r_w2     = (const float*)d_in[27];
    const float* r_b2     = (const float*)d_in[28];
    float* out = (float*)d_out;

    static int init_done = 0;
    static cudaStream_t s2;
    static cudaEvent_t ev_fork, ev_join;
    if (!init_done) {
        cudaFuncSetAttribute(gemm_bf16_kernel,
                             cudaFuncAttributeMaxDynamicSharedMemorySize, 2*STGB);
        cudaStreamCreateWithFlags(&s2, cudaStreamNonBlocking);
        cudaEventCreateWithFlags(&ev_fork, cudaEventDisableTiming);
        cudaEventCreateWithFlags(&ev_join, cudaEventDisableTiming);
        init_done = 1;
    }

    float *p_part, *p_qkv, *p_seg1, *p_qh, *p_kv, *p_plan, *p_qkvr, *p_seg0;
    cudaGetSymbolAddress((void**)&p_part, g_part);
    cudaGetSymbolAddress((void**)&p_seg0, g_seg0);
    cudaGetSymbolAddress((void**)&p_qkv,  g_qkv);
    cudaGetSymbolAddress((void**)&p_seg1, g_seg1);
    cudaGetSymbolAddress((void**)&p_qh,   g_qh);
    cudaGetSymbolAddress((void**)&p_kv,   g_kv);
    cudaGetSymbolAddress((void**)&p_plan, g_plan);
    cudaGetSymbolAddress((void**)&p_qkvr, g_qkvr);

    __nv_bfloat16 *t_seg0, *t_o, *t_seg1, *t_wseg, *t_pq, *t_o2, *t_y, *t_o3, *t_ffn, *wbf;
    cudaGetSymbolAddress((void**)&t_seg0, g_bf_seg0);
    cudaGetSymbolAddress((void**)&t_o,    g_bf_o);
    cudaGetSymbolAddress((void**)&t_seg1, g_bf_seg1);
    cudaGetSymbolAddress((void**)&t_wseg, g_bf_wseg);
    cudaGetSymbolAddress((void**)&t_pq,   g_bf_pq);
    cudaGetSymbolAddress((void**)&t_o2,   g_bf_o2);
    cudaGetSymbolAddress((void**)&t_y,    g_bf_y);
    cudaGetSymbolAddress((void**)&t_o3,   g_bf_o3);
    cudaGetSymbolAddress((void**)&t_ffn,  g_bf_ffn);
    cudaGetSymbolAddress((void**)&wbf,    g_wbf);

    // 0) weight conversion forked onto side stream; overlaps with pooling below
    CvtTab tab;
    tab.src[0]=sa_in_w;  tab.dst[0]=wbf+WOFF_SAIN;  tab.n[0]=3145728; tab.logK[0]=10;
    tab.src[1]=sa_out_w; tab.dst[1]=wbf+WOFF_SAOUT; tab.n[1]=1048576; tab.logK[1]=10;
    tab.src[2]=sal_w1;   tab.dst[2]=wbf+WOFF_SAL1;  tab.n[2]=1048576; tab.logK[2]=10;
    tab.src[3]=qa_in_w;  tab.dst[3]=wbf+WOFF_QAIN;  tab.n[3]=3145728; tab.logK[3]=10;
    tab.src[4]=qa_out_w; tab.dst[4]=wbf+WOFF_QAOUT; tab.n[4]=1048576; tab.logK[4]=10;
    tab.src[5]=r_in_w;   tab.dst[5]=wbf+WOFF_RIN;   tab.n[5]=6291456; tab.logK[5]=10;
    tab.src[6]=r_out_w;  tab.dst[6]=wbf+WOFF_ROUT;  tab.n[6]=2097152; tab.logK[6]=10;
    tab.src[7]=r_w1;     tab.dst[7]=wbf+WOFF_RW1;   tab.n[7]=8388608; tab.logK[7]=10;
    tab.src[8]=r_w2;     tab.dst[8]=wbf+WOFF_RW2;   tab.n[8]=8388608; tab.logK[8]=12;
    tab.src[9]=plan_q;   tab.dst[9]=t_pq;           tab.n[9]=6144;    tab.logK[9]=10;

    cudaEventRecord(ev_fork, 0);
    cudaStreamWaitEvent(s2, ev_fork, 0);
    convert_kernel<<<dim3(2048, 10), 256, 0, s2>>>(tab);
    cudaEventRecord(ev_join, s2);

    // 1) lengths + bounds, fused segment pooling (main stream, overlaps convert)
    lengths_kernel<<<16, 256>>>(mask);
    segpool_kernel<<<NB*NS, 256>>>(ts);

    // join: everything below needs converted weights
    cudaStreamWaitEvent(0, ev_join, 0);

    // 2) segment self-attention
    gemm(t_seg0, wbf+WOFF_SAIN, 256, 3*HH, HH, 8, p_part);
    epi(p_part, sa_in_b, nullptr, p_qkv, nullptr, 0, nullptr, 256, 3*HH, 8, 0);
    attn_kernel<<<dim3(NB, NHEAD), 128>>>(p_qkv, p_qkv + HH, p_qkv + 2*HH, t_o,
                                          16, 16,
                                          3*HH, (long long)NS*3*HH,
                                          3*HH, (long long)NS*3*HH,
                                          3*HH, (long long)NS*3*HH);
    gemm(t_o, wbf+WOFF_SAOUT, 256, HH, HH, 16, p_part);
    epilogue_ln_kernel<<<256, 256>>>(p_part, sa_out_b, p_seg0, ln_g, ln_b,
                                     nullptr, p_seg1, t_seg1, 256, 16);

    // 3) salience (gelu-epilogue + logits fused)
    gemm(t_seg1, wbf+WOFF_SAL1, 256, HH, HH, 16, p_part);
    epilogue_logits_kernel<<<256, 256>>>(p_part, sal_b1, sal_w2, sal_b2, 256, 16);
    salience_kernel<<<16, 256>>>();

    // 4) plan cross-attention (qh batch-independent)
    gemm(t_pq, wbf+WOFF_QAIN, NP, HH, HH, 32, p_part);
    epi(p_part, qa_in_b, nullptr, p_qh, nullptr, 0, nullptr, NP, HH, 32, 0);
    gemm(t_wseg, wbf+WOFF_QAIN + (size_t)HH*2*HH, 256, 2*HH, HH, 8, p_part);
    epi(p_part, qa_in_b + HH, nullptr, p_kv, nullptr, 0, nullptr, 256, 2*HH, 8, 0);
    attn_kernel<<<dim3(NB, NHEAD), 128>>>(p_qh, p_kv, p_kv + HH, t_o2,
                                          NP, 16,
                                          HH,   0LL,
                                          2*HH, (long long)NS*2*HH,
                                          2*HH, (long long)NS*2*HH);
    gemm(t_o2, wbf+WOFF_QAOUT, NB*NP, HH, HH, 16, p_part);
    epilogue_ln_kernel<<<NB*NP, 256>>>(p_part, qa_out_b, nullptr, r_ln1_g, r_ln1_b,
                                       p_plan, nullptr, t_y, NB*NP, 16);

    // 5) refinement transformer layers (norm_first)
    for (int l = 0; l < 2; l++) {
        gemm(t_y, wbf+WOFF_RIN + (size_t)l*6291456, NB*NP, 3*HH, HH, 8, p_part);
        epi(p_part, r_in_b + l*3*HH, nullptr, p_qkvr, nullptr, 0, nullptr, NB*NP, 3*HH, 8, 0);
        attn_kernel<<<dim3(NB, NHEAD), 128>>>(p_qkvr, p_qkvr + HH, p_qkvr + 2*HH, t_o3,
                                              NP, NP,
                                              3*HH, (long long)NP*3*HH,
                                              3*HH, (long long)NP*3*HH,
                                              3*HH, (long long)NP*3*HH);
        gemm(t_o3, wbf+WOFF_ROUT + (size_t)l*2097152, NB*NP, HH, HH, 16, p_part);
        epilogue_ln_kernel<<<NB*NP, 256>>>(p_part, r_out_b + l*HH, p_plan,
                                           r_ln2_g + l*HH, r_ln2_b + l*HH,
                                           p_plan, nullptr, t_y, NB*NP, 16);
        gemm(t_y, wbf+WOFF_RW1 + (size_t)l*8388608, NB*NP, 4*HH, HH, 8, p_part);
        epi(p_part, r_b1 + l*4*HH, nullptr, nullptr, nullptr, 0, t_ffn, NB*NP, 4*HH, 8, 1);
        gemm(t_ffn, wbf+WOFF_RW2 + (size_t)l*8388608, NB*NP, HH, 4*HH, 32, p_part);
        if (l == 0) {
            epilogue_ln_kernel<<<NB*NP, 256>>>(p_part, r_b2, p_plan,
                                               r_ln1_g + HH, r_ln1_b + HH,
                                               p_plan, nullptr, t_y, NB*NP, 32);
        } else {
            int lim = out_size < PLAN_ELEMS ? out_size : PLAN_ELEMS;
            epi(p_part, r_b2 + HH, p_plan, p_plan, out, lim, nullptr, NB*NP, HH, 32, 0);
        }
    }

    // 6) redundancy + finalize (fused)
    red_kernel<<<16, 128>>>(out, out_size);
}